// round 1
// baseline (speedup 1.0000x reference)
#include <cuda_runtime.h>
#include <math.h>

// ---------------- problem constants ----------------
#define Tn   4096      // B*N tokens
#define Dd   1024
#define Hh   16
#define HD   64
#define Nn   2048
#define Bb   2
#define Ee   4
#define CAP  2048
#define MLPH 4096
#define MOEH 256

// ---------------- scratch (__device__ globals; no allocations allowed) ----
// layout (floats):
//   S       : 33554432  (8 heads * 2048 * 2048, reused 4x)
//   qkv     : 12582912
//   hmlp    : 16777216
//   x1,ao,xres,x2,mlpout : 4194304 each
//   moeout  : 8388608
//   hmoe    : 2097152
#define OFF_S      0LL
#define OFF_QKV    33554432LL
#define OFF_HMLP   46137344LL
#define OFF_X1     62914560LL
#define OFF_AO     67108864LL
#define OFF_XRES   71303168LL
#define OFF_X2     75497472LL
#define OFF_MLPOUT 79691776LL
#define OFF_MOEOUT 83886080LL
#define OFF_HMOE   92274688LL
#define BUF_TOTAL  94371840LL

__device__ float  g_buf[BUF_TOTAL];
__device__ int2   g_topi[Tn];
__device__ float2 g_tw[Tn];
__device__ int    g_tslot[Tn * 2];
__device__ int    g_sel[Ee * CAP];

// ---------------- helpers ----------------
__device__ __forceinline__ float gelu_f(float x) {
    return 0.5f * x * (1.0f + erff(x * 0.7071067811865476f));
}

// ---------------- generic batched SGEMM ----------------
// C[m,n] = alpha * sum_k A[m,k] * (TB ? B[n,k] : B[k,n])   (+bias)(gelu)(+res)
// batch z decomposed: zo = z / zdiv, zi = z % zdiv; offsets via (sX0, sX1).
// GATHER: A row index m -> gidx[zo*sG + m].
// Requires: M % 64 == 0, N % 64 == 0, K % 16 == 0, all leading dims % 4 == 0.
struct GemmP {
    const float* A; const float* B; float* C;
    const float* bias; const float* res; const int* gidx;
    int lda, ldb, ldc, ldres;
    long long sA0, sA1, sB0, sB1, sC0, sC1, sBias, sG;
    int zdiv;
    int K;
    float alpha;
    int epi;  // bit0: +bias[n], bit1: gelu, bit2: +res[m,n]
};

template <bool TB, bool GATHER>
__global__ __launch_bounds__(256) void sgemm_k(GemmP p) {
    int z  = blockIdx.z;
    int zo = z / p.zdiv, zi = z - zo * p.zdiv;
    const float* A = p.A + zo * p.sA0 + zi * p.sA1;
    const float* B = p.B + zo * p.sB0 + zi * p.sB1;
    float*       C = p.C + zo * p.sC0 + zi * p.sC1;

    int m0 = blockIdx.x * 64, n0 = blockIdx.y * 64;
    __shared__ float As[16][64];
    __shared__ float Bs[16][64];

    int tid = threadIdx.x;
    int tx = tid & 15, ty = tid >> 4;

    // A tile loader: thread -> (row am in [0,64), 4 consecutive k at ak)
    int am = tid >> 2, ak = (tid & 3) << 2;
    long long arow = m0 + am;
    if (GATHER) arow = p.gidx[zo * p.sG + arow];
    const float* Aptr = A + arow * (long long)p.lda + ak;

    // B tile loader
    int bk, bn;
    const float* Bptr;
    if (!TB) { bk = tid >> 4;       bn = (tid & 15) << 2; Bptr = B + (long long)bk * p.ldb + n0 + bn; }
    else     { bn = tid >> 2;       bk = (tid & 3)  << 2; Bptr = B + (long long)(n0 + bn) * p.ldb + bk; }

    float acc[4][4];
#pragma unroll
    for (int i = 0; i < 4; i++)
#pragma unroll
        for (int j = 0; j < 4; j++) acc[i][j] = 0.0f;

    for (int kt = 0; kt < p.K; kt += 16) {
        float4 a4 = *(const float4*)Aptr;  Aptr += 16;
        As[ak + 0][am] = a4.x; As[ak + 1][am] = a4.y;
        As[ak + 2][am] = a4.z; As[ak + 3][am] = a4.w;

        float4 b4 = *(const float4*)Bptr;
        if (!TB) {
            *(float4*)&Bs[bk][bn] = b4;
            Bptr += 16LL * p.ldb;
        } else {
            Bs[bk + 0][bn] = b4.x; Bs[bk + 1][bn] = b4.y;
            Bs[bk + 2][bn] = b4.z; Bs[bk + 3][bn] = b4.w;
            Bptr += 16;
        }
        __syncthreads();

#pragma unroll
        for (int kk = 0; kk < 16; kk++) {
            float4 a = *(const float4*)&As[kk][ty << 2];
            float4 b = *(const float4*)&Bs[kk][tx << 2];
            acc[0][0] += a.x * b.x; acc[0][1] += a.x * b.y; acc[0][2] += a.x * b.z; acc[0][3] += a.x * b.w;
            acc[1][0] += a.y * b.x; acc[1][1] += a.y * b.y; acc[1][2] += a.y * b.z; acc[1][3] += a.y * b.w;
            acc[2][0] += a.z * b.x; acc[2][1] += a.z * b.y; acc[2][2] += a.z * b.z; acc[2][3] += a.z * b.w;
            acc[3][0] += a.w * b.x; acc[3][1] += a.w * b.y; acc[3][2] += a.w * b.z; acc[3][3] += a.w * b.w;
        }
        __syncthreads();
    }

    const float* bias = p.bias ? (p.bias + zo * p.sBias) : nullptr;
#pragma unroll
    for (int i = 0; i < 4; i++) {
        int m = m0 + (ty << 2) + i;
#pragma unroll
        for (int j = 0; j < 4; j++) {
            int n = n0 + (tx << 2) + j;
            float v = acc[i][j] * p.alpha;
            if (p.epi & 1) v += bias[n];
            if (p.epi & 2) v = gelu_f(v);
            if (p.epi & 4) v += p.res[(long long)m * p.ldres + n];
            C[(long long)m * p.ldc + n] = v;
        }
    }
}

// ---------------- layernorm (one block per row, D = 1024) ----------------
__global__ __launch_bounds__(256) void ln_kernel(const float* __restrict__ x,
                                                 const float* __restrict__ g,
                                                 const float* __restrict__ b,
                                                 float* __restrict__ out) {
    int row = blockIdx.x;
    int tid = threadIdx.x;
    const float4* xr = (const float4*)(x + (long long)row * Dd);
    float4 v = xr[tid];
    __shared__ float s[256];

    s[tid] = v.x + v.y + v.z + v.w;
    __syncthreads();
    for (int o = 128; o > 0; o >>= 1) { if (tid < o) s[tid] += s[tid + o]; __syncthreads(); }
    float mu = s[0] * (1.0f / Dd);
    __syncthreads();

    float dx = v.x - mu, dy = v.y - mu, dz = v.z - mu, dw = v.w - mu;
    s[tid] = dx * dx + dy * dy + dz * dz + dw * dw;
    __syncthreads();
    for (int o = 128; o > 0; o >>= 1) { if (tid < o) s[tid] += s[tid + o]; __syncthreads(); }
    float rstd = rsqrtf(s[0] * (1.0f / Dd) + 1e-5f);

    float4 gg = ((const float4*)g)[tid];
    float4 bb = ((const float4*)b)[tid];
    float4 o4;
    o4.x = dx * rstd * gg.x + bb.x;
    o4.y = dy * rstd * gg.y + bb.y;
    o4.z = dz * rstd * gg.z + bb.z;
    o4.w = dw * rstd * gg.w + bb.w;
    ((float4*)(out + (long long)row * Dd))[tid] = o4;
}

// ---------------- row softmax over 2048 cols (in place) ----------------
__global__ __launch_bounds__(256) void softmax_k(float* __restrict__ S) {
    long long row = blockIdx.x;
    float4* r4 = (float4*)(S + row * (long long)Nn);
    int tid = threadIdx.x;
    float4 a = r4[tid], b = r4[tid + 256];
    __shared__ float s[256];

    float mx = fmaxf(fmaxf(fmaxf(a.x, a.y), fmaxf(a.z, a.w)),
                     fmaxf(fmaxf(b.x, b.y), fmaxf(b.z, b.w)));
    s[tid] = mx; __syncthreads();
    for (int o = 128; o > 0; o >>= 1) { if (tid < o) s[tid] = fmaxf(s[tid], s[tid + o]); __syncthreads(); }
    mx = s[0]; __syncthreads();

    a.x = expf(a.x - mx); a.y = expf(a.y - mx); a.z = expf(a.z - mx); a.w = expf(a.w - mx);
    b.x = expf(b.x - mx); b.y = expf(b.y - mx); b.z = expf(b.z - mx); b.w = expf(b.w - mx);
    s[tid] = a.x + a.y + a.z + a.w + b.x + b.y + b.z + b.w;
    __syncthreads();
    for (int o = 128; o > 0; o >>= 1) { if (tid < o) s[tid] += s[tid + o]; __syncthreads(); }
    float inv = 1.0f / s[0];

    a.x *= inv; a.y *= inv; a.z *= inv; a.w *= inv;
    b.x *= inv; b.y *= inv; b.z *= inv; b.w *= inv;
    r4[tid] = a; r4[tid + 256] = b;
}

// ---------------- router: logits + noisy softplus + top-2 ----------------
__global__ __launch_bounds__(256) void route_kernel(const float* __restrict__ x2,
                                                    const float* __restrict__ wr,
                                                    const float* __restrict__ br,
                                                    const float* __restrict__ wn,
                                                    const float* __restrict__ bn,
                                                    const float* __restrict__ noise,
                                                    int2* __restrict__ topi,
                                                    float2* __restrict__ tw) {
    int t    = blockIdx.x * 8 + (threadIdx.x >> 5);
    int lane = threadIdx.x & 31;
    if (t >= Tn) return;
    const float* xr = x2 + (long long)t * Dd;

    float aR[4] = {0, 0, 0, 0}, aN[4] = {0, 0, 0, 0};
    for (int d = lane; d < Dd; d += 32) {
        float xv = xr[d];
        float4 r = ((const float4*)wr)[d];
        float4 nq = ((const float4*)wn)[d];
        aR[0] += xv * r.x;  aR[1] += xv * r.y;  aR[2] += xv * r.z;  aR[3] += xv * r.w;
        aN[0] += xv * nq.x; aN[1] += xv * nq.y; aN[2] += xv * nq.z; aN[3] += xv * nq.w;
    }
#pragma unroll
    for (int o = 16; o > 0; o >>= 1) {
#pragma unroll
        for (int e = 0; e < 4; e++) {
            aR[e] += __shfl_down_sync(0xffffffffu, aR[e], o);
            aN[e] += __shfl_down_sync(0xffffffffu, aN[e], o);
        }
    }
    if (lane == 0) {
        float nv[4];
#pragma unroll
        for (int e = 0; e < 4; e++) {
            float lg  = aR[e] + br[e];
            float pre = aN[e] + bn[e];
            float sp  = (pre > 20.0f) ? pre : log1pf(expf(pre));
            nv[e] = lg + noise[t * 4 + e] * sp;
        }
        int e0 = 0;
#pragma unroll
        for (int e = 1; e < 4; e++) if (nv[e] > nv[e0]) e0 = e;
        int e1 = -1;
#pragma unroll
        for (int e = 0; e < 4; e++) if (e != e0 && (e1 < 0 || nv[e] > nv[e1])) e1 = e;
        float d  = expf(nv[e1] - nv[e0]);
        float p0 = 1.0f / (1.0f + d);
        topi[t] = make_int2(e0, e1);
        tw[t]   = make_float2(p0, d * p0);
    }
}

// ---------------- capacity scan: stable order per expert ----------------
__global__ __launch_bounds__(1024) void scan_kernel(const int2* __restrict__ topi,
                                                    int* __restrict__ sel,
                                                    int* __restrict__ tslot) {
    int e = blockIdx.x;
    int tid = threadIdx.x;
    __shared__ int s[1024];

    int m[4]; int cnt = 0;
#pragma unroll
    for (int i = 0; i < 4; i++) {
        int t = tid * 4 + i;
        int2 ti = topi[t];
        m[i] = (ti.x == e) ? 1 : ((ti.y == e) ? 2 : 0);
        cnt += (m[i] != 0);
    }
    s[tid] = cnt;
    __syncthreads();
    for (int off = 1; off < 1024; off <<= 1) {
        int v = 0;
        if (tid >= off) v = s[tid - off];
        __syncthreads();
        s[tid] += v;
        __syncthreads();
    }
    int total = s[1023];
    int rank  = s[tid] - cnt;  // exclusive prefix
#pragma unroll
    for (int i = 0; i < 4; i++) {
        if (m[i]) {
            int t = tid * 4 + i;
            int j = m[i] - 1;
            if (rank < CAP) { sel[e * CAP + rank] = t; tslot[t * 2 + j] = rank; }
            else            { tslot[t * 2 + j] = -1; }
            rank++;
        }
    }
    for (int r = total + tid; r < CAP; r += 1024) sel[e * CAP + r] = 0;  // fillers (weight 0)
}

// ---------------- final combine: out = xres + mlp + gated expert outs ----
__global__ __launch_bounds__(256) void final_kernel(const float* __restrict__ xres,
                                                    const float* __restrict__ mlp,
                                                    const float* __restrict__ moeout,
                                                    const int2* __restrict__ topi,
                                                    const int* __restrict__ tslot,
                                                    const float2* __restrict__ tw,
                                                    float* __restrict__ out) {
    long long idx = (long long)blockIdx.x * blockDim.x + threadIdx.x;
    int t = (int)(idx >> 10);
    int dcol = (int)(idx & 1023);
    float v = xres[idx] + mlp[idx];
    int2 ti = topi[t];
    float2 w = tw[t];
    int s0 = tslot[t * 2], s1 = tslot[t * 2 + 1];
    if (s0 >= 0) v += w.x * moeout[((long long)ti.x * CAP + s0) * Dd + dcol];
    if (s1 >= 0) v += w.y * moeout[((long long)ti.y * CAP + s1) * Dd + dcol];
    out[idx] = v;
}

// ---------------- host launch helpers ----------------
static void run_gemm(bool tb, bool gather, const GemmP& p, int M, int N, int batch) {
    dim3 grid(M / 64, N / 64, batch);
    if (tb) {
        if (gather) sgemm_k<true,  true ><<<grid, 256>>>(p);
        else        sgemm_k<true,  false><<<grid, 256>>>(p);
    } else {
        if (gather) sgemm_k<false, true ><<<grid, 256>>>(p);
        else        sgemm_k<false, false><<<grid, 256>>>(p);
    }
}

extern "C" void kernel_launch(void* const* d_in, const int* in_sizes, int n_in,
                              void* d_out, int out_size) {
    const float* x       = (const float*)d_in[0];
    const float* noise   = (const float*)d_in[1];
    const float* ln1_g   = (const float*)d_in[2];
    const float* ln1_b   = (const float*)d_in[3];
    const float* ln2_g   = (const float*)d_in[4];
    const float* ln2_b   = (const float*)d_in[5];
    const float* w_qkv   = (const float*)d_in[6];
    const float* w_proj  = (const float*)d_in[7];
    const float* b_proj  = (const float*)d_in[8];
    const float* w_route = (const float*)d_in[9];
    const float* b_route = (const float*)d_in[10];
    const float* w_noise = (const float*)d_in[11];
    const float* b_noise = (const float*)d_in[12];
    const float* we1     = (const float*)d_in[13];
    const float* be1     = (const float*)d_in[14];
    const float* we2     = (const float*)d_in[15];
    const float* be2     = (const float*)d_in[16];
    const float* w_mlp1  = (const float*)d_in[17];
    const float* b_mlp1  = (const float*)d_in[18];
    const float* w_mlp2  = (const float*)d_in[19];
    const float* b_mlp2  = (const float*)d_in[20];
    float* out = (float*)d_out;

    float*  buf;   cudaGetSymbolAddress((void**)&buf,   g_buf);
    int2*   topi;  cudaGetSymbolAddress((void**)&topi,  g_topi);
    float2* tw;    cudaGetSymbolAddress((void**)&tw,    g_tw);
    int*    tslot; cudaGetSymbolAddress((void**)&tslot, g_tslot);
    int*    sel;   cudaGetSymbolAddress((void**)&sel,   g_sel);

    float* S      = buf + OFF_S;
    float* qkv    = buf + OFF_QKV;
    float* hmlp   = buf + OFF_HMLP;
    float* x1     = buf + OFF_X1;
    float* ao     = buf + OFF_AO;
    float* xres   = buf + OFF_XRES;
    float* x2     = buf + OFF_X2;
    float* mlpout = buf + OFF_MLPOUT;
    float* moeout = buf + OFF_MOEOUT;
    float* hmoe   = buf + OFF_HMOE;

    // 1) LN1
    ln_kernel<<<Tn, 256>>>(x, ln1_g, ln1_b, x1);

    // 2) QKV = x1 @ w_qkv^T   (4096 x 3072 x 1024)
    {
        GemmP p{}; p.zdiv = 1; p.alpha = 1.0f; p.K = Dd;
        p.A = x1; p.lda = Dd;
        p.B = w_qkv; p.ldb = Dd;
        p.C = qkv; p.ldc = 3 * Dd;
        run_gemm(true, false, p, Tn, 3 * Dd, 1);
    }

    // 3) Attention in 4 chunks of 8 heads (reuse S buffer)
    for (int gch = 0; gch < 4; gch++) {
        int b = gch >> 1, h0 = (gch & 1) * 8;
        long long qoff = (long long)b * Nn * (3 * Dd) + (long long)h0 * HD;

        GemmP p{}; p.zdiv = 8; p.alpha = 0.125f; p.K = HD;  // hd^-0.5 = 1/8
        p.A = qkv + qoff;      p.lda = 3 * Dd; p.sA1 = HD;
        p.B = qkv + Dd + qoff; p.ldb = 3 * Dd; p.sB1 = HD;
        p.C = S;               p.ldc = Nn;     p.sC1 = (long long)Nn * Nn;
        run_gemm(true, false, p, Nn, Nn, 8);

        softmax_k<<<8 * Nn, 256>>>(S);

        GemmP q{}; q.zdiv = 8; q.alpha = 1.0f; q.K = Nn;
        q.A = S;                    q.lda = Nn;     q.sA1 = (long long)Nn * Nn;
        q.B = qkv + 2 * Dd + qoff;  q.ldb = 3 * Dd; q.sB1 = HD;
        q.C = ao + (long long)b * Nn * Dd + (long long)h0 * HD;
        q.ldc = Dd; q.sC1 = HD;
        run_gemm(false, false, q, Nn, HD, 8);
    }

    // 4) xres = x + ao @ w_proj^T + b_proj
    {
        GemmP p{}; p.zdiv = 1; p.alpha = 1.0f; p.K = Dd;
        p.A = ao; p.lda = Dd;
        p.B = w_proj; p.ldb = Dd;
        p.C = xres; p.ldc = Dd;
        p.bias = b_proj; p.res = x; p.ldres = Dd;
        p.epi = 1 | 4;
        run_gemm(true, false, p, Tn, Dd, 1);
    }

    // 5) LN2
    ln_kernel<<<Tn, 256>>>(xres, ln2_g, ln2_b, x2);

    // 6) routing (noisy top-2)
    route_kernel<<<Tn / 8, 256>>>(x2, w_route, b_route, w_noise, b_noise, noise, topi, tw);

    // 7) per-expert stable capacity scan
    scan_kernel<<<Ee, 1024>>>(topi, sel, tslot);

    // 8) MoE expert GEMM 1 (gathered rows): gelu(Xsel @ we1[e] + be1[e])
    {
        GemmP p{}; p.zdiv = 1; p.alpha = 1.0f; p.K = Dd;
        p.A = x2; p.lda = Dd;
        p.gidx = sel; p.sG = CAP;
        p.B = we1; p.ldb = MOEH; p.sB0 = (long long)Dd * MOEH;
        p.C = hmoe; p.ldc = MOEH; p.sC0 = (long long)CAP * MOEH;
        p.bias = be1; p.sBias = MOEH;
        p.epi = 1 | 2;
        run_gemm(false, true, p, CAP, MOEH, Ee);
    }

    // 9) MoE expert GEMM 2: h_e @ we2[e] + be2[e]
    {
        GemmP p{}; p.zdiv = 1; p.alpha = 1.0f; p.K = MOEH;
        p.A = hmoe; p.lda = MOEH; p.sA0 = (long long)CAP * MOEH;
        p.B = we2; p.ldb = Dd; p.sB0 = (long long)MOEH * Dd;
        p.C = moeout; p.ldc = Dd; p.sC0 = (long long)CAP * Dd;
        p.bias = be2; p.sBias = Dd;
        p.epi = 1;
        run_gemm(false, false, p, CAP, Dd, Ee);
    }

    // 10) MLP1: gelu(x2 @ w_mlp1 + b_mlp1)
    {
        GemmP p{}; p.zdiv = 1; p.alpha = 1.0f; p.K = Dd;
        p.A = x2; p.lda = Dd;
        p.B = w_mlp1; p.ldb = MLPH;
        p.C = hmlp; p.ldc = MLPH;
        p.bias = b_mlp1;
        p.epi = 1 | 2;
        run_gemm(false, false, p, Tn, MLPH, 1);
    }

    // 11) MLP2: hmlp @ w_mlp2 + b_mlp2
    {
        GemmP p{}; p.zdiv = 1; p.alpha = 1.0f; p.K = MLPH;
        p.A = hmlp; p.lda = MLPH;
        p.B = w_mlp2; p.ldb = Dd;
        p.C = mlpout; p.ldc = Dd;
        p.bias = b_mlp2;
        p.epi = 1;
        run_gemm(false, false, p, Tn, Dd, 1);
    }

    // 12) out = xres + mlp + gated MoE (gather; deterministic, no atomics)
    final_kernel<<<(Tn * Dd) / 256, 256>>>(xres, mlpout, moeout, topi, tslot, tw, out);
}

// round 2
// speedup vs baseline: 1.8214x; 1.8214x over previous
#include <cuda_runtime.h>
#include <math.h>
#include <stdint.h>

// ---------------- problem constants ----------------
#define Tn   4096      // B*N tokens
#define Dd   1024
#define Hh   16
#define HD   64
#define Nn   2048
#define Bb   2
#define Ee   4
#define CAP  2048
#define MLPH 4096
#define MOEH 256

// ---------------- scratch (__device__ globals; no allocations allowed) ----
#define OFF_S      0LL
#define OFF_QKV    33554432LL
#define OFF_HMLP   46137344LL
#define OFF_X1     62914560LL
#define OFF_AO     67108864LL
#define OFF_XRES   71303168LL
#define OFF_X2     75497472LL
#define OFF_MLPOUT 79691776LL
#define OFF_MOEOUT 83886080LL
#define OFF_HMOE   92274688LL
#define BUF_TOTAL  94371840LL

__device__ float  g_buf[BUF_TOTAL];
__device__ int2   g_topi[Tn];
__device__ float2 g_tw[Tn];
__device__ int    g_tslot[Tn * 2];
__device__ int    g_sel[Ee * CAP];

// ---------------- helpers ----------------
__device__ __forceinline__ float gelu_f(float x) {
    return 0.5f * x * (1.0f + erff(x * 0.7071067811865476f));
}
__device__ __forceinline__ unsigned f2tf(float x) {
    unsigned u;
    asm("cvt.rna.tf32.f32 %0, %1;" : "=r"(u) : "f"(x));
    return u;
}

// ---------------- tf32 tensor-core batched GEMM ----------------
// C[m,n] = alpha * sum_k A[m,k] * (TB ? B[n,k] : B[k,n])   (+bias)(gelu)(+res)
// BM = 128 fixed, BN in {128, 64}, K-tile 32, 256 threads (8 warps).
// Requires M % 128 == 0, N % BN == 0, K % 32 == 0, 16B-aligned rows.
struct GemmP {
    const float* A; const float* B; float* C;
    const float* bias; const float* res; const int* gidx;
    int lda, ldb, ldc, ldres;
    long long sA0, sA1, sB0, sB1, sC0, sC1, sBias, sG;
    int zdiv;
    int K;
    float alpha;
    int epi;  // bit0: +bias[n], bit1: gelu, bit2: +res[m,n]
};

template <int BN, bool TB, bool GATHER>
__global__ __launch_bounds__(256) void tgemm_k(GemmP p) {
    constexpr int WM = (BN == 128) ? 64 : 32;
    constexpr int WN = 32;
    constexpr int WARPS_M = 128 / WM;
    constexpr int MT = WM / 16;
    constexpr int NT = WN / 8;
    constexpr int JB = BN / 32;     // B loader float4s per thread

    __shared__ unsigned As[4096];       // 8 mt * 4 ks blocks of 32 lanes * 4 regs
    __shared__ unsigned Bs[BN * 32];    // (BN/8) nt * 4 ks blocks of 32 lanes * 2 regs

    int z  = blockIdx.z;
    int zo = z / p.zdiv, zi = z - zo * p.zdiv;
    const float* A = p.A + zo * p.sA0 + zi * p.sA1;
    const float* B = p.B + zo * p.sB0 + zi * p.sB1;
    float*       C = p.C + zo * p.sC0 + zi * p.sC1;

    int m0 = blockIdx.x * 128, n0 = blockIdx.y * BN;
    int tid = threadIdx.x;
    int w = tid >> 5, lane = tid & 31;
    int wm = w % WARPS_M, wn = w / WARPS_M;

    // ---- A loader: thread covers row am, 16 consecutive k at akb ----
    int am = tid >> 1, akb = (tid & 1) * 16;
    long long arow = m0 + am;
    if (GATHER) arow = p.gidx[zo * p.sG + arow];
    const float* Aptr = A + arow * (long long)p.lda + akb;

    // ---- B loader ----
    int bkrow = 0, bf4 = 0, bnrow = 0, bkb = 0;
    const float* Bptr;
    if (!TB) {
        bkrow = tid >> 3; bf4 = tid & 7;
        Bptr = B + (long long)bkrow * p.ldb + n0;
    } else {
        if (BN == 128) { bnrow = tid >> 1; bkb = (tid & 1) * 16; }
        else           { bnrow = tid >> 2; bkb = (tid & 3) * 8;  }
        Bptr = B + (long long)(n0 + bnrow) * p.ldb + bkb;
    }

    float4 ar[4];
    float4 br[JB];
    float acc[MT][NT][4];
#pragma unroll
    for (int i = 0; i < MT; i++)
#pragma unroll
        for (int j = 0; j < NT; j++)
#pragma unroll
            for (int q = 0; q < 4; q++) acc[i][j][q] = 0.0f;

    auto loadg = [&](int kt) {
#pragma unroll
        for (int j = 0; j < 4; j++)
            ar[j] = *(const float4*)(Aptr + kt + j * 4);
        if (!TB) {
#pragma unroll
            for (int j = 0; j < JB; j++)
                br[j] = *(const float4*)(Bptr + (long long)kt * p.ldb + (bf4 + j * 8) * 4);
        } else {
#pragma unroll
            for (int j = 0; j < JB; j++)
                br[j] = *(const float4*)(Bptr + kt + j * 4);
        }
    };

    auto stores = [&]() {
        // A: element (am, k..k+3) -> fragment layout
#pragma unroll
        for (int j = 0; j < 4; j++) {
            int k = akb + j * 4;
            int ks = k >> 3, c = k & 7;
            int mt = am >> 4, r = am & 15;
            int reg  = (r >> 3) + ((c >= 4) ? 2 : 0);
            int base = ((mt * 4 + ks) * 32 + (r & 7) * 4) * 4 + reg;
            As[base + 0]  = f2tf(ar[j].x);
            As[base + 4]  = f2tf(ar[j].y);
            As[base + 8]  = f2tf(ar[j].z);
            As[base + 12] = f2tf(ar[j].w);
        }
        if (!TB) {
#pragma unroll
            for (int j = 0; j < JB; j++) {
                int n = (bf4 + j * 8) * 4;          // n%8 in {0,4}
                int k = bkrow;
                int ks = k >> 3, kk = k & 7;
                int nt = n >> 3, g = n & 7;
                int base = (nt * 4 + ks) * 64 + g * 8 + (kk & 3) * 2 + (kk >= 4);
                Bs[base + 0]  = f2tf(br[j].x);
                Bs[base + 8]  = f2tf(br[j].y);
                Bs[base + 16] = f2tf(br[j].z);
                Bs[base + 24] = f2tf(br[j].w);
            }
        } else {
#pragma unroll
            for (int j = 0; j < JB; j++) {
                int k = bkb + j * 4;                // k%8 in {0,4}
                int ks = k >> 3, kkb = k & 7;
                int nt = bnrow >> 3, g = bnrow & 7;
                int base = (nt * 4 + ks) * 64 + g * 8 + (kkb >= 4);
                Bs[base + 0] = f2tf(br[j].x);
                Bs[base + 2] = f2tf(br[j].y);
                Bs[base + 4] = f2tf(br[j].z);
                Bs[base + 6] = f2tf(br[j].w);
            }
        }
    };

    auto compute = [&]() {
#pragma unroll
        for (int ks = 0; ks < 4; ks++) {
            unsigned a[MT][4];
            unsigned b[NT][2];
#pragma unroll
            for (int mt = 0; mt < MT; mt++) {
                int blk = (wm * MT + mt) * 4 + ks;
                uint4 t = *(const uint4*)&As[blk * 128 + lane * 4];
                a[mt][0] = t.x; a[mt][1] = t.y; a[mt][2] = t.z; a[mt][3] = t.w;
            }
#pragma unroll
            for (int nt = 0; nt < NT; nt++) {
                int blk = (wn * NT + nt) * 4 + ks;
                uint2 t = *(const uint2*)&Bs[blk * 64 + lane * 2];
                b[nt][0] = t.x; b[nt][1] = t.y;
            }
#pragma unroll
            for (int mt = 0; mt < MT; mt++)
#pragma unroll
                for (int nt = 0; nt < NT; nt++)
                    asm volatile(
                        "mma.sync.aligned.m16n8k8.row.col.f32.tf32.tf32.f32 "
                        "{%0,%1,%2,%3}, {%4,%5,%6,%7}, {%8,%9}, {%0,%1,%2,%3};"
                        : "+f"(acc[mt][nt][0]), "+f"(acc[mt][nt][1]),
                          "+f"(acc[mt][nt][2]), "+f"(acc[mt][nt][3])
                        : "r"(a[mt][0]), "r"(a[mt][1]), "r"(a[mt][2]), "r"(a[mt][3]),
                          "r"(b[nt][0]), "r"(b[nt][1]));
        }
    };

    // ---- mainloop with register-staged prefetch ----
    loadg(0);
    stores();
    __syncthreads();
    for (int kt = 32; kt < p.K; kt += 32) {
        loadg(kt);
        compute();
        __syncthreads();
        stores();
        __syncthreads();
    }
    compute();

    // ---- epilogue ----
    const float* bias = p.bias ? (p.bias + zo * p.sBias) : nullptr;
    int g = lane >> 2, tig = lane & 3;
#pragma unroll
    for (int mt = 0; mt < MT; mt++) {
#pragma unroll
        for (int half = 0; half < 2; half++) {
            int m = m0 + wm * WM + mt * 16 + g + half * 8;
#pragma unroll
            for (int nt = 0; nt < NT; nt++) {
                int n = n0 + wn * WN + nt * 8 + tig * 2;
                float v0 = acc[mt][nt][half * 2 + 0] * p.alpha;
                float v1 = acc[mt][nt][half * 2 + 1] * p.alpha;
                if (p.epi & 1) { v0 += bias[n]; v1 += bias[n + 1]; }
                if (p.epi & 2) { v0 = gelu_f(v0); v1 = gelu_f(v1); }
                if (p.epi & 4) {
                    v0 += p.res[(long long)m * p.ldres + n];
                    v1 += p.res[(long long)m * p.ldres + n + 1];
                }
                *(float2*)&C[(long long)m * p.ldc + n] = make_float2(v0, v1);
            }
        }
    }
}

template <int BN, bool TB, bool GATHER>
static void launch_g(const GemmP& p, int M, int N, int batch) {
    dim3 grid(M / 128, N / BN, batch);
    tgemm_k<BN, TB, GATHER><<<grid, 256>>>(p);
}

// ---------------- layernorm (one block per row, D = 1024) ----------------
__global__ __launch_bounds__(256) void ln_kernel(const float* __restrict__ x,
                                                 const float* __restrict__ g,
                                                 const float* __restrict__ b,
                                                 float* __restrict__ out) {
    int row = blockIdx.x;
    int tid = threadIdx.x;
    const float4* xr = (const float4*)(x + (long long)row * Dd);
    float4 v = xr[tid];
    __shared__ float s[256];

    s[tid] = v.x + v.y + v.z + v.w;
    __syncthreads();
    for (int o = 128; o > 0; o >>= 1) { if (tid < o) s[tid] += s[tid + o]; __syncthreads(); }
    float mu = s[0] * (1.0f / Dd);
    __syncthreads();

    float dx = v.x - mu, dy = v.y - mu, dz = v.z - mu, dw = v.w - mu;
    s[tid] = dx * dx + dy * dy + dz * dz + dw * dw;
    __syncthreads();
    for (int o = 128; o > 0; o >>= 1) { if (tid < o) s[tid] += s[tid + o]; __syncthreads(); }
    float rstd = rsqrtf(s[0] * (1.0f / Dd) + 1e-5f);

    float4 gg = ((const float4*)g)[tid];
    float4 bb = ((const float4*)b)[tid];
    float4 o4;
    o4.x = dx * rstd * gg.x + bb.x;
    o4.y = dy * rstd * gg.y + bb.y;
    o4.z = dz * rstd * gg.z + bb.z;
    o4.w = dw * rstd * gg.w + bb.w;
    ((float4*)(out + (long long)row * Dd))[tid] = o4;
}

// ---------------- row softmax over 2048 cols (in place) ----------------
__global__ __launch_bounds__(256) void softmax_k(float* __restrict__ S) {
    long long row = blockIdx.x;
    float4* r4 = (float4*)(S + row * (long long)Nn);
    int tid = threadIdx.x;
    float4 a = r4[tid], b = r4[tid + 256];
    __shared__ float s[256];

    float mx = fmaxf(fmaxf(fmaxf(a.x, a.y), fmaxf(a.z, a.w)),
                     fmaxf(fmaxf(b.x, b.y), fmaxf(b.z, b.w)));
    s[tid] = mx; __syncthreads();
    for (int o = 128; o > 0; o >>= 1) { if (tid < o) s[tid] = fmaxf(s[tid], s[tid + o]); __syncthreads(); }
    mx = s[0]; __syncthreads();

    a.x = expf(a.x - mx); a.y = expf(a.y - mx); a.z = expf(a.z - mx); a.w = expf(a.w - mx);
    b.x = expf(b.x - mx); b.y = expf(b.y - mx); b.z = expf(b.z - mx); b.w = expf(b.w - mx);
    s[tid] = a.x + a.y + a.z + a.w + b.x + b.y + b.z + b.w;
    __syncthreads();
    for (int o = 128; o > 0; o >>= 1) { if (tid < o) s[tid] += s[tid + o]; __syncthreads(); }
    float inv = 1.0f / s[0];

    a.x *= inv; a.y *= inv; a.z *= inv; a.w *= inv;
    b.x *= inv; b.y *= inv; b.z *= inv; b.w *= inv;
    r4[tid] = a; r4[tid + 256] = b;
}

// ---------------- router: logits + noisy softplus + top-2 ----------------
__global__ __launch_bounds__(256) void route_kernel(const float* __restrict__ x2,
                                                    const float* __restrict__ wr,
                                                    const float* __restrict__ br,
                                                    const float* __restrict__ wn,
                                                    const float* __restrict__ bn,
                                                    const float* __restrict__ noise,
                                                    int2* __restrict__ topi,
                                                    float2* __restrict__ tw) {
    int t    = blockIdx.x * 8 + (threadIdx.x >> 5);
    int lane = threadIdx.x & 31;
    if (t >= Tn) return;
    const float* xr = x2 + (long long)t * Dd;

    float aR[4] = {0, 0, 0, 0}, aN[4] = {0, 0, 0, 0};
    for (int d = lane; d < Dd; d += 32) {
        float xv = xr[d];
        float4 r = ((const float4*)wr)[d];
        float4 nq = ((const float4*)wn)[d];
        aR[0] += xv * r.x;  aR[1] += xv * r.y;  aR[2] += xv * r.z;  aR[3] += xv * r.w;
        aN[0] += xv * nq.x; aN[1] += xv * nq.y; aN[2] += xv * nq.z; aN[3] += xv * nq.w;
    }
#pragma unroll
    for (int o = 16; o > 0; o >>= 1) {
#pragma unroll
        for (int e = 0; e < 4; e++) {
            aR[e] += __shfl_down_sync(0xffffffffu, aR[e], o);
            aN[e] += __shfl_down_sync(0xffffffffu, aN[e], o);
        }
    }
    if (lane == 0) {
        float nv[4];
#pragma unroll
        for (int e = 0; e < 4; e++) {
            float lg  = aR[e] + br[e];
            float pre = aN[e] + bn[e];
            float sp  = (pre > 20.0f) ? pre : log1pf(expf(pre));
            nv[e] = lg + noise[t * 4 + e] * sp;
        }
        int e0 = 0;
#pragma unroll
        for (int e = 1; e < 4; e++) if (nv[e] > nv[e0]) e0 = e;
        int e1 = -1;
#pragma unroll
        for (int e = 0; e < 4; e++) if (e != e0 && (e1 < 0 || nv[e] > nv[e1])) e1 = e;
        float d  = expf(nv[e1] - nv[e0]);
        float p0 = 1.0f / (1.0f + d);
        topi[t] = make_int2(e0, e1);
        tw[t]   = make_float2(p0, d * p0);
    }
}

// ---------------- capacity scan: stable order per expert ----------------
__global__ __launch_bounds__(1024) void scan_kernel(const int2* __restrict__ topi,
                                                    int* __restrict__ sel,
                                                    int* __restrict__ tslot) {
    int e = blockIdx.x;
    int tid = threadIdx.x;
    __shared__ int s[1024];

    int m[4]; int cnt = 0;
#pragma unroll
    for (int i = 0; i < 4; i++) {
        int t = tid * 4 + i;
        int2 ti = topi[t];
        m[i] = (ti.x == e) ? 1 : ((ti.y == e) ? 2 : 0);
        cnt += (m[i] != 0);
    }
    s[tid] = cnt;
    __syncthreads();
    for (int off = 1; off < 1024; off <<= 1) {
        int v = 0;
        if (tid >= off) v = s[tid - off];
        __syncthreads();
        s[tid] += v;
        __syncthreads();
    }
    int total = s[1023];
    int rank  = s[tid] - cnt;  // exclusive prefix
#pragma unroll
    for (int i = 0; i < 4; i++) {
        if (m[i]) {
            int t = tid * 4 + i;
            int j = m[i] - 1;
            if (rank < CAP) { sel[e * CAP + rank] = t; tslot[t * 2 + j] = rank; }
            else            { tslot[t * 2 + j] = -1; }
            rank++;
        }
    }
    for (int r = total + tid; r < CAP; r += 1024) sel[e * CAP + r] = 0;  // fillers (weight 0)
}

// ---------------- final combine: out = xres + mlp + gated expert outs ----
__global__ __launch_bounds__(256) void final_kernel(const float* __restrict__ xres,
                                                    const float* __restrict__ mlp,
                                                    const float* __restrict__ moeout,
                                                    const int2* __restrict__ topi,
                                                    const int* __restrict__ tslot,
                                                    const float2* __restrict__ tw,
                                                    float* __restrict__ out) {
    long long idx = (long long)blockIdx.x * blockDim.x + threadIdx.x;
    int t = (int)(idx >> 10);
    int dcol = (int)(idx & 1023);
    float v = xres[idx] + mlp[idx];
    int2 ti = topi[t];
    float2 w = tw[t];
    int s0 = tslot[t * 2], s1 = tslot[t * 2 + 1];
    if (s0 >= 0) v += w.x * moeout[((long long)ti.x * CAP + s0) * Dd + dcol];
    if (s1 >= 0) v += w.y * moeout[((long long)ti.y * CAP + s1) * Dd + dcol];
    out[idx] = v;
}

extern "C" void kernel_launch(void* const* d_in, const int* in_sizes, int n_in,
                              void* d_out, int out_size) {
    const float* x       = (const float*)d_in[0];
    const float* noise   = (const float*)d_in[1];
    const float* ln1_g   = (const float*)d_in[2];
    const float* ln1_b   = (const float*)d_in[3];
    const float* ln2_g   = (const float*)d_in[4];
    const float* ln2_b   = (const float*)d_in[5];
    const float* w_qkv   = (const float*)d_in[6];
    const float* w_proj  = (const float*)d_in[7];
    const float* b_proj  = (const float*)d_in[8];
    const float* w_route = (const float*)d_in[9];
    const float* b_route = (const float*)d_in[10];
    const float* w_noise = (const float*)d_in[11];
    const float* b_noise = (const float*)d_in[12];
    const float* we1     = (const float*)d_in[13];
    const float* be1     = (const float*)d_in[14];
    const float* we2     = (const float*)d_in[15];
    const float* be2     = (const float*)d_in[16];
    const float* w_mlp1  = (const float*)d_in[17];
    const float* b_mlp1  = (const float*)d_in[18];
    const float* w_mlp2  = (const float*)d_in[19];
    const float* b_mlp2  = (const float*)d_in[20];
    float* out = (float*)d_out;

    float*  buf;   cudaGetSymbolAddress((void**)&buf,   g_buf);
    int2*   topi;  cudaGetSymbolAddress((void**)&topi,  g_topi);
    float2* tw;    cudaGetSymbolAddress((void**)&tw,    g_tw);
    int*    tslot; cudaGetSymbolAddress((void**)&tslot, g_tslot);
    int*    sel;   cudaGetSymbolAddress((void**)&sel,   g_sel);

    float* S      = buf + OFF_S;
    float* qkv    = buf + OFF_QKV;
    float* hmlp   = buf + OFF_HMLP;
    float* x1     = buf + OFF_X1;
    float* ao     = buf + OFF_AO;
    float* xres   = buf + OFF_XRES;
    float* x2     = buf + OFF_X2;
    float* mlpout = buf + OFF_MLPOUT;
    float* moeout = buf + OFF_MOEOUT;
    float* hmoe   = buf + OFF_HMOE;

    // 1) LN1
    ln_kernel<<<Tn, 256>>>(x, ln1_g, ln1_b, x1);

    // 2) QKV = x1 @ w_qkv^T   (4096 x 3072 x 1024)
    {
        GemmP p{}; p.zdiv = 1; p.alpha = 1.0f; p.K = Dd;
        p.A = x1; p.lda = Dd;
        p.B = w_qkv; p.ldb = Dd;
        p.C = qkv; p.ldc = 3 * Dd;
        launch_g<128, true, false>(p, Tn, 3 * Dd, 1);
    }

    // 3) Attention in 4 chunks of 8 heads (reuse S buffer)
    for (int gch = 0; gch < 4; gch++) {
        int b = gch >> 1, h0 = (gch & 1) * 8;
        long long qoff = (long long)b * Nn * (3 * Dd) + (long long)h0 * HD;

        GemmP p{}; p.zdiv = 8; p.alpha = 0.125f; p.K = HD;  // hd^-0.5 = 1/8
        p.A = qkv + qoff;      p.lda = 3 * Dd; p.sA1 = HD;
        p.B = qkv + Dd + qoff; p.ldb = 3 * Dd; p.sB1 = HD;
        p.C = S;               p.ldc = Nn;     p.sC1 = (long long)Nn * Nn;
        launch_g<128, true, false>(p, Nn, Nn, 8);

        softmax_k<<<8 * Nn, 256>>>(S);

        GemmP q{}; q.zdiv = 8; q.alpha = 1.0f; q.K = Nn;
        q.A = S;                    q.lda = Nn;     q.sA1 = (long long)Nn * Nn;
        q.B = qkv + 2 * Dd + qoff;  q.ldb = 3 * Dd; q.sB1 = HD;
        q.C = ao + (long long)b * Nn * Dd + (long long)h0 * HD;
        q.ldc = Dd; q.sC1 = HD;
        launch_g<64, false, false>(q, Nn, HD, 8);
    }

    // 4) xres = x + ao @ w_proj^T + b_proj
    {
        GemmP p{}; p.zdiv = 1; p.alpha = 1.0f; p.K = Dd;
        p.A = ao; p.lda = Dd;
        p.B = w_proj; p.ldb = Dd;
        p.C = xres; p.ldc = Dd;
        p.bias = b_proj; p.res = x; p.ldres = Dd;
        p.epi = 1 | 4;
        launch_g<128, true, false>(p, Tn, Dd, 1);
    }

    // 5) LN2
    ln_kernel<<<Tn, 256>>>(xres, ln2_g, ln2_b, x2);

    // 6) routing (noisy top-2)
    route_kernel<<<Tn / 8, 256>>>(x2, w_route, b_route, w_noise, b_noise, noise, topi, tw);

    // 7) per-expert stable capacity scan
    scan_kernel<<<Ee, 1024>>>(topi, sel, tslot);

    // 8) MoE expert GEMM 1 (gathered rows): gelu(Xsel @ we1[e] + be1[e])
    {
        GemmP p{}; p.zdiv = 1; p.alpha = 1.0f; p.K = Dd;
        p.A = x2; p.lda = Dd;
        p.gidx = sel; p.sG = CAP;
        p.B = we1; p.ldb = MOEH; p.sB0 = (long long)Dd * MOEH;
        p.C = hmoe; p.ldc = MOEH; p.sC0 = (long long)CAP * MOEH;
        p.bias = be1; p.sBias = MOEH;
        p.epi = 1 | 2;
        launch_g<128, false, true>(p, CAP, MOEH, Ee);
    }

    // 9) MoE expert GEMM 2: h_e @ we2[e] + be2[e]
    {
        GemmP p{}; p.zdiv = 1; p.alpha = 1.0f; p.K = MOEH;
        p.A = hmoe; p.lda = MOEH; p.sA0 = (long long)CAP * MOEH;
        p.B = we2; p.ldb = Dd; p.sB0 = (long long)MOEH * Dd;
        p.C = moeout; p.ldc = Dd; p.sC0 = (long long)CAP * Dd;
        p.bias = be2; p.sBias = Dd;
        p.epi = 1;
        launch_g<128, false, false>(p, CAP, Dd, Ee);
    }

    // 10) MLP1: gelu(x2 @ w_mlp1 + b_mlp1)
    {
        GemmP p{}; p.zdiv = 1; p.alpha = 1.0f; p.K = Dd;
        p.A = x2; p.lda = Dd;
        p.B = w_mlp1; p.ldb = MLPH;
        p.C = hmlp; p.ldc = MLPH;
        p.bias = b_mlp1;
        p.epi = 1 | 2;
        launch_g<128, false, false>(p, Tn, MLPH, 1);
    }

    // 11) MLP2: hmlp @ w_mlp2 + b_mlp2
    {
        GemmP p{}; p.zdiv = 1; p.alpha = 1.0f; p.K = MLPH;
        p.A = hmlp; p.lda = MLPH;
        p.B = w_mlp2; p.ldb = Dd;
        p.C = mlpout; p.ldc = Dd;
        p.bias = b_mlp2;
        p.epi = 1;
        launch_g<128, false, false>(p, Tn, Dd, 1);
    }

    // 12) out = xres + mlp + gated MoE (gather; deterministic, no atomics)
    final_kernel<<<(Tn * Dd) / 256, 256>>>(xres, mlpout, moeout, topi, tslot, tw, out);
}

// round 3
// speedup vs baseline: 2.2588x; 1.2401x over previous
#include <cuda_runtime.h>
#include <math.h>
#include <stdint.h>

// ---------------- problem constants ----------------
#define Tn   4096      // B*N tokens
#define Dd   1024
#define Hh   16
#define HD   64
#define Nn   2048
#define Bb   2
#define Ee   4
#define CAP  2048
#define MLPH 4096
#define MOEH 256

// ---------------- scratch (__device__ globals; no allocations allowed) ----
#define OFF_S      0LL
#define OFF_QKV    33554432LL
#define OFF_HMLP   46137344LL
#define OFF_X1     62914560LL
#define OFF_AO     67108864LL
#define OFF_XRES   71303168LL
#define OFF_X2     75497472LL
#define OFF_MLPOUT 79691776LL
#define OFF_MOEOUT 83886080LL
#define OFF_HMOE   92274688LL
#define BUF_TOTAL  94371840LL

__device__ float  g_buf[BUF_TOTAL];
__device__ int2   g_topi[Tn];
__device__ float2 g_tw[Tn];
__device__ int    g_tslot[Tn * 2];
__device__ int    g_sel[Ee * CAP];

// ---------------- helpers ----------------
__device__ __forceinline__ float gelu_f(float x) {
    return 0.5f * x * (1.0f + erff(x * 0.7071067811865476f));
}
__device__ __forceinline__ unsigned f2tf(float x) {
    unsigned u;
    asm("cvt.rna.tf32.f32 %0, %1;" : "=r"(u) : "f"(x));
    return u;
}
__device__ __forceinline__ void cp16(float* dst, const float* src) {
    unsigned s = (unsigned)__cvta_generic_to_shared(dst);
    asm volatile("cp.async.cg.shared.global [%0], [%1], 16;" :: "r"(s), "l"(src));
}
#define CP_COMMIT() asm volatile("cp.async.commit_group;")
#define CP_WAIT1()  asm volatile("cp.async.wait_group 1;")

// ---------------- tf32 tensor-core batched GEMM (cp.async 2-stage) -------
// C[m,n] = alpha * sum_k A[m,k] * (TB ? B[n,k] : B[k,n])   (+bias)(gelu)(+res)
// K-tile 32, 256 threads (8 warps). Requires M%BM==0, N%BN==0, K%64==0 (>=2 tiles).
struct GemmP {
    const float* A; const float* B; float* C;
    const float* bias; const float* res; const int* gidx;
    int lda, ldb, ldc, ldres;
    long long sA0, sA1, sB0, sB1, sC0, sC1, sBias, sG;
    int zdiv;
    int K;
    float alpha;
    int epi;  // bit0: +bias[n], bit1: gelu, bit2: +res[m,n]
};

template <int BM, int BN, bool TB, bool GATHER>
__global__ __launch_bounds__(256) void tgemm2(GemmP p) {
    constexpr bool SMALL = (BM == 128 && BN == 64);
    constexpr int WM = SMALL ? 32 : 64;
    constexpr int WN = SMALL ? 32 : 64;
    constexpr int WARPS_M = BM / WM;
    constexpr int MT = WM / 16;
    constexpr int NT = WN / 8;
    constexpr int LDA = 36;                    // 32 + 4 pad
    constexpr int LDBN = BN + 8;               // k-major B pad
    constexpr int ASZ = BM * LDA;
    constexpr int BSZ = TB ? BN * 36 : 32 * LDBN;
    constexpr int STAGE = ASZ + BSZ;
    constexpr int ACH = BM / 32;               // A float4 chunks per thread
    constexpr int BCH = BN / 32;               // B float4 chunks per thread

    extern __shared__ float sm[];

    int z  = blockIdx.z;
    int zo = z / p.zdiv, zi = z - zo * p.zdiv;
    const float* A = p.A + zo * p.sA0 + zi * p.sA1;
    const float* B = p.B + zo * p.sB0 + zi * p.sB1;
    float*       C = p.C + zo * p.sC0 + zi * p.sC1;

    int m0 = blockIdx.x * BM, n0 = blockIdx.y * BN;
    int t = threadIdx.x;
    int w = t >> 5, lane = t & 31;
    int wm = w % WARPS_M, wn = w / WARPS_M;
    int g = lane >> 2, tig = lane & 3;

    // ---- A loader: fixed row per thread ----
    int arowi, ac4;
    if (BM == 128) { arowi = t >> 1; ac4 = (t & 1) * 4; }
    else           { arowi = t;      ac4 = 0; }
    long long arow = m0 + arowi;
    if (GATHER) arow = p.gidx[zo * p.sG + m0 + arowi];
    const float* gA = A + arow * (long long)p.lda;
    int sA0off = arowi * LDA + ac4 * 4;

    // ---- B loader: fixed row per thread ----
    int brow, bc4, sB0off;
    const float* gB;
    if (!TB) {
        brow = t >> 3; bc4 = (t & 7) * BCH;
        gB = B + (long long)brow * p.ldb + n0;
        sB0off = brow * LDBN + bc4 * 4;
    } else {
        brow = t >> 1; bc4 = (t & 1) * 4;
        gB = B + (long long)(n0 + brow) * p.ldb;
        sB0off = brow * 36 + bc4 * 4;
    }

    float acc[MT][NT][4];
#pragma unroll
    for (int i = 0; i < MT; i++)
#pragma unroll
        for (int j = 0; j < NT; j++)
#pragma unroll
            for (int q = 0; q < 4; q++) acc[i][j][q] = 0.0f;

    auto load_tile = [&](int ti, int buf) {
        float* As_ = sm + buf * STAGE;
        float* Bs_ = As_ + ASZ;
        int kt = ti * 32;
#pragma unroll
        for (int j = 0; j < ACH; j++)
            cp16(As_ + sA0off + j * 4, gA + kt + ac4 * 4 + j * 4);
        if (!TB) {
#pragma unroll
            for (int j = 0; j < BCH; j++)
                cp16(Bs_ + sB0off + j * 4, gB + (long long)kt * p.ldb + (bc4 + j) * 4);
        } else {
#pragma unroll
            for (int j = 0; j < BCH; j++)
                cp16(Bs_ + sB0off + j * 4, gB + kt + (bc4 + j) * 4);
        }
        CP_COMMIT();
    };

    auto compute = [&](int buf) {
        const float* As_ = sm + buf * STAGE;
        const float* Bs_ = As_ + ASZ;
#pragma unroll
        for (int ks = 0; ks < 4; ks++) {
            unsigned a[MT][4];
            unsigned b[NT][2];
#pragma unroll
            for (int mt = 0; mt < MT; mt++) {
                int base = (wm * WM + mt * 16 + g) * LDA + ks * 8 + tig;
                a[mt][0] = f2tf(As_[base]);
                a[mt][1] = f2tf(As_[base + 8 * LDA]);
                a[mt][2] = f2tf(As_[base + 4]);
                a[mt][3] = f2tf(As_[base + 8 * LDA + 4]);
            }
#pragma unroll
            for (int nt = 0; nt < NT; nt++) {
                if (!TB) {
                    int base = (ks * 8 + tig) * LDBN + wn * WN + nt * 8 + g;
                    b[nt][0] = f2tf(Bs_[base]);
                    b[nt][1] = f2tf(Bs_[base + 4 * LDBN]);
                } else {
                    int base = (wn * WN + nt * 8 + g) * 36 + ks * 8 + tig;
                    b[nt][0] = f2tf(Bs_[base]);
                    b[nt][1] = f2tf(Bs_[base + 4]);
                }
            }
#pragma unroll
            for (int mt = 0; mt < MT; mt++)
#pragma unroll
                for (int nt = 0; nt < NT; nt++)
                    asm volatile(
                        "mma.sync.aligned.m16n8k8.row.col.f32.tf32.tf32.f32 "
                        "{%0,%1,%2,%3}, {%4,%5,%6,%7}, {%8,%9}, {%0,%1,%2,%3};"
                        : "+f"(acc[mt][nt][0]), "+f"(acc[mt][nt][1]),
                          "+f"(acc[mt][nt][2]), "+f"(acc[mt][nt][3])
                        : "r"(a[mt][0]), "r"(a[mt][1]), "r"(a[mt][2]), "r"(a[mt][3]),
                          "r"(b[nt][0]), "r"(b[nt][1]));
        }
    };

    // ---- 2-stage pipelined mainloop ----
    int ntiles = p.K >> 5;
    load_tile(0, 0);
    load_tile(1, 1);
    for (int i = 0; i < ntiles; i++) {
        CP_WAIT1();
        __syncthreads();
        compute(i & 1);
        __syncthreads();
        if (i + 2 < ntiles) load_tile(i + 2, i & 1);
        else CP_COMMIT();          // empty group keeps wait_group invariant
    }

    // ---- epilogue ----
    const float* bias = p.bias ? (p.bias + zo * p.sBias) : nullptr;
#pragma unroll
    for (int mt = 0; mt < MT; mt++) {
#pragma unroll
        for (int half = 0; half < 2; half++) {
            int m = m0 + wm * WM + mt * 16 + g + half * 8;
#pragma unroll
            for (int nt = 0; nt < NT; nt++) {
                int n = n0 + wn * WN + nt * 8 + tig * 2;
                float v0 = acc[mt][nt][half * 2 + 0] * p.alpha;
                float v1 = acc[mt][nt][half * 2 + 1] * p.alpha;
                if (p.epi & 1) { v0 += bias[n]; v1 += bias[n + 1]; }
                if (p.epi & 2) { v0 = gelu_f(v0); v1 = gelu_f(v1); }
                if (p.epi & 4) {
                    v0 += p.res[(long long)m * p.ldres + n];
                    v1 += p.res[(long long)m * p.ldres + n + 1];
                }
                *(float2*)&C[(long long)m * p.ldc + n] = make_float2(v0, v1);
            }
        }
    }
}

template <int BM, int BN, bool TB, bool GATHER>
static void launch2(const GemmP& p, int M, int N, int batch) {
    constexpr int ASZ = BM * 36;
    constexpr int BSZ = TB ? BN * 36 : 32 * (BN + 8);
    int smem = 2 * (ASZ + BSZ) * 4;
    cudaFuncSetAttribute(tgemm2<BM, BN, TB, GATHER>,
                         cudaFuncAttributeMaxDynamicSharedMemorySize, smem);
    dim3 grid(M / BM, N / BN, batch);
    tgemm2<BM, BN, TB, GATHER><<<grid, 256, smem>>>(p);
}

// ---------------- layernorm (one block per row, D = 1024) ----------------
__global__ __launch_bounds__(256) void ln_kernel(const float* __restrict__ x,
                                                 const float* __restrict__ g,
                                                 const float* __restrict__ b,
                                                 float* __restrict__ out) {
    int row = blockIdx.x;
    int tid = threadIdx.x;
    const float4* xr = (const float4*)(x + (long long)row * Dd);
    float4 v = xr[tid];
    __shared__ float s[256];

    s[tid] = v.x + v.y + v.z + v.w;
    __syncthreads();
    for (int o = 128; o > 0; o >>= 1) { if (tid < o) s[tid] += s[tid + o]; __syncthreads(); }
    float mu = s[0] * (1.0f / Dd);
    __syncthreads();

    float dx = v.x - mu, dy = v.y - mu, dz = v.z - mu, dw = v.w - mu;
    s[tid] = dx * dx + dy * dy + dz * dz + dw * dw;
    __syncthreads();
    for (int o = 128; o > 0; o >>= 1) { if (tid < o) s[tid] += s[tid + o]; __syncthreads(); }
    float rstd = rsqrtf(s[0] * (1.0f / Dd) + 1e-5f);

    float4 gg = ((const float4*)g)[tid];
    float4 bb = ((const float4*)b)[tid];
    float4 o4;
    o4.x = dx * rstd * gg.x + bb.x;
    o4.y = dy * rstd * gg.y + bb.y;
    o4.z = dz * rstd * gg.z + bb.z;
    o4.w = dw * rstd * gg.w + bb.w;
    ((float4*)(out + (long long)row * Dd))[tid] = o4;
}

// ---------------- row softmax over 2048 cols (in place) ----------------
__global__ __launch_bounds__(256) void softmax_k(float* __restrict__ S) {
    long long row = blockIdx.x;
    float4* r4 = (float4*)(S + row * (long long)Nn);
    int tid = threadIdx.x;
    float4 a = r4[tid], b = r4[tid + 256];
    __shared__ float s[256];

    float mx = fmaxf(fmaxf(fmaxf(a.x, a.y), fmaxf(a.z, a.w)),
                     fmaxf(fmaxf(b.x, b.y), fmaxf(b.z, b.w)));
    s[tid] = mx; __syncthreads();
    for (int o = 128; o > 0; o >>= 1) { if (tid < o) s[tid] = fmaxf(s[tid], s[tid + o]); __syncthreads(); }
    mx = s[0]; __syncthreads();

    a.x = expf(a.x - mx); a.y = expf(a.y - mx); a.z = expf(a.z - mx); a.w = expf(a.w - mx);
    b.x = expf(b.x - mx); b.y = expf(b.y - mx); b.z = expf(b.z - mx); b.w = expf(b.w - mx);
    s[tid] = a.x + a.y + a.z + a.w + b.x + b.y + b.z + b.w;
    __syncthreads();
    for (int o = 128; o > 0; o >>= 1) { if (tid < o) s[tid] += s[tid + o]; __syncthreads(); }
    float inv = 1.0f / s[0];

    a.x *= inv; a.y *= inv; a.z *= inv; a.w *= inv;
    b.x *= inv; b.y *= inv; b.z *= inv; b.w *= inv;
    r4[tid] = a; r4[tid + 256] = b;
}

// ---------------- router: logits + noisy softplus + top-2 ----------------
__global__ __launch_bounds__(256) void route_kernel(const float* __restrict__ x2,
                                                    const float* __restrict__ wr,
                                                    const float* __restrict__ br,
                                                    const float* __restrict__ wn,
                                                    const float* __restrict__ bn,
                                                    const float* __restrict__ noise,
                                                    int2* __restrict__ topi,
                                                    float2* __restrict__ tw) {
    int t    = blockIdx.x * 8 + (threadIdx.x >> 5);
    int lane = threadIdx.x & 31;
    if (t >= Tn) return;
    const float* xr = x2 + (long long)t * Dd;

    float aR[4] = {0, 0, 0, 0}, aN[4] = {0, 0, 0, 0};
    for (int d = lane; d < Dd; d += 32) {
        float xv = xr[d];
        float4 r = ((const float4*)wr)[d];
        float4 nq = ((const float4*)wn)[d];
        aR[0] += xv * r.x;  aR[1] += xv * r.y;  aR[2] += xv * r.z;  aR[3] += xv * r.w;
        aN[0] += xv * nq.x; aN[1] += xv * nq.y; aN[2] += xv * nq.z; aN[3] += xv * nq.w;
    }
#pragma unroll
    for (int o = 16; o > 0; o >>= 1) {
#pragma unroll
        for (int e = 0; e < 4; e++) {
            aR[e] += __shfl_down_sync(0xffffffffu, aR[e], o);
            aN[e] += __shfl_down_sync(0xffffffffu, aN[e], o);
        }
    }
    if (lane == 0) {
        float nv[4];
#pragma unroll
        for (int e = 0; e < 4; e++) {
            float lg  = aR[e] + br[e];
            float pre = aN[e] + bn[e];
            float sp  = (pre > 20.0f) ? pre : log1pf(expf(pre));
            nv[e] = lg + noise[t * 4 + e] * sp;
        }
        int e0 = 0;
#pragma unroll
        for (int e = 1; e < 4; e++) if (nv[e] > nv[e0]) e0 = e;
        int e1 = -1;
#pragma unroll
        for (int e = 0; e < 4; e++) if (e != e0 && (e1 < 0 || nv[e] > nv[e1])) e1 = e;
        float d  = expf(nv[e1] - nv[e0]);
        float p0 = 1.0f / (1.0f + d);
        topi[t] = make_int2(e0, e1);
        tw[t]   = make_float2(p0, d * p0);
    }
}

// ---------------- capacity scan: stable order per expert ----------------
__global__ __launch_bounds__(1024) void scan_kernel(const int2* __restrict__ topi,
                                                    int* __restrict__ sel,
                                                    int* __restrict__ tslot) {
    int e = blockIdx.x;
    int tid = threadIdx.x;
    __shared__ int s[1024];

    int m[4]; int cnt = 0;
#pragma unroll
    for (int i = 0; i < 4; i++) {
        int t = tid * 4 + i;
        int2 ti = topi[t];
        m[i] = (ti.x == e) ? 1 : ((ti.y == e) ? 2 : 0);
        cnt += (m[i] != 0);
    }
    s[tid] = cnt;
    __syncthreads();
    for (int off = 1; off < 1024; off <<= 1) {
        int v = 0;
        if (tid >= off) v = s[tid - off];
        __syncthreads();
        s[tid] += v;
        __syncthreads();
    }
    int total = s[1023];
    int rank  = s[tid] - cnt;  // exclusive prefix
#pragma unroll
    for (int i = 0; i < 4; i++) {
        if (m[i]) {
            int t = tid * 4 + i;
            int j = m[i] - 1;
            if (rank < CAP) { sel[e * CAP + rank] = t; tslot[t * 2 + j] = rank; }
            else            { tslot[t * 2 + j] = -1; }
            rank++;
        }
    }
    for (int r = total + tid; r < CAP; r += 1024) sel[e * CAP + r] = 0;  // fillers (weight 0)
}

// ---------------- final combine: out = xres + mlp + gated expert outs ----
__global__ __launch_bounds__(256) void final_kernel(const float* __restrict__ xres,
                                                    const float* __restrict__ mlp,
                                                    const float* __restrict__ moeout,
                                                    const int2* __restrict__ topi,
                                                    const int* __restrict__ tslot,
                                                    const float2* __restrict__ tw,
                                                    float* __restrict__ out) {
    long long idx = (long long)blockIdx.x * blockDim.x + threadIdx.x;
    int t = (int)(idx >> 10);
    int dcol = (int)(idx & 1023);
    float v = xres[idx] + mlp[idx];
    int2 ti = topi[t];
    float2 w = tw[t];
    int s0 = tslot[t * 2], s1 = tslot[t * 2 + 1];
    if (s0 >= 0) v += w.x * moeout[((long long)ti.x * CAP + s0) * Dd + dcol];
    if (s1 >= 0) v += w.y * moeout[((long long)ti.y * CAP + s1) * Dd + dcol];
    out[idx] = v;
}

extern "C" void kernel_launch(void* const* d_in, const int* in_sizes, int n_in,
                              void* d_out, int out_size) {
    const float* x       = (const float*)d_in[0];
    const float* noise   = (const float*)d_in[1];
    const float* ln1_g   = (const float*)d_in[2];
    const float* ln1_b   = (const float*)d_in[3];
    const float* ln2_g   = (const float*)d_in[4];
    const float* ln2_b   = (const float*)d_in[5];
    const float* w_qkv   = (const float*)d_in[6];
    const float* w_proj  = (const float*)d_in[7];
    const float* b_proj  = (const float*)d_in[8];
    const float* w_route = (const float*)d_in[9];
    const float* b_route = (const float*)d_in[10];
    const float* w_noise = (const float*)d_in[11];
    const float* b_noise = (const float*)d_in[12];
    const float* we1     = (const float*)d_in[13];
    const float* be1     = (const float*)d_in[14];
    const float* we2     = (const float*)d_in[15];
    const float* be2     = (const float*)d_in[16];
    const float* w_mlp1  = (const float*)d_in[17];
    const float* b_mlp1  = (const float*)d_in[18];
    const float* w_mlp2  = (const float*)d_in[19];
    const float* b_mlp2  = (const float*)d_in[20];
    float* out = (float*)d_out;

    float*  buf;   cudaGetSymbolAddress((void**)&buf,   g_buf);
    int2*   topi;  cudaGetSymbolAddress((void**)&topi,  g_topi);
    float2* tw;    cudaGetSymbolAddress((void**)&tw,    g_tw);
    int*    tslot; cudaGetSymbolAddress((void**)&tslot, g_tslot);
    int*    sel;   cudaGetSymbolAddress((void**)&sel,   g_sel);

    float* S      = buf + OFF_S;
    float* qkv    = buf + OFF_QKV;
    float* hmlp   = buf + OFF_HMLP;
    float* x1     = buf + OFF_X1;
    float* ao     = buf + OFF_AO;
    float* xres   = buf + OFF_XRES;
    float* x2     = buf + OFF_X2;
    float* mlpout = buf + OFF_MLPOUT;
    float* moeout = buf + OFF_MOEOUT;
    float* hmoe   = buf + OFF_HMOE;

    // 1) LN1
    ln_kernel<<<Tn, 256>>>(x, ln1_g, ln1_b, x1);

    // 2) QKV = x1 @ w_qkv^T   (4096 x 3072 x 1024)
    {
        GemmP p{}; p.zdiv = 1; p.alpha = 1.0f; p.K = Dd;
        p.A = x1; p.lda = Dd;
        p.B = w_qkv; p.ldb = Dd;
        p.C = qkv; p.ldc = 3 * Dd;
        launch2<256, 128, true, false>(p, Tn, 3 * Dd, 1);
    }

    // 3) Attention in 4 chunks of 8 heads (reuse S buffer)
    for (int gch = 0; gch < 4; gch++) {
        int b = gch >> 1, h0 = (gch & 1) * 8;
        long long qoff = (long long)b * Nn * (3 * Dd) + (long long)h0 * HD;

        GemmP p{}; p.zdiv = 8; p.alpha = 0.125f; p.K = HD;  // hd^-0.5 = 1/8
        p.A = qkv + qoff;      p.lda = 3 * Dd; p.sA1 = HD;
        p.B = qkv + Dd + qoff; p.ldb = 3 * Dd; p.sB1 = HD;
        p.C = S;               p.ldc = Nn;     p.sC1 = (long long)Nn * Nn;
        launch2<256, 128, true, false>(p, Nn, Nn, 8);

        softmax_k<<<8 * Nn, 256>>>(S);

        GemmP q{}; q.zdiv = 8; q.alpha = 1.0f; q.K = Nn;
        q.A = S;                    q.lda = Nn;     q.sA1 = (long long)Nn * Nn;
        q.B = qkv + 2 * Dd + qoff;  q.ldb = 3 * Dd; q.sB1 = HD;
        q.C = ao + (long long)b * Nn * Dd + (long long)h0 * HD;
        q.ldc = Dd; q.sC1 = HD;
        launch2<128, 64, false, false>(q, Nn, HD, 8);
    }

    // 4) xres = x + ao @ w_proj^T + b_proj
    {
        GemmP p{}; p.zdiv = 1; p.alpha = 1.0f; p.K = Dd;
        p.A = ao; p.lda = Dd;
        p.B = w_proj; p.ldb = Dd;
        p.C = xres; p.ldc = Dd;
        p.bias = b_proj; p.res = x; p.ldres = Dd;
        p.epi = 1 | 4;
        launch2<256, 128, true, false>(p, Tn, Dd, 1);
    }

    // 5) LN2
    ln_kernel<<<Tn, 256>>>(xres, ln2_g, ln2_b, x2);

    // 6) routing (noisy top-2)
    route_kernel<<<Tn / 8, 256>>>(x2, w_route, b_route, w_noise, b_noise, noise, topi, tw);

    // 7) per-expert stable capacity scan
    scan_kernel<<<Ee, 1024>>>(topi, sel, tslot);

    // 8) MoE expert GEMM 1 (gathered rows): gelu(Xsel @ we1[e] + be1[e])
    {
        GemmP p{}; p.zdiv = 1; p.alpha = 1.0f; p.K = Dd;
        p.A = x2; p.lda = Dd;
        p.gidx = sel; p.sG = CAP;
        p.B = we1; p.ldb = MOEH; p.sB0 = (long long)Dd * MOEH;
        p.C = hmoe; p.ldc = MOEH; p.sC0 = (long long)CAP * MOEH;
        p.bias = be1; p.sBias = MOEH;
        p.epi = 1 | 2;
        launch2<128, 256, false, true>(p, CAP, MOEH, Ee);
    }

    // 9) MoE expert GEMM 2: h_e @ we2[e] + be2[e]
    {
        GemmP p{}; p.zdiv = 1; p.alpha = 1.0f; p.K = MOEH;
        p.A = hmoe; p.lda = MOEH; p.sA0 = (long long)CAP * MOEH;
        p.B = we2; p.ldb = Dd; p.sB0 = (long long)MOEH * Dd;
        p.C = moeout; p.ldc = Dd; p.sC0 = (long long)CAP * Dd;
        p.bias = be2; p.sBias = Dd;
        p.epi = 1;
        launch2<128, 256, false, false>(p, CAP, Dd, Ee);
    }

    // 10) MLP1: gelu(x2 @ w_mlp1 + b_mlp1)
    {
        GemmP p{}; p.zdiv = 1; p.alpha = 1.0f; p.K = Dd;
        p.A = x2; p.lda = Dd;
        p.B = w_mlp1; p.ldb = MLPH;
        p.C = hmlp; p.ldc = MLPH;
        p.bias = b_mlp1;
        p.epi = 1 | 2;
        launch2<128, 256, false, false>(p, Tn, MLPH, 1);
    }

    // 11) MLP2: hmlp @ w_mlp2 + b_mlp2
    {
        GemmP p{}; p.zdiv = 1; p.alpha = 1.0f; p.K = MLPH;
        p.A = hmlp; p.lda = MLPH;
        p.B = w_mlp2; p.ldb = Dd;
        p.C = mlpout; p.ldc = Dd;
        p.bias = b_mlp2;
        p.epi = 1;
        launch2<128, 256, false, false>(p, Tn, Dd, 1);
    }

    // 12) out = xres + mlp + gated MoE (gather; deterministic, no atomics)
    final_kernel<<<(Tn * Dd) / 256, 256>>>(xres, mlpout, moeout, topi, tslot, tw, out);
}

// round 5
// speedup vs baseline: 2.6405x; 1.1690x over previous
#include <cuda_runtime.h>
#include <math.h>
#include <stdint.h>

// ---------------- problem constants ----------------
#define Tn   4096      // B*N tokens
#define Dd   1024
#define Hh   16
#define HD   64
#define Nn   2048
#define Bb   2
#define Ee   4
#define CAP  2048
#define MLPH 4096
#define MOEH 256

// ---------------- scratch (__device__ globals; no allocations allowed) ----
#define OFF_QKV    0LL
#define OFF_HMLP   12582912LL
#define OFF_X1     29360128LL
#define OFF_AO     33554432LL
#define OFF_XRES   37748736LL
#define OFF_X2     41943040LL
#define OFF_MLPOUT 46137344LL
#define OFF_MOEOUT 50331648LL
#define OFF_HMOE   58720256LL
#define BUF_TOTAL  60817408LL

__device__ float  g_buf[BUF_TOTAL];
__device__ int2   g_topi[Tn];
__device__ float2 g_tw[Tn];
__device__ int    g_tslot[Tn * 2];
__device__ int    g_sel[Ee * CAP];

// ---------------- helpers ----------------
__device__ __forceinline__ float gelu_f(float x) {
    return 0.5f * x * (1.0f + erff(x * 0.7071067811865476f));
}
__device__ __forceinline__ unsigned f2tf(float x) {
    unsigned u;
    asm("cvt.rna.tf32.f32 %0, %1;" : "=r"(u) : "f"(x));
    return u;
}
__device__ __forceinline__ void cp16(float* dst, const float* src) {
    unsigned s = (unsigned)__cvta_generic_to_shared(dst);
    asm volatile("cp.async.cg.shared.global [%0], [%1], 16;" :: "r"(s), "l"(src));
}
#define CP_COMMIT() asm volatile("cp.async.commit_group;")
#define CP_WAIT1()  asm volatile("cp.async.wait_group 1;")
#define CP_WAIT2()  asm volatile("cp.async.wait_group 2;")

__device__ __forceinline__ void mma8(float* c, const unsigned* a, unsigned b0, unsigned b1) {
    asm volatile(
        "mma.sync.aligned.m16n8k8.row.col.f32.tf32.tf32.f32 "
        "{%0,%1,%2,%3}, {%4,%5,%6,%7}, {%8,%9}, {%0,%1,%2,%3};"
        : "+f"(c[0]), "+f"(c[1]), "+f"(c[2]), "+f"(c[3])
        : "r"(a[0]), "r"(a[1]), "r"(a[2]), "r"(a[3]), "r"(b0), "r"(b1));
}

// ---------------- fused flash attention (tf32 mma) ----------------------
// One CTA = one (b,h) and a 128-row Q tile. 8 warps * 16 rows.
// smem: Qs/Ps 128x68 (reused), Ks 2x 64x68, Vs 2x 64x72.
#define LDQ 68
#define LDK 68
#define LDV 72
#define KS_OFF  8704
#define VS_OFF  17408   // 8704 + 2*4352
#define FLASH_SMEM ((8704 + 2*4352 + 2*4608) * 4)

__global__ __launch_bounds__(256, 1) void flash_k(const float* __restrict__ qkv,
                                                  float* __restrict__ ao) {
    extern __shared__ float sm[];
    float* Qs = sm;                       // later reused as Ps
    int qt = blockIdx.x, bh = blockIdx.y;
    int b = bh >> 4, h = bh & 15;
    const float* base = qkv + (long long)b * Nn * 3072 + h * 64;

    int t = threadIdx.x, w = t >> 5, lane = t & 31;
    int g = lane >> 2, tig = lane & 3;

    // ---- Q tile load (group 0) ----
    {
        int row = t >> 1, c0 = (t & 1) * 32;
        const float* gq = base + (long long)(qt * 128 + row) * 3072 + c0;
        float* sq = Qs + row * LDQ + c0;
#pragma unroll
        for (int j = 0; j < 8; j++) cp16(sq + j * 4, gq + j * 4);
    }
    CP_COMMIT();

    // ---- K/V tile loader ----
    int kr = t >> 2, kc = (t & 3) * 16;
    auto loadKV = [&](int ti, int buf) {
        const float* gk = base + 1024 + (long long)(ti * 64 + kr) * 3072 + kc;
        const float* gv = base + 2048 + (long long)(ti * 64 + kr) * 3072 + kc;
        float* sk = sm + KS_OFF + buf * 4352 + kr * LDK + kc;
        float* sv = sm + VS_OFF + buf * 4608 + kr * LDV + kc;
#pragma unroll
        for (int j = 0; j < 4; j++) cp16(sk + j * 4, gk + j * 4);
#pragma unroll
        for (int j = 0; j < 4; j++) cp16(sv + j * 4, gv + j * 4);
        CP_COMMIT();
    };
    loadKV(0, 0);
    loadKV(1, 1);

    // ---- Q fragments to registers (scaled by hd^-0.5 = 1/8) ----
    unsigned aq[8][4];
    CP_WAIT2();
    __syncthreads();
    {
        int r0 = (w * 16 + g) * LDQ;
#pragma unroll
        for (int ks = 0; ks < 8; ks++) {
            int r = r0 + ks * 8 + tig;
            aq[ks][0] = f2tf(0.125f * Qs[r]);
            aq[ks][1] = f2tf(0.125f * Qs[r + 8 * LDQ]);
            aq[ks][2] = f2tf(0.125f * Qs[r + 4]);
            aq[ks][3] = f2tf(0.125f * Qs[r + 8 * LDQ + 4]);
        }
    }
    __syncthreads();   // Qs now reusable as Ps

    float accO[8][4];
#pragma unroll
    for (int nt = 0; nt < 8; nt++)
#pragma unroll
        for (int q = 0; q < 4; q++) accO[nt][q] = 0.0f;
    float m0 = -3.0e38f, m1 = -3.0e38f;
    float l0 = 0.0f, l1 = 0.0f;

    float* Ps = Qs;
    for (int i = 0; i < 32; i++) {
        int buf = i & 1;
        CP_WAIT1();
        __syncthreads();
        const float* K_ = sm + KS_OFF + buf * 4352;
        const float* V_ = sm + VS_OFF + buf * 4608;

        // ---- S = Q @ K^T ----
        float S[8][4];
#pragma unroll
        for (int nt = 0; nt < 8; nt++)
#pragma unroll
            for (int q = 0; q < 4; q++) S[nt][q] = 0.0f;
#pragma unroll
        for (int ks = 0; ks < 8; ks++) {
#pragma unroll
            for (int nt = 0; nt < 8; nt++) {
                int a = (nt * 8 + g) * LDK + ks * 8 + tig;
                mma8(S[nt], aq[ks], f2tf(K_[a]), f2tf(K_[a + 4]));
            }
        }

        // ---- online softmax ----
        float mx0 = S[0][0], mx1 = S[0][2];
#pragma unroll
        for (int nt = 0; nt < 8; nt++) {
            mx0 = fmaxf(mx0, fmaxf(S[nt][0], S[nt][1]));
            mx1 = fmaxf(mx1, fmaxf(S[nt][2], S[nt][3]));
        }
        mx0 = fmaxf(mx0, __shfl_xor_sync(0xffffffffu, mx0, 1));
        mx0 = fmaxf(mx0, __shfl_xor_sync(0xffffffffu, mx0, 2));
        mx1 = fmaxf(mx1, __shfl_xor_sync(0xffffffffu, mx1, 1));
        mx1 = fmaxf(mx1, __shfl_xor_sync(0xffffffffu, mx1, 2));
        float mn0 = fmaxf(m0, mx0), mn1 = fmaxf(m1, mx1);
        float c0 = __expf(m0 - mn0), c1 = __expf(m1 - mn1);
        m0 = mn0; m1 = mn1;
        float s0 = 0.0f, s1 = 0.0f;
#pragma unroll
        for (int nt = 0; nt < 8; nt++) {
            S[nt][0] = __expf(S[nt][0] - mn0);
            S[nt][1] = __expf(S[nt][1] - mn0);
            S[nt][2] = __expf(S[nt][2] - mn1);
            S[nt][3] = __expf(S[nt][3] - mn1);
            s0 += S[nt][0] + S[nt][1];
            s1 += S[nt][2] + S[nt][3];
        }
        l0 = l0 * c0 + s0;
        l1 = l1 * c1 + s1;
#pragma unroll
        for (int nt = 0; nt < 8; nt++) {
            accO[nt][0] *= c0; accO[nt][1] *= c0;
            accO[nt][2] *= c1; accO[nt][3] *= c1;
        }

        // ---- stage P to smem ----
        {
            int r = (w * 16 + g) * LDQ + 2 * tig;
#pragma unroll
            for (int nt = 0; nt < 8; nt++) {
                *(float2*)&Ps[r + nt * 8] = make_float2(S[nt][0], S[nt][1]);
                *(float2*)&Ps[r + 8 * LDQ + nt * 8] = make_float2(S[nt][2], S[nt][3]);
            }
        }
        __syncthreads();

        // ---- O += P @ V ----
#pragma unroll
        for (int ks = 0; ks < 8; ks++) {
            unsigned ap[4];
            int r = (w * 16 + g) * LDQ + ks * 8 + tig;
            ap[0] = f2tf(Ps[r]);
            ap[1] = f2tf(Ps[r + 8 * LDQ]);
            ap[2] = f2tf(Ps[r + 4]);
            ap[3] = f2tf(Ps[r + 8 * LDQ + 4]);
#pragma unroll
            for (int nt = 0; nt < 8; nt++) {
                unsigned bv0 = f2tf(V_[(ks * 8 + tig) * LDV + nt * 8 + g]);
                unsigned bv1 = f2tf(V_[(ks * 8 + tig + 4) * LDV + nt * 8 + g]);
                mma8(accO[nt], ap, bv0, bv1);
            }
        }
        __syncthreads();
        if (i + 2 < 32) loadKV(i + 2, buf);
        else CP_COMMIT();
    }

    // ---- epilogue: divide by l, write ao ----
    l0 += __shfl_xor_sync(0xffffffffu, l0, 1);
    l0 += __shfl_xor_sync(0xffffffffu, l0, 2);
    l1 += __shfl_xor_sync(0xffffffffu, l1, 1);
    l1 += __shfl_xor_sync(0xffffffffu, l1, 2);
    float inv0 = 1.0f / l0, inv1 = 1.0f / l1;
    long long tok0 = (long long)b * Nn + qt * 128 + w * 16 + g;
#pragma unroll
    for (int nt = 0; nt < 8; nt++) {
        int n = h * 64 + nt * 8 + tig * 2;
        *(float2*)&ao[tok0 * Dd + n] =
            make_float2(accO[nt][0] * inv0, accO[nt][1] * inv0);
        *(float2*)&ao[(tok0 + 8) * Dd + n] =
            make_float2(accO[nt][2] * inv1, accO[nt][3] * inv1);
    }
}

// ---------------- tf32 tensor-core batched GEMM (cp.async 2-stage) -------
struct GemmP {
    const float* A; const float* B; float* C;
    const float* bias; const float* res; const int* gidx;
    int lda, ldb, ldc, ldres;
    long long sA0, sA1, sB0, sB1, sC0, sC1, sBias, sG;
    int zdiv;
    int K;
    float alpha;
    int epi;  // bit0: +bias[n], bit1: gelu, bit2: +res[m,n]
};

template <int BM, int BN, bool TB, bool GATHER>
__global__ __launch_bounds__(256) void tgemm2(GemmP p) {
    constexpr int WM = 64;
    constexpr int WN = 64;
    constexpr int WARPS_M = BM / WM;
    constexpr int MT = WM / 16;
    constexpr int NT = WN / 8;
    constexpr int LDA = 36;
    constexpr int LDBN = BN + 8;
    constexpr int ASZ = BM * LDA;
    constexpr int BSZ = TB ? BN * 36 : 32 * LDBN;
    constexpr int STAGE = ASZ + BSZ;
    constexpr int ACH = BM / 32;
    constexpr int BCH = BN / 32;

    extern __shared__ float sm[];

    int z  = blockIdx.z;
    int zo = z / p.zdiv, zi = z - zo * p.zdiv;
    const float* A = p.A + zo * p.sA0 + zi * p.sA1;
    const float* B = p.B + zo * p.sB0 + zi * p.sB1;
    float*       C = p.C + zo * p.sC0 + zi * p.sC1;

    int m0 = blockIdx.x * BM, n0 = blockIdx.y * BN;
    int t = threadIdx.x;
    int w = t >> 5, lane = t & 31;
    int wm = w % WARPS_M, wn = w / WARPS_M;
    int g = lane >> 2, tig = lane & 3;

    int arowi, ac4;
    if (BM == 128) { arowi = t >> 1; ac4 = (t & 1) * 4; }
    else           { arowi = t;      ac4 = 0; }
    long long arow = m0 + arowi;
    if (GATHER) arow = p.gidx[zo * p.sG + m0 + arowi];
    const float* gA = A + arow * (long long)p.lda;
    int sA0off = arowi * LDA + ac4 * 4;

    int brow, bc4, sB0off;
    const float* gB;
    if (!TB) {
        brow = t >> 3; bc4 = (t & 7) * BCH;
        gB = B + (long long)brow * p.ldb + n0;
        sB0off = brow * LDBN + bc4 * 4;
    } else {
        brow = t >> 1; bc4 = (t & 1) * 4;
        gB = B + (long long)(n0 + brow) * p.ldb;
        sB0off = brow * 36 + bc4 * 4;
    }

    float acc[MT][NT][4];
#pragma unroll
    for (int i = 0; i < MT; i++)
#pragma unroll
        for (int j = 0; j < NT; j++)
#pragma unroll
            for (int q = 0; q < 4; q++) acc[i][j][q] = 0.0f;

    auto load_tile = [&](int ti, int buf) {
        float* As_ = sm + buf * STAGE;
        float* Bs_ = As_ + ASZ;
        int kt = ti * 32;
#pragma unroll
        for (int j = 0; j < ACH; j++)
            cp16(As_ + sA0off + j * 4, gA + kt + ac4 * 4 + j * 4);
        if (!TB) {
#pragma unroll
            for (int j = 0; j < BCH; j++)
                cp16(Bs_ + sB0off + j * 4, gB + (long long)kt * p.ldb + (bc4 + j) * 4);
        } else {
#pragma unroll
            for (int j = 0; j < BCH; j++)
                cp16(Bs_ + sB0off + j * 4, gB + kt + (bc4 + j) * 4);
        }
        CP_COMMIT();
    };

    auto compute = [&](int buf) {
        const float* As_ = sm + buf * STAGE;
        const float* Bs_ = As_ + ASZ;
#pragma unroll
        for (int ks = 0; ks < 4; ks++) {
            unsigned a[MT][4];
            unsigned b[NT][2];
#pragma unroll
            for (int mt = 0; mt < MT; mt++) {
                int base = (wm * WM + mt * 16 + g) * LDA + ks * 8 + tig;
                a[mt][0] = f2tf(As_[base]);
                a[mt][1] = f2tf(As_[base + 8 * LDA]);
                a[mt][2] = f2tf(As_[base + 4]);
                a[mt][3] = f2tf(As_[base + 8 * LDA + 4]);
            }
#pragma unroll
            for (int nt = 0; nt < NT; nt++) {
                if (!TB) {
                    int base = (ks * 8 + tig) * LDBN + wn * WN + nt * 8 + g;
                    b[nt][0] = f2tf(Bs_[base]);
                    b[nt][1] = f2tf(Bs_[base + 4 * LDBN]);
                } else {
                    int base = (wn * WN + nt * 8 + g) * 36 + ks * 8 + tig;
                    b[nt][0] = f2tf(Bs_[base]);
                    b[nt][1] = f2tf(Bs_[base + 4]);
                }
            }
#pragma unroll
            for (int mt = 0; mt < MT; mt++)
#pragma unroll
                for (int nt = 0; nt < NT; nt++)
                    mma8(acc[mt][nt], a[mt], b[nt][0], b[nt][1]);
        }
    };

    int ntiles = p.K >> 5;
    load_tile(0, 0);
    load_tile(1, 1);
    for (int i = 0; i < ntiles; i++) {
        CP_WAIT1();
        __syncthreads();
        compute(i & 1);
        __syncthreads();
        if (i + 2 < ntiles) load_tile(i + 2, i & 1);
        else CP_COMMIT();
    }

    const float* bias = p.bias ? (p.bias + zo * p.sBias) : nullptr;
#pragma unroll
    for (int mt = 0; mt < MT; mt++) {
#pragma unroll
        for (int half = 0; half < 2; half++) {
            int m = m0 + wm * WM + mt * 16 + g + half * 8;
#pragma unroll
            for (int nt = 0; nt < NT; nt++) {
                int n = n0 + wn * WN + nt * 8 + tig * 2;
                float v0 = acc[mt][nt][half * 2 + 0] * p.alpha;
                float v1 = acc[mt][nt][half * 2 + 1] * p.alpha;
                if (p.epi & 1) { v0 += bias[n]; v1 += bias[n + 1]; }
                if (p.epi & 2) { v0 = gelu_f(v0); v1 = gelu_f(v1); }
                if (p.epi & 4) {
                    v0 += p.res[(long long)m * p.ldres + n];
                    v1 += p.res[(long long)m * p.ldres + n + 1];
                }
                *(float2*)&C[(long long)m * p.ldc + n] = make_float2(v0, v1);
            }
        }
    }
}

template <int BM, int BN, bool TB, bool GATHER>
static void launch2(const GemmP& p, int M, int N, int batch) {
    constexpr int ASZ = BM * 36;
    constexpr int BSZ = TB ? BN * 36 : 32 * (BN + 8);
    int smem = 2 * (ASZ + BSZ) * 4;
    cudaFuncSetAttribute(tgemm2<BM, BN, TB, GATHER>,
                         cudaFuncAttributeMaxDynamicSharedMemorySize, smem);
    dim3 grid(M / BM, N / BN, batch);
    tgemm2<BM, BN, TB, GATHER><<<grid, 256, smem>>>(p);
}

// ---------------- layernorm (one block per row, D = 1024) ----------------
__global__ __launch_bounds__(256) void ln_kernel(const float* __restrict__ x,
                                                 const float* __restrict__ g,
                                                 const float* __restrict__ b,
                                                 float* __restrict__ out) {
    int row = blockIdx.x;
    int tid = threadIdx.x;
    const float4* xr = (const float4*)(x + (long long)row * Dd);
    float4 v = xr[tid];
    __shared__ float s[256];

    s[tid] = v.x + v.y + v.z + v.w;
    __syncthreads();
    for (int o = 128; o > 0; o >>= 1) { if (tid < o) s[tid] += s[tid + o]; __syncthreads(); }
    float mu = s[0] * (1.0f / Dd);
    __syncthreads();

    float dx = v.x - mu, dy = v.y - mu, dz = v.z - mu, dw = v.w - mu;
    s[tid] = dx * dx + dy * dy + dz * dz + dw * dw;
    __syncthreads();
    for (int o = 128; o > 0; o >>= 1) { if (tid < o) s[tid] += s[tid + o]; __syncthreads(); }
    float rstd = rsqrtf(s[0] * (1.0f / Dd) + 1e-5f);

    float4 gg = ((const float4*)g)[tid];
    float4 bb = ((const float4*)b)[tid];
    float4 o4;
    o4.x = dx * rstd * gg.x + bb.x;
    o4.y = dy * rstd * gg.y + bb.y;
    o4.z = dz * rstd * gg.z + bb.z;
    o4.w = dw * rstd * gg.w + bb.w;
    ((float4*)(out + (long long)row * Dd))[tid] = o4;
}

// ---------------- router: logits + noisy softplus + top-2 ----------------
__global__ __launch_bounds__(256) void route_kernel(const float* __restrict__ x2,
                                                    const float* __restrict__ wr,
                                                    const float* __restrict__ br,
                                                    const float* __restrict__ wn,
                                                    const float* __restrict__ bn,
                                                    const float* __restrict__ noise,
                                                    int2* __restrict__ topi,
                                                    float2* __restrict__ tw) {
    int t    = blockIdx.x * 8 + (threadIdx.x >> 5);
    int lane = threadIdx.x & 31;
    if (t >= Tn) return;
    const float* xr = x2 + (long long)t * Dd;

    float aR[4] = {0, 0, 0, 0}, aN[4] = {0, 0, 0, 0};
    for (int d = lane; d < Dd; d += 32) {
        float xv = xr[d];
        float4 r = ((const float4*)wr)[d];
        float4 nq = ((const float4*)wn)[d];
        aR[0] += xv * r.x;  aR[1] += xv * r.y;  aR[2] += xv * r.z;  aR[3] += xv * r.w;
        aN[0] += xv * nq.x; aN[1] += xv * nq.y; aN[2] += xv * nq.z; aN[3] += xv * nq.w;
    }
#pragma unroll
    for (int o = 16; o > 0; o >>= 1) {
#pragma unroll
        for (int e = 0; e < 4; e++) {
            aR[e] += __shfl_down_sync(0xffffffffu, aR[e], o);
            aN[e] += __shfl_down_sync(0xffffffffu, aN[e], o);
        }
    }
    if (lane == 0) {
        float nv[4];
#pragma unroll
        for (int e = 0; e < 4; e++) {
            float lg  = aR[e] + br[e];
            float pre = aN[e] + bn[e];
            float sp  = (pre > 20.0f) ? pre : log1pf(expf(pre));
            nv[e] = lg + noise[t * 4 + e] * sp;
        }
        int e0 = 0;
#pragma unroll
        for (int e = 1; e < 4; e++) if (nv[e] > nv[e0]) e0 = e;
        int e1 = -1;
#pragma unroll
        for (int e = 0; e < 4; e++) if (e != e0 && (e1 < 0 || nv[e] > nv[e1])) e1 = e;
        float d  = expf(nv[e1] - nv[e0]);
        float p0 = 1.0f / (1.0f + d);
        topi[t] = make_int2(e0, e1);
        tw[t]   = make_float2(p0, d * p0);
    }
}

// ---------------- capacity scan: stable order per expert ----------------
__global__ __launch_bounds__(1024) void scan_kernel(const int2* __restrict__ topi,
                                                    int* __restrict__ sel,
                                                    int* __restrict__ tslot) {
    int e = blockIdx.x;
    int tid = threadIdx.x;
    __shared__ int s[1024];

    int m[4]; int cnt = 0;
#pragma unroll
    for (int i = 0; i < 4; i++) {
        int t = tid * 4 + i;
        int2 ti = topi[t];
        m[i] = (ti.x == e) ? 1 : ((ti.y == e) ? 2 : 0);
        cnt += (m[i] != 0);
    }
    s[tid] = cnt;
    __syncthreads();
    for (int off = 1; off < 1024; off <<= 1) {
        int v = 0;
        if (tid >= off) v = s[tid - off];
        __syncthreads();
        s[tid] += v;
        __syncthreads();
    }
    int total = s[1023];
    int rank  = s[tid] - cnt;  // exclusive prefix
#pragma unroll
    for (int i = 0; i < 4; i++) {
        if (m[i]) {
            int t = tid * 4 + i;
            int j = m[i] - 1;
            if (rank < CAP) { sel[e * CAP + rank] = t; tslot[t * 2 + j] = rank; }
            else            { tslot[t * 2 + j] = -1; }
            rank++;
        }
    }
    for (int r = total + tid; r < CAP; r += 1024) sel[e * CAP + r] = 0;
}

// ---------------- final combine: out = xres + mlp + gated expert outs ----
__global__ __launch_bounds__(256) void final_kernel(const float* __restrict__ xres,
                                                    const float* __restrict__ mlp,
                                                    const float* __restrict__ moeout,
                                                    const int2* __restrict__ topi,
                                                    const int* __restrict__ tslot,
                                                    const float2* __restrict__ tw,
                                                    float* __restrict__ out) {
    long long idx = (long long)blockIdx.x * blockDim.x + threadIdx.x;
    int t = (int)(idx >> 10);
    int dcol = (int)(idx & 1023);
    float v = xres[idx] + mlp[idx];
    int2 ti = topi[t];
    float2 w = tw[t];
    int s0 = tslot[t * 2], s1 = tslot[t * 2 + 1];
    if (s0 >= 0) v += w.x * moeout[((long long)ti.x * CAP + s0) * Dd + dcol];
    if (s1 >= 0) v += w.y * moeout[((long long)ti.y * CAP + s1) * Dd + dcol];
    out[idx] = v;
}

extern "C" void kernel_launch(void* const* d_in, const int* in_sizes, int n_in,
                              void* d_out, int out_size) {
    const float* x       = (const float*)d_in[0];
    const float* noise   = (const float*)d_in[1];
    const float* ln1_g   = (const float*)d_in[2];
    const float* ln1_b   = (const float*)d_in[3];
    const float* ln2_g   = (const float*)d_in[4];
    const float* ln2_b   = (const float*)d_in[5];
    const float* w_qkv   = (const float*)d_in[6];
    const float* w_proj  = (const float*)d_in[7];
    const float* b_proj  = (const float*)d_in[8];
    const float* w_route = (const float*)d_in[9];
    const float* b_route = (const float*)d_in[10];
    const float* w_noise = (const float*)d_in[11];
    const float* b_noise = (const float*)d_in[12];
    const float* we1     = (const float*)d_in[13];
    const float* be1     = (const float*)d_in[14];
    const float* we2     = (const float*)d_in[15];
    const float* be2     = (const float*)d_in[16];
    const float* w_mlp1  = (const float*)d_in[17];
    const float* b_mlp1  = (const float*)d_in[18];
    const float* w_mlp2  = (const float*)d_in[19];
    const float* b_mlp2  = (const float*)d_in[20];
    float* out = (float*)d_out;

    float*  buf;   cudaGetSymbolAddress((void**)&buf,   g_buf);
    int2*   topi;  cudaGetSymbolAddress((void**)&topi,  g_topi);
    float2* tw;    cudaGetSymbolAddress((void**)&tw,    g_tw);
    int*    tslot; cudaGetSymbolAddress((void**)&tslot, g_tslot);
    int*    sel;   cudaGetSymbolAddress((void**)&sel,   g_sel);

    float* qkv    = buf + OFF_QKV;
    float* hmlp   = buf + OFF_HMLP;
    float* x1     = buf + OFF_X1;
    float* ao     = buf + OFF_AO;
    float* xres   = buf + OFF_XRES;
    float* x2     = buf + OFF_X2;
    float* mlpout = buf + OFF_MLPOUT;
    float* moeout = buf + OFF_MOEOUT;
    float* hmoe   = buf + OFF_HMOE;

    // 1) LN1
    ln_kernel<<<Tn, 256>>>(x, ln1_g, ln1_b, x1);

    // 2) QKV = x1 @ w_qkv^T   (4096 x 3072 x 1024)
    {
        GemmP p{}; p.zdiv = 1; p.alpha = 1.0f; p.K = Dd;
        p.A = x1; p.lda = Dd;
        p.B = w_qkv; p.ldb = Dd;
        p.C = qkv; p.ldc = 3 * Dd;
        launch2<256, 128, true, false>(p, Tn, 3 * Dd, 1);
    }

    // 3) fused flash attention -> ao
    {
        cudaFuncSetAttribute(flash_k, cudaFuncAttributeMaxDynamicSharedMemorySize,
                             FLASH_SMEM);
        dim3 grid(Nn / 128, Bb * Hh);
        flash_k<<<grid, 256, FLASH_SMEM>>>(qkv, ao);
    }

    // 4) xres = x + ao @ w_proj^T + b_proj
    {
        GemmP p{}; p.zdiv = 1; p.alpha = 1.0f; p.K = Dd;
        p.A = ao; p.lda = Dd;
        p.B = w_proj; p.ldb = Dd;
        p.C = xres; p.ldc = Dd;
        p.bias = b_proj; p.res = x; p.ldres = Dd;
        p.epi = 1 | 4;
        launch2<256, 128, true, false>(p, Tn, Dd, 1);
    }

    // 5) LN2
    ln_kernel<<<Tn, 256>>>(xres, ln2_g, ln2_b, x2);

    // 6) routing (noisy top-2)
    route_kernel<<<Tn / 8, 256>>>(x2, w_route, b_route, w_noise, b_noise, noise, topi, tw);

    // 7) per-expert stable capacity scan
    scan_kernel<<<Ee, 1024>>>(topi, sel, tslot);

    // 8) MoE expert GEMM 1 (gathered rows): gelu(Xsel @ we1[e] + be1[e])
    {
        GemmP p{}; p.zdiv = 1; p.alpha = 1.0f; p.K = Dd;
        p.A = x2; p.lda = Dd;
        p.gidx = sel; p.sG = CAP;
        p.B = we1; p.ldb = MOEH; p.sB0 = (long long)Dd * MOEH;
        p.C = hmoe; p.ldc = MOEH; p.sC0 = (long long)CAP * MOEH;
        p.bias = be1; p.sBias = MOEH;
        p.epi = 1 | 2;
        launch2<128, 256, false, true>(p, CAP, MOEH, Ee);
    }

    // 9) MoE expert GEMM 2: h_e @ we2[e] + be2[e]
    {
        GemmP p{}; p.zdiv = 1; p.alpha = 1.0f; p.K = MOEH;
        p.A = hmoe; p.lda = MOEH; p.sA0 = (long long)CAP * MOEH;
        p.B = we2; p.ldb = Dd; p.sB0 = (long long)MOEH * Dd;
        p.C = moeout; p.ldc = Dd; p.sC0 = (long long)CAP * Dd;
        p.bias = be2; p.sBias = Dd;
        p.epi = 1;
        launch2<128, 256, false, false>(p, CAP, Dd, Ee);
    }

    // 10) MLP1: gelu(x2 @ w_mlp1 + b_mlp1)
    {
        GemmP p{}; p.zdiv = 1; p.alpha = 1.0f; p.K = Dd;
        p.A = x2; p.lda = Dd;
        p.B = w_mlp1; p.ldb = MLPH;
        p.C = hmlp; p.ldc = MLPH;
        p.bias = b_mlp1;
        p.epi = 1 | 2;
        launch2<128, 256, false, false>(p, Tn, MLPH, 1);
    }

    // 11) MLP2: hmlp @ w_mlp2 + b_mlp2
    {
        GemmP p{}; p.zdiv = 1; p.alpha = 1.0f; p.K = MLPH;
        p.A = hmlp; p.lda = MLPH;
        p.B = w_mlp2; p.ldb = Dd;
        p.C = mlpout; p.ldc = Dd;
        p.bias = b_mlp2;
        p.epi = 1;
        launch2<128, 256, false, false>(p, Tn, Dd, 1);
    }

    // 12) out = xres + mlp + gated MoE (gather; deterministic, no atomics)
    final_kernel<<<(Tn * Dd) / 256, 256>>>(xres, mlpout, moeout, topi, tslot, tw, out);
}

// round 6
// speedup vs baseline: 2.9738x; 1.1262x over previous
#include <cuda_runtime.h>
#include <math.h>
#include <stdint.h>

// ---------------- problem constants ----------------
#define Tn   4096      // B*N tokens
#define Dd   1024
#define Hh   16
#define HD   64
#define Nn   2048
#define Bb   2
#define Ee   4
#define CAP  2048
#define MLPH 4096
#define MOEH 256

// ---------------- scratch (__device__ globals; no allocations allowed) ----
#define OFF_QKV    0LL
#define OFF_HMLP   12582912LL
#define OFF_X1     29360128LL
#define OFF_AO     33554432LL
#define OFF_XRES   37748736LL
#define OFF_X2     41943040LL
#define OFF_MLPOUT 46137344LL
#define OFF_MOEOUT 50331648LL
#define OFF_HMOE   58720256LL
#define BUF_TOTAL  60817408LL

__device__ float  g_buf[BUF_TOTAL];
__device__ int2   g_topi[Tn];
__device__ float2 g_tw[Tn];
__device__ int    g_tslot[Tn * 2];
__device__ int    g_sel[Ee * CAP];

// ---------------- helpers ----------------
__device__ __forceinline__ float gelu_f(float x) {
    return 0.5f * x * (1.0f + erff(x * 0.7071067811865476f));
}
__device__ __forceinline__ unsigned f2tf(float x) {
    unsigned u;
    asm("cvt.rna.tf32.f32 %0, %1;" : "=r"(u) : "f"(x));
    return u;
}
__device__ __forceinline__ void cp16(float* dst, const float* src) {
    unsigned s = (unsigned)__cvta_generic_to_shared(dst);
    asm volatile("cp.async.cg.shared.global [%0], [%1], 16;" :: "r"(s), "l"(src));
}
#define CP_COMMIT() asm volatile("cp.async.commit_group;")
#define CP_WAIT1()  asm volatile("cp.async.wait_group 1;")
#define CP_WAIT2()  asm volatile("cp.async.wait_group 2;")

__device__ __forceinline__ void mma8(float* c, const unsigned* a, unsigned b0, unsigned b1) {
    asm volatile(
        "mma.sync.aligned.m16n8k8.row.col.f32.tf32.tf32.f32 "
        "{%0,%1,%2,%3}, {%4,%5,%6,%7}, {%8,%9}, {%0,%1,%2,%3};"
        : "+f"(c[0]), "+f"(c[1]), "+f"(c[2]), "+f"(c[3])
        : "r"(a[0]), "r"(a[1]), "r"(a[2]), "r"(a[3]), "r"(b0), "r"(b1));
}

// ---------------- fused flash attention (tf32 mma) ----------------------
// One CTA = one (b,h) and a 128-row Q tile. 8 warps * 16 rows.
// smem: Qs/Ps 128x68 (reused), Ks 2x 64x68, Vs 2x 64x72.
#define LDQ 68
#define LDK 68
#define LDV 72
#define KS_OFF  8704
#define VS_OFF  17408   // 8704 + 2*4352
#define FLASH_SMEM ((8704 + 2*4352 + 2*4608) * 4)

__global__ __launch_bounds__(256, 1) void flash_k(const float* __restrict__ qkv,
                                                  float* __restrict__ ao) {
    extern __shared__ float sm[];
    float* Qs = sm;                       // later reused as Ps
    int qt = blockIdx.x, bh = blockIdx.y;
    int b = bh >> 4, h = bh & 15;
    const float* base = qkv + (long long)b * Nn * 3072 + h * 64;

    int t = threadIdx.x, w = t >> 5, lane = t & 31;
    int g = lane >> 2, tig = lane & 3;

    // ---- Q tile load (group 0) ----
    {
        int row = t >> 1, c0 = (t & 1) * 32;
        const float* gq = base + (long long)(qt * 128 + row) * 3072 + c0;
        float* sq = Qs + row * LDQ + c0;
#pragma unroll
        for (int j = 0; j < 8; j++) cp16(sq + j * 4, gq + j * 4);
    }
    CP_COMMIT();

    // ---- K/V tile loader ----
    int kr = t >> 2, kc = (t & 3) * 16;
    auto loadKV = [&](int ti, int buf) {
        const float* gk = base + 1024 + (long long)(ti * 64 + kr) * 3072 + kc;
        const float* gv = base + 2048 + (long long)(ti * 64 + kr) * 3072 + kc;
        float* sk = sm + KS_OFF + buf * 4352 + kr * LDK + kc;
        float* sv = sm + VS_OFF + buf * 4608 + kr * LDV + kc;
#pragma unroll
        for (int j = 0; j < 4; j++) cp16(sk + j * 4, gk + j * 4);
#pragma unroll
        for (int j = 0; j < 4; j++) cp16(sv + j * 4, gv + j * 4);
        CP_COMMIT();
    };
    loadKV(0, 0);
    loadKV(1, 1);

    // ---- Q fragments to registers (scaled by hd^-0.5 = 1/8) ----
    unsigned aq[8][4];
    CP_WAIT2();
    __syncthreads();
    {
        int r0 = (w * 16 + g) * LDQ;
#pragma unroll
        for (int ks = 0; ks < 8; ks++) {
            int r = r0 + ks * 8 + tig;
            aq[ks][0] = f2tf(0.125f * Qs[r]);
            aq[ks][1] = f2tf(0.125f * Qs[r + 8 * LDQ]);
            aq[ks][2] = f2tf(0.125f * Qs[r + 4]);
            aq[ks][3] = f2tf(0.125f * Qs[r + 8 * LDQ + 4]);
        }
    }
    __syncthreads();   // Qs now reusable as Ps

    float accO[8][4];
#pragma unroll
    for (int nt = 0; nt < 8; nt++)
#pragma unroll
        for (int q = 0; q < 4; q++) accO[nt][q] = 0.0f;
    float m0 = -3.0e38f, m1 = -3.0e38f;
    float l0 = 0.0f, l1 = 0.0f;

    float* Ps = Qs;
    for (int i = 0; i < 32; i++) {
        int buf = i & 1;
        CP_WAIT1();
        __syncthreads();
        const float* K_ = sm + KS_OFF + buf * 4352;
        const float* V_ = sm + VS_OFF + buf * 4608;

        // ---- S = Q @ K^T ----
        float S[8][4];
#pragma unroll
        for (int nt = 0; nt < 8; nt++)
#pragma unroll
            for (int q = 0; q < 4; q++) S[nt][q] = 0.0f;
#pragma unroll
        for (int ks = 0; ks < 8; ks++) {
#pragma unroll
            for (int nt = 0; nt < 8; nt++) {
                int a = (nt * 8 + g) * LDK + ks * 8 + tig;
                mma8(S[nt], aq[ks], f2tf(K_[a]), f2tf(K_[a + 4]));
            }
        }

        // ---- online softmax ----
        float mx0 = S[0][0], mx1 = S[0][2];
#pragma unroll
        for (int nt = 0; nt < 8; nt++) {
            mx0 = fmaxf(mx0, fmaxf(S[nt][0], S[nt][1]));
            mx1 = fmaxf(mx1, fmaxf(S[nt][2], S[nt][3]));
        }
        mx0 = fmaxf(mx0, __shfl_xor_sync(0xffffffffu, mx0, 1));
        mx0 = fmaxf(mx0, __shfl_xor_sync(0xffffffffu, mx0, 2));
        mx1 = fmaxf(mx1, __shfl_xor_sync(0xffffffffu, mx1, 1));
        mx1 = fmaxf(mx1, __shfl_xor_sync(0xffffffffu, mx1, 2));
        float mn0 = fmaxf(m0, mx0), mn1 = fmaxf(m1, mx1);
        float c0 = __expf(m0 - mn0), c1 = __expf(m1 - mn1);
        m0 = mn0; m1 = mn1;
        float s0 = 0.0f, s1 = 0.0f;
#pragma unroll
        for (int nt = 0; nt < 8; nt++) {
            S[nt][0] = __expf(S[nt][0] - mn0);
            S[nt][1] = __expf(S[nt][1] - mn0);
            S[nt][2] = __expf(S[nt][2] - mn1);
            S[nt][3] = __expf(S[nt][3] - mn1);
            s0 += S[nt][0] + S[nt][1];
            s1 += S[nt][2] + S[nt][3];
        }
        l0 = l0 * c0 + s0;
        l1 = l1 * c1 + s1;
#pragma unroll
        for (int nt = 0; nt < 8; nt++) {
            accO[nt][0] *= c0; accO[nt][1] *= c0;
            accO[nt][2] *= c1; accO[nt][3] *= c1;
        }

        // ---- stage P to smem ----
        {
            int r = (w * 16 + g) * LDQ + 2 * tig;
#pragma unroll
            for (int nt = 0; nt < 8; nt++) {
                *(float2*)&Ps[r + nt * 8] = make_float2(S[nt][0], S[nt][1]);
                *(float2*)&Ps[r + 8 * LDQ + nt * 8] = make_float2(S[nt][2], S[nt][3]);
            }
        }
        __syncthreads();

        // ---- O += P @ V ----
#pragma unroll
        for (int ks = 0; ks < 8; ks++) {
            unsigned ap[4];
            int r = (w * 16 + g) * LDQ + ks * 8 + tig;
            ap[0] = f2tf(Ps[r]);
            ap[1] = f2tf(Ps[r + 8 * LDQ]);
            ap[2] = f2tf(Ps[r + 4]);
            ap[3] = f2tf(Ps[r + 8 * LDQ + 4]);
#pragma unroll
            for (int nt = 0; nt < 8; nt++) {
                unsigned bv0 = f2tf(V_[(ks * 8 + tig) * LDV + nt * 8 + g]);
                unsigned bv1 = f2tf(V_[(ks * 8 + tig + 4) * LDV + nt * 8 + g]);
                mma8(accO[nt], ap, bv0, bv1);
            }
        }
        __syncthreads();
        if (i + 2 < 32) loadKV(i + 2, buf);
        else CP_COMMIT();
    }

    // ---- epilogue: divide by l, write ao ----
    l0 += __shfl_xor_sync(0xffffffffu, l0, 1);
    l0 += __shfl_xor_sync(0xffffffffu, l0, 2);
    l1 += __shfl_xor_sync(0xffffffffu, l1, 1);
    l1 += __shfl_xor_sync(0xffffffffu, l1, 2);
    float inv0 = 1.0f / l0, inv1 = 1.0f / l1;
    long long tok0 = (long long)b * Nn + qt * 128 + w * 16 + g;
#pragma unroll
    for (int nt = 0; nt < 8; nt++) {
        int n = h * 64 + nt * 8 + tig * 2;
        *(float2*)&ao[tok0 * Dd + n] =
            make_float2(accO[nt][0] * inv0, accO[nt][1] * inv0);
        *(float2*)&ao[(tok0 + 8) * Dd + n] =
            make_float2(accO[nt][2] * inv1, accO[nt][3] * inv1);
    }
}

// ---------------- tf32 tensor-core batched GEMM (cp.async 2-stage) -------
// 128x128 CTA tile, 8 warps in 2x4 grid (WM=64, WN=32), 2 CTAs/SM target.
struct GemmP {
    const float* A; const float* B; float* C;
    const float* bias; const float* res; const int* gidx;
    int lda, ldb, ldc, ldres;
    long long sA0, sA1, sB0, sB1, sC0, sC1, sBias, sG;
    int zdiv;
    int K;
    float alpha;
    int epi;  // bit0: +bias[n], bit1: gelu, bit2: +res[m,n]
};

template <bool TB, bool GATHER>
__global__ __launch_bounds__(256, 2) void tgemm2(GemmP p) {
    constexpr int BM = 128, BN = 128;
    constexpr int WM = 64, WN = 32;
    constexpr int WARPS_M = BM / WM;   // 2
    constexpr int MT = WM / 16;        // 4
    constexpr int NT = WN / 8;         // 4
    constexpr int LDA = 36;
    constexpr int LDBN = BN + 8;       // 136
    constexpr int ASZ = BM * LDA;                  // 4608
    constexpr int BSZ = TB ? BN * 36 : 32 * LDBN;  // 4608 / 4352
    constexpr int STAGE = ASZ + BSZ;
    constexpr int ACH = 4;             // A float4 chunks per thread
    constexpr int BCH = 4;             // B float4 chunks per thread

    extern __shared__ float sm[];

    int z  = blockIdx.z;
    int zo = z / p.zdiv, zi = z - zo * p.zdiv;
    const float* A = p.A + zo * p.sA0 + zi * p.sA1;
    const float* B = p.B + zo * p.sB0 + zi * p.sB1;
    float*       C = p.C + zo * p.sC0 + zi * p.sC1;

    int m0 = blockIdx.x * BM, n0 = blockIdx.y * BN;
    int t = threadIdx.x;
    int w = t >> 5, lane = t & 31;
    int wm = w % WARPS_M, wn = w / WARPS_M;
    int g = lane >> 2, tig = lane & 3;

    // ---- A loader: 2 threads per row, 16 consecutive floats each ----
    int arowi = t >> 1, ac16 = (t & 1) * 16;
    long long arow = m0 + arowi;
    if (GATHER) arow = p.gidx[zo * p.sG + m0 + arowi];
    const float* gA = A + arow * (long long)p.lda;
    int sA0off = arowi * LDA + ac16;

    // ---- B loader ----
    int brow, bc, sB0off;
    const float* gB;
    if (!TB) {
        brow = t >> 3; bc = (t & 7) * 16;
        gB = B + (long long)brow * p.ldb + n0;
        sB0off = brow * LDBN + bc;
    } else {
        brow = t >> 1; bc = (t & 1) * 16;
        gB = B + (long long)(n0 + brow) * p.ldb;
        sB0off = brow * 36 + bc;
    }

    float acc[MT][NT][4];
#pragma unroll
    for (int i = 0; i < MT; i++)
#pragma unroll
        for (int j = 0; j < NT; j++)
#pragma unroll
            for (int q = 0; q < 4; q++) acc[i][j][q] = 0.0f;

    auto load_tile = [&](int ti, int buf) {
        float* As_ = sm + buf * STAGE;
        float* Bs_ = As_ + ASZ;
        int kt = ti * 32;
#pragma unroll
        for (int j = 0; j < ACH; j++)
            cp16(As_ + sA0off + j * 4, gA + kt + ac16 + j * 4);
        if (!TB) {
#pragma unroll
            for (int j = 0; j < BCH; j++)
                cp16(Bs_ + sB0off + j * 4, gB + (long long)kt * p.ldb + bc + j * 4);
        } else {
#pragma unroll
            for (int j = 0; j < BCH; j++)
                cp16(Bs_ + sB0off + j * 4, gB + kt + bc + j * 4);
        }
        CP_COMMIT();
    };

    auto compute = [&](int buf) {
        const float* As_ = sm + buf * STAGE;
        const float* Bs_ = As_ + ASZ;
#pragma unroll
        for (int ks = 0; ks < 4; ks++) {
            unsigned a[MT][4];
            unsigned b[NT][2];
#pragma unroll
            for (int mt = 0; mt < MT; mt++) {
                int base = (wm * WM + mt * 16 + g) * LDA + ks * 8 + tig;
                a[mt][0] = f2tf(As_[base]);
                a[mt][1] = f2tf(As_[base + 8 * LDA]);
                a[mt][2] = f2tf(As_[base + 4]);
                a[mt][3] = f2tf(As_[base + 8 * LDA + 4]);
            }
#pragma unroll
            for (int nt = 0; nt < NT; nt++) {
                if (!TB) {
                    int base = (ks * 8 + tig) * LDBN + wn * WN + nt * 8 + g;
                    b[nt][0] = f2tf(Bs_[base]);
                    b[nt][1] = f2tf(Bs_[base + 4 * LDBN]);
                } else {
                    int base = (wn * WN + nt * 8 + g) * 36 + ks * 8 + tig;
                    b[nt][0] = f2tf(Bs_[base]);
                    b[nt][1] = f2tf(Bs_[base + 4]);
                }
            }
#pragma unroll
            for (int mt = 0; mt < MT; mt++)
#pragma unroll
                for (int nt = 0; nt < NT; nt++)
                    mma8(acc[mt][nt], a[mt], b[nt][0], b[nt][1]);
        }
    };

    int ntiles = p.K >> 5;
    load_tile(0, 0);
    load_tile(1, 1);
    for (int i = 0; i < ntiles; i++) {
        CP_WAIT1();
        __syncthreads();
        compute(i & 1);
        __syncthreads();
        if (i + 2 < ntiles) load_tile(i + 2, i & 1);
        else CP_COMMIT();
    }

    const float* bias = p.bias ? (p.bias + zo * p.sBias) : nullptr;
#pragma unroll
    for (int mt = 0; mt < MT; mt++) {
#pragma unroll
        for (int half = 0; half < 2; half++) {
            int m = m0 + wm * WM + mt * 16 + g + half * 8;
#pragma unroll
            for (int nt = 0; nt < NT; nt++) {
                int n = n0 + wn * WN + nt * 8 + tig * 2;
                float v0 = acc[mt][nt][half * 2 + 0] * p.alpha;
                float v1 = acc[mt][nt][half * 2 + 1] * p.alpha;
                if (p.epi & 1) { v0 += bias[n]; v1 += bias[n + 1]; }
                if (p.epi & 2) { v0 = gelu_f(v0); v1 = gelu_f(v1); }
                if (p.epi & 4) {
                    v0 += p.res[(long long)m * p.ldres + n];
                    v1 += p.res[(long long)m * p.ldres + n + 1];
                }
                *(float2*)&C[(long long)m * p.ldc + n] = make_float2(v0, v1);
            }
        }
    }
}

template <bool TB, bool GATHER>
static void launch2(const GemmP& p, int M, int N, int batch) {
    constexpr int ASZ = 128 * 36;
    constexpr int BSZ = TB ? 128 * 36 : 32 * 136;
    int smem = 2 * (ASZ + BSZ) * 4;
    cudaFuncSetAttribute(tgemm2<TB, GATHER>,
                         cudaFuncAttributeMaxDynamicSharedMemorySize, smem);
    dim3 grid(M / 128, N / 128, batch);
    tgemm2<TB, GATHER><<<grid, 256, smem>>>(p);
}

// ---------------- layernorm (one block per row, D = 1024) ----------------
__global__ __launch_bounds__(256) void ln_kernel(const float* __restrict__ x,
                                                 const float* __restrict__ g,
                                                 const float* __restrict__ b,
                                                 float* __restrict__ out) {
    int row = blockIdx.x;
    int tid = threadIdx.x;
    const float4* xr = (const float4*)(x + (long long)row * Dd);
    float4 v = xr[tid];
    __shared__ float s[256];

    s[tid] = v.x + v.y + v.z + v.w;
    __syncthreads();
    for (int o = 128; o > 0; o >>= 1) { if (tid < o) s[tid] += s[tid + o]; __syncthreads(); }
    float mu = s[0] * (1.0f / Dd);
    __syncthreads();

    float dx = v.x - mu, dy = v.y - mu, dz = v.z - mu, dw = v.w - mu;
    s[tid] = dx * dx + dy * dy + dz * dz + dw * dw;
    __syncthreads();
    for (int o = 128; o > 0; o >>= 1) { if (tid < o) s[tid] += s[tid + o]; __syncthreads(); }
    float rstd = rsqrtf(s[0] * (1.0f / Dd) + 1e-5f);

    float4 gg = ((const float4*)g)[tid];
    float4 bb = ((const float4*)b)[tid];
    float4 o4;
    o4.x = dx * rstd * gg.x + bb.x;
    o4.y = dy * rstd * gg.y + bb.y;
    o4.z = dz * rstd * gg.z + bb.z;
    o4.w = dw * rstd * gg.w + bb.w;
    ((float4*)(out + (long long)row * Dd))[tid] = o4;
}

// ---------------- router: logits + noisy softplus + top-2 ----------------
__global__ __launch_bounds__(256) void route_kernel(const float* __restrict__ x2,
                                                    const float* __restrict__ wr,
                                                    const float* __restrict__ br,
                                                    const float* __restrict__ wn,
                                                    const float* __restrict__ bn,
                                                    const float* __restrict__ noise,
                                                    int2* __restrict__ topi,
                                                    float2* __restrict__ tw) {
    int t    = blockIdx.x * 8 + (threadIdx.x >> 5);
    int lane = threadIdx.x & 31;
    if (t >= Tn) return;
    const float* xr = x2 + (long long)t * Dd;

    float aR[4] = {0, 0, 0, 0}, aN[4] = {0, 0, 0, 0};
    for (int d = lane; d < Dd; d += 32) {
        float xv = xr[d];
        float4 r = ((const float4*)wr)[d];
        float4 nq = ((const float4*)wn)[d];
        aR[0] += xv * r.x;  aR[1] += xv * r.y;  aR[2] += xv * r.z;  aR[3] += xv * r.w;
        aN[0] += xv * nq.x; aN[1] += xv * nq.y; aN[2] += xv * nq.z; aN[3] += xv * nq.w;
    }
#pragma unroll
    for (int o = 16; o > 0; o >>= 1) {
#pragma unroll
        for (int e = 0; e < 4; e++) {
            aR[e] += __shfl_down_sync(0xffffffffu, aR[e], o);
            aN[e] += __shfl_down_sync(0xffffffffu, aN[e], o);
        }
    }
    if (lane == 0) {
        float nv[4];
#pragma unroll
        for (int e = 0; e < 4; e++) {
            float lg  = aR[e] + br[e];
            float pre = aN[e] + bn[e];
            float sp  = (pre > 20.0f) ? pre : log1pf(expf(pre));
            nv[e] = lg + noise[t * 4 + e] * sp;
        }
        int e0 = 0;
#pragma unroll
        for (int e = 1; e < 4; e++) if (nv[e] > nv[e0]) e0 = e;
        int e1 = -1;
#pragma unroll
        for (int e = 0; e < 4; e++) if (e != e0 && (e1 < 0 || nv[e] > nv[e1])) e1 = e;
        float d  = expf(nv[e1] - nv[e0]);
        float p0 = 1.0f / (1.0f + d);
        topi[t] = make_int2(e0, e1);
        tw[t]   = make_float2(p0, d * p0);
    }
}

// ---------------- capacity scan: stable order per expert ----------------
__global__ __launch_bounds__(1024) void scan_kernel(const int2* __restrict__ topi,
                                                    int* __restrict__ sel,
                                                    int* __restrict__ tslot) {
    int e = blockIdx.x;
    int tid = threadIdx.x;
    __shared__ int s[1024];

    int m[4]; int cnt = 0;
#pragma unroll
    for (int i = 0; i < 4; i++) {
        int t = tid * 4 + i;
        int2 ti = topi[t];
        m[i] = (ti.x == e) ? 1 : ((ti.y == e) ? 2 : 0);
        cnt += (m[i] != 0);
    }
    s[tid] = cnt;
    __syncthreads();
    for (int off = 1; off < 1024; off <<= 1) {
        int v = 0;
        if (tid >= off) v = s[tid - off];
        __syncthreads();
        s[tid] += v;
        __syncthreads();
    }
    int total = s[1023];
    int rank  = s[tid] - cnt;  // exclusive prefix
#pragma unroll
    for (int i = 0; i < 4; i++) {
        if (m[i]) {
            int t = tid * 4 + i;
            int j = m[i] - 1;
            if (rank < CAP) { sel[e * CAP + rank] = t; tslot[t * 2 + j] = rank; }
            else            { tslot[t * 2 + j] = -1; }
            rank++;
        }
    }
    for (int r = total + tid; r < CAP; r += 1024) sel[e * CAP + r] = 0;
}

// ---------------- final combine: out = xres + mlp + gated expert outs ----
__global__ __launch_bounds__(256) void final_kernel(const float* __restrict__ xres,
                                                    const float* __restrict__ mlp,
                                                    const float* __restrict__ moeout,
                                                    const int2* __restrict__ topi,
                                                    const int* __restrict__ tslot,
                                                    const float2* __restrict__ tw,
                                                    float* __restrict__ out) {
    long long idx = (long long)blockIdx.x * blockDim.x + threadIdx.x;
    int t = (int)(idx >> 10);
    int dcol = (int)(idx & 1023);
    float v = xres[idx] + mlp[idx];
    int2 ti = topi[t];
    float2 w = tw[t];
    int s0 = tslot[t * 2], s1 = tslot[t * 2 + 1];
    if (s0 >= 0) v += w.x * moeout[((long long)ti.x * CAP + s0) * Dd + dcol];
    if (s1 >= 0) v += w.y * moeout[((long long)ti.y * CAP + s1) * Dd + dcol];
    out[idx] = v;
}

extern "C" void kernel_launch(void* const* d_in, const int* in_sizes, int n_in,
                              void* d_out, int out_size) {
    const float* x       = (const float*)d_in[0];
    const float* noise   = (const float*)d_in[1];
    const float* ln1_g   = (const float*)d_in[2];
    const float* ln1_b   = (const float*)d_in[3];
    const float* ln2_g   = (const float*)d_in[4];
    const float* ln2_b   = (const float*)d_in[5];
    const float* w_qkv   = (const float*)d_in[6];
    const float* w_proj  = (const float*)d_in[7];
    const float* b_proj  = (const float*)d_in[8];
    const float* w_route = (const float*)d_in[9];
    const float* b_route = (const float*)d_in[10];
    const float* w_noise = (const float*)d_in[11];
    const float* b_noise = (const float*)d_in[12];
    const float* we1     = (const float*)d_in[13];
    const float* be1     = (const float*)d_in[14];
    const float* we2     = (const float*)d_in[15];
    const float* be2     = (const float*)d_in[16];
    const float* w_mlp1  = (const float*)d_in[17];
    const float* b_mlp1  = (const float*)d_in[18];
    const float* w_mlp2  = (const float*)d_in[19];
    const float* b_mlp2  = (const float*)d_in[20];
    float* out = (float*)d_out;

    float*  buf;   cudaGetSymbolAddress((void**)&buf,   g_buf);
    int2*   topi;  cudaGetSymbolAddress((void**)&topi,  g_topi);
    float2* tw;    cudaGetSymbolAddress((void**)&tw,    g_tw);
    int*    tslot; cudaGetSymbolAddress((void**)&tslot, g_tslot);
    int*    sel;   cudaGetSymbolAddress((void**)&sel,   g_sel);

    float* qkv    = buf + OFF_QKV;
    float* hmlp   = buf + OFF_HMLP;
    float* x1     = buf + OFF_X1;
    float* ao     = buf + OFF_AO;
    float* xres   = buf + OFF_XRES;
    float* x2     = buf + OFF_X2;
    float* mlpout = buf + OFF_MLPOUT;
    float* moeout = buf + OFF_MOEOUT;
    float* hmoe   = buf + OFF_HMOE;

    // 1) LN1
    ln_kernel<<<Tn, 256>>>(x, ln1_g, ln1_b, x1);

    // 2) QKV = x1 @ w_qkv^T   (4096 x 3072 x 1024)
    {
        GemmP p{}; p.zdiv = 1; p.alpha = 1.0f; p.K = Dd;
        p.A = x1; p.lda = Dd;
        p.B = w_qkv; p.ldb = Dd;
        p.C = qkv; p.ldc = 3 * Dd;
        launch2<true, false>(p, Tn, 3 * Dd, 1);
    }

    // 3) fused flash attention -> ao
    {
        cudaFuncSetAttribute(flash_k, cudaFuncAttributeMaxDynamicSharedMemorySize,
                             FLASH_SMEM);
        dim3 grid(Nn / 128, Bb * Hh);
        flash_k<<<grid, 256, FLASH_SMEM>>>(qkv, ao);
    }

    // 4) xres = x + ao @ w_proj^T + b_proj
    {
        GemmP p{}; p.zdiv = 1; p.alpha = 1.0f; p.K = Dd;
        p.A = ao; p.lda = Dd;
        p.B = w_proj; p.ldb = Dd;
        p.C = xres; p.ldc = Dd;
        p.bias = b_proj; p.res = x; p.ldres = Dd;
        p.epi = 1 | 4;
        launch2<true, false>(p, Tn, Dd, 1);
    }

    // 5) LN2
    ln_kernel<<<Tn, 256>>>(xres, ln2_g, ln2_b, x2);

    // 6) routing (noisy top-2)
    route_kernel<<<Tn / 8, 256>>>(x2, w_route, b_route, w_noise, b_noise, noise, topi, tw);

    // 7) per-expert stable capacity scan
    scan_kernel<<<Ee, 1024>>>(topi, sel, tslot);

    // 8) MoE expert GEMM 1 (gathered rows): gelu(Xsel @ we1[e] + be1[e])
    {
        GemmP p{}; p.zdiv = 1; p.alpha = 1.0f; p.K = Dd;
        p.A = x2; p.lda = Dd;
        p.gidx = sel; p.sG = CAP;
        p.B = we1; p.ldb = MOEH; p.sB0 = (long long)Dd * MOEH;
        p.C = hmoe; p.ldc = MOEH; p.sC0 = (long long)CAP * MOEH;
        p.bias = be1; p.sBias = MOEH;
        p.epi = 1 | 2;
        launch2<false, true>(p, CAP, MOEH, Ee);
    }

    // 9) MoE expert GEMM 2: h_e @ we2[e] + be2[e]
    {
        GemmP p{}; p.zdiv = 1; p.alpha = 1.0f; p.K = MOEH;
        p.A = hmoe; p.lda = MOEH; p.sA0 = (long long)CAP * MOEH;
        p.B = we2; p.ldb = Dd; p.sB0 = (long long)MOEH * Dd;
        p.C = moeout; p.ldc = Dd; p.sC0 = (long long)CAP * Dd;
        p.bias = be2; p.sBias = Dd;
        p.epi = 1;
        launch2<false, false>(p, CAP, Dd, Ee);
    }

    // 10) MLP1: gelu(x2 @ w_mlp1 + b_mlp1)
    {
        GemmP p{}; p.zdiv = 1; p.alpha = 1.0f; p.K = Dd;
        p.A = x2; p.lda = Dd;
        p.B = w_mlp1; p.ldb = MLPH;
        p.C = hmlp; p.ldc = MLPH;
        p.bias = b_mlp1;
        p.epi = 1 | 2;
        launch2<false, false>(p, Tn, MLPH, 1);
    }

    // 11) MLP2: hmlp @ w_mlp2 + b_mlp2
    {
        GemmP p{}; p.zdiv = 1; p.alpha = 1.0f; p.K = MLPH;
        p.A = hmlp; p.lda = MLPH;
        p.B = w_mlp2; p.ldb = Dd;
        p.C = mlpout; p.ldc = Dd;
        p.bias = b_mlp2;
        p.epi = 1;
        launch2<false, false>(p, Tn, Dd, 1);
    }

    // 12) out = xres + mlp + gated MoE (gather; deterministic, no atomics)
    final_kernel<<<(Tn * Dd) / 256, 256>>>(xres, mlpout, moeout, topi, tslot, tw, out);
}

// round 8
// speedup vs baseline: 3.1463x; 1.0580x over previous
#include <cuda_runtime.h>
#include <math.h>
#include <stdint.h>

// ---------------- problem constants ----------------
#define Tn   4096      // B*N tokens
#define Dd   1024
#define Hh   16
#define HD   64
#define Nn   2048
#define Bb   2
#define Ee   4
#define CAP  2048
#define MLPH 4096
#define MOEH 256

// ---------------- scratch (__device__ globals; no allocations allowed) ----
#define OFF_QKV    0LL
#define OFF_HMLP   12582912LL
#define OFF_X1     29360128LL
#define OFF_AO     33554432LL
#define OFF_XRES   37748736LL
#define OFF_X2     41943040LL
#define OFF_MLPOUT 46137344LL
#define OFF_MOEOUT 50331648LL
#define OFF_HMOE   58720256LL
#define BUF_TOTAL  60817408LL

__device__ float  g_buf[BUF_TOTAL];
__device__ int2   g_topi[Tn];
__device__ float2 g_tw[Tn];
__device__ int    g_tslot[Tn * 2];
__device__ int    g_sel[Ee * CAP];

// ---------------- helpers ----------------
__device__ __forceinline__ float gelu_f(float x) {
    return 0.5f * x * (1.0f + erff(x * 0.7071067811865476f));
}
// raw fp32 bits into tf32 mma operand (HW truncates mantissa; no ALU cvt)
__device__ __forceinline__ unsigned rawtf(float x) { return __float_as_uint(x); }

__device__ __forceinline__ void cp16(float* dst, const float* src) {
    unsigned s = (unsigned)__cvta_generic_to_shared(dst);
    asm volatile("cp.async.cg.shared.global [%0], [%1], 16;" :: "r"(s), "l"(src));
}
#define CP_COMMIT() asm volatile("cp.async.commit_group;")
#define CP_WAIT1()  asm volatile("cp.async.wait_group 1;")
#define CP_WAIT2()  asm volatile("cp.async.wait_group 2;")

__device__ __forceinline__ void mma8(float* c, const unsigned* a, unsigned b0, unsigned b1) {
    asm volatile(
        "mma.sync.aligned.m16n8k8.row.col.f32.tf32.tf32.f32 "
        "{%0,%1,%2,%3}, {%4,%5,%6,%7}, {%8,%9}, {%0,%1,%2,%3};"
        : "+f"(c[0]), "+f"(c[1]), "+f"(c[2]), "+f"(c[3])
        : "r"(a[0]), "r"(a[1]), "r"(a[2]), "r"(a[3]), "r"(b0), "r"(b1));
}

// ---------------- fused flash attention (tf32 mma) ----------------------
// One CTA = one (b,h) and a 128-row Q tile. 8 warps * 16 rows.
// smem: Qs/Ps 128x68 (reused), Ks 2x 64x68, Vs 2x 64x72.
#define LDQ 68
#define LDK 68
#define LDV 72
#define KS_OFF  8704
#define VS_OFF  17408   // 8704 + 2*4352
#define FLASH_SMEM ((8704 + 2*4352 + 2*4608) * 4)

__global__ __launch_bounds__(256, 1) void flash_k(const float* __restrict__ qkv,
                                                  float* __restrict__ ao) {
    extern __shared__ float sm[];
    float* Qs = sm;                       // later reused as Ps
    int qt = blockIdx.x, bh = blockIdx.y;
    int b = bh >> 4, h = bh & 15;
    const float* base = qkv + (long long)b * Nn * 3072 + h * 64;

    int t = threadIdx.x, w = t >> 5, lane = t & 31;
    int g = lane >> 2, tig = lane & 3;

    // ---- Q tile load (group 0) ----
    {
        int row = t >> 1, c0 = (t & 1) * 32;
        const float* gq = base + (long long)(qt * 128 + row) * 3072 + c0;
        float* sq = Qs + row * LDQ + c0;
#pragma unroll
        for (int j = 0; j < 8; j++) cp16(sq + j * 4, gq + j * 4);
    }
    CP_COMMIT();

    // ---- K/V tile loader ----
    int kr = t >> 2, kc = (t & 3) * 16;
    auto loadKV = [&](int ti, int buf) {
        const float* gk = base + 1024 + (long long)(ti * 64 + kr) * 3072 + kc;
        const float* gv = base + 2048 + (long long)(ti * 64 + kr) * 3072 + kc;
        float* sk = sm + KS_OFF + buf * 4352 + kr * LDK + kc;
        float* sv = sm + VS_OFF + buf * 4608 + kr * LDV + kc;
#pragma unroll
        for (int j = 0; j < 4; j++) cp16(sk + j * 4, gk + j * 4);
#pragma unroll
        for (int j = 0; j < 4; j++) cp16(sv + j * 4, gv + j * 4);
        CP_COMMIT();
    };
    loadKV(0, 0);
    loadKV(1, 1);

    // ---- Q fragments to registers (scaled by hd^-0.5 = 1/8) ----
    unsigned aq[8][4];
    CP_WAIT2();
    __syncthreads();
    {
        int r0 = (w * 16 + g) * LDQ;
#pragma unroll
        for (int ks = 0; ks < 8; ks++) {
            int r = r0 + ks * 8 + tig;
            aq[ks][0] = rawtf(0.125f * Qs[r]);
            aq[ks][1] = rawtf(0.125f * Qs[r + 8 * LDQ]);
            aq[ks][2] = rawtf(0.125f * Qs[r + 4]);
            aq[ks][3] = rawtf(0.125f * Qs[r + 8 * LDQ + 4]);
        }
    }
    __syncthreads();   // Qs now reusable as Ps

    float accO[8][4];
#pragma unroll
    for (int nt = 0; nt < 8; nt++)
#pragma unroll
        for (int q = 0; q < 4; q++) accO[nt][q] = 0.0f;
    float m0 = -3.0e38f, m1 = -3.0e38f;
    float l0 = 0.0f, l1 = 0.0f;

    float* Ps = Qs;
    for (int i = 0; i < 32; i++) {
        int buf = i & 1;
        CP_WAIT1();
        __syncthreads();
        const float* K_ = sm + KS_OFF + buf * 4352;
        const float* V_ = sm + VS_OFF + buf * 4608;

        // ---- S = Q @ K^T ----
        float S[8][4];
#pragma unroll
        for (int nt = 0; nt < 8; nt++)
#pragma unroll
            for (int q = 0; q < 4; q++) S[nt][q] = 0.0f;
#pragma unroll
        for (int ks = 0; ks < 8; ks++) {
#pragma unroll
            for (int nt = 0; nt < 8; nt++) {
                int a = (nt * 8 + g) * LDK + ks * 8 + tig;
                mma8(S[nt], aq[ks], rawtf(K_[a]), rawtf(K_[a + 4]));
            }
        }

        // ---- online softmax ----
        float mx0 = S[0][0], mx1 = S[0][2];
#pragma unroll
        for (int nt = 0; nt < 8; nt++) {
            mx0 = fmaxf(mx0, fmaxf(S[nt][0], S[nt][1]));
            mx1 = fmaxf(mx1, fmaxf(S[nt][2], S[nt][3]));
        }
        mx0 = fmaxf(mx0, __shfl_xor_sync(0xffffffffu, mx0, 1));
        mx0 = fmaxf(mx0, __shfl_xor_sync(0xffffffffu, mx0, 2));
        mx1 = fmaxf(mx1, __shfl_xor_sync(0xffffffffu, mx1, 1));
        mx1 = fmaxf(mx1, __shfl_xor_sync(0xffffffffu, mx1, 2));
        float mn0 = fmaxf(m0, mx0), mn1 = fmaxf(m1, mx1);
        float c0 = __expf(m0 - mn0), c1 = __expf(m1 - mn1);
        m0 = mn0; m1 = mn1;
        float s0 = 0.0f, s1 = 0.0f;
#pragma unroll
        for (int nt = 0; nt < 8; nt++) {
            S[nt][0] = __expf(S[nt][0] - mn0);
            S[nt][1] = __expf(S[nt][1] - mn0);
            S[nt][2] = __expf(S[nt][2] - mn1);
            S[nt][3] = __expf(S[nt][3] - mn1);
            s0 += S[nt][0] + S[nt][1];
            s1 += S[nt][2] + S[nt][3];
        }
        l0 = l0 * c0 + s0;
        l1 = l1 * c1 + s1;
#pragma unroll
        for (int nt = 0; nt < 8; nt++) {
            accO[nt][0] *= c0; accO[nt][1] *= c0;
            accO[nt][2] *= c1; accO[nt][3] *= c1;
        }

        // ---- stage P to smem ----
        {
            int r = (w * 16 + g) * LDQ + 2 * tig;
#pragma unroll
            for (int nt = 0; nt < 8; nt++) {
                *(float2*)&Ps[r + nt * 8] = make_float2(S[nt][0], S[nt][1]);
                *(float2*)&Ps[r + 8 * LDQ + nt * 8] = make_float2(S[nt][2], S[nt][3]);
            }
        }
        __syncthreads();

        // ---- O += P @ V ----
#pragma unroll
        for (int ks = 0; ks < 8; ks++) {
            unsigned ap[4];
            int r = (w * 16 + g) * LDQ + ks * 8 + tig;
            ap[0] = rawtf(Ps[r]);
            ap[1] = rawtf(Ps[r + 8 * LDQ]);
            ap[2] = rawtf(Ps[r + 4]);
            ap[3] = rawtf(Ps[r + 8 * LDQ + 4]);
#pragma unroll
            for (int nt = 0; nt < 8; nt++) {
                unsigned bv0 = rawtf(V_[(ks * 8 + tig) * LDV + nt * 8 + g]);
                unsigned bv1 = rawtf(V_[(ks * 8 + tig + 4) * LDV + nt * 8 + g]);
                mma8(accO[nt], ap, bv0, bv1);
            }
        }
        __syncthreads();
        if (i + 2 < 32) loadKV(i + 2, buf);
        else CP_COMMIT();
    }

    // ---- epilogue: divide by l, write ao ----
    l0 += __shfl_xor_sync(0xffffffffu, l0, 1);
    l0 += __shfl_xor_sync(0xffffffffu, l0, 2);
    l1 += __shfl_xor_sync(0xffffffffu, l1, 1);
    l1 += __shfl_xor_sync(0xffffffffu, l1, 2);
    float inv0 = 1.0f / l0, inv1 = 1.0f / l1;
    long long tok0 = (long long)b * Nn + qt * 128 + w * 16 + g;
#pragma unroll
    for (int nt = 0; nt < 8; nt++) {
        int n = h * 64 + nt * 8 + tig * 2;
        *(float2*)&ao[tok0 * Dd + n] =
            make_float2(accO[nt][0] * inv0, accO[nt][1] * inv0);
        *(float2*)&ao[(tok0 + 8) * Dd + n] =
            make_float2(accO[nt][2] * inv1, accO[nt][3] * inv1);
    }
}

// ---------------- tf32 tensor-core batched GEMM (cp.async 2-stage) -------
// 128x128 CTA tile, 8 warps in 2x4 grid (WM=64, WN=32), 2 CTAs/SM.
struct GemmP {
    const float* A; const float* B; float* C;
    const float* bias; const float* res; const int* gidx;
    int lda, ldb, ldc, ldres;
    long long sA0, sA1, sB0, sB1, sC0, sC1, sBias, sG;
    int zdiv;
    int K;
    float alpha;
    int epi;  // bit0: +bias[n], bit1: gelu, bit2: +res[m,n]
};

template <bool TB, bool GATHER>
__global__ __launch_bounds__(256, 2) void tgemm2(GemmP p) {
    constexpr int BM = 128, BN = 128;
    constexpr int WM = 64, WN = 32;
    constexpr int WARPS_M = BM / WM;   // 2
    constexpr int MT = WM / 16;        // 4
    constexpr int NT = WN / 8;         // 4
    constexpr int LDA = 36;
    constexpr int LDBN = BN + 8;       // 136
    constexpr int ASZ = BM * LDA;                  // 4608
    constexpr int BSZ = TB ? BN * 36 : 32 * LDBN;  // 4608 / 4352
    constexpr int STAGE = ASZ + BSZ;
    constexpr int ACH = 4;
    constexpr int BCH = 4;

    extern __shared__ float sm[];

    int z  = blockIdx.z;
    int zo = z / p.zdiv, zi = z - zo * p.zdiv;
    const float* A = p.A + zo * p.sA0 + zi * p.sA1;
    const float* B = p.B + zo * p.sB0 + zi * p.sB1;
    float*       C = p.C + zo * p.sC0 + zi * p.sC1;

    int m0 = blockIdx.x * BM, n0 = blockIdx.y * BN;
    int t = threadIdx.x;
    int w = t >> 5, lane = t & 31;
    int wm = w % WARPS_M, wn = w / WARPS_M;
    int g = lane >> 2, tig = lane & 3;

    // ---- A loader: 2 threads per row, 16 consecutive floats each ----
    int arowi = t >> 1, ac16 = (t & 1) * 16;
    long long arow = m0 + arowi;
    if (GATHER) arow = p.gidx[zo * p.sG + m0 + arowi];
    const float* gA = A + arow * (long long)p.lda;
    int sA0off = arowi * LDA + ac16;

    // ---- B loader ----
    int brow, bc, sB0off;
    const float* gB;
    if (!TB) {
        brow = t >> 3; bc = (t & 7) * 16;
        gB = B + (long long)brow * p.ldb + n0;
        sB0off = brow * LDBN + bc;
    } else {
        brow = t >> 1; bc = (t & 1) * 16;
        gB = B + (long long)(n0 + brow) * p.ldb;
        sB0off = brow * 36 + bc;
    }

    float acc[MT][NT][4];
#pragma unroll
    for (int i = 0; i < MT; i++)
#pragma unroll
        for (int j = 0; j < NT; j++)
#pragma unroll
            for (int q = 0; q < 4; q++) acc[i][j][q] = 0.0f;

    auto load_tile = [&](int ti, int buf) {
        float* As_ = sm + buf * STAGE;
        float* Bs_ = As_ + ASZ;
        int kt = ti * 32;
#pragma unroll
        for (int j = 0; j < ACH; j++)
            cp16(As_ + sA0off + j * 4, gA + kt + ac16 + j * 4);
        if (!TB) {
#pragma unroll
            for (int j = 0; j < BCH; j++)
                cp16(Bs_ + sB0off + j * 4, gB + (long long)kt * p.ldb + bc + j * 4);
        } else {
#pragma unroll
            for (int j = 0; j < BCH; j++)
                cp16(Bs_ + sB0off + j * 4, gB + kt + bc + j * 4);
        }
        CP_COMMIT();
    };

    auto compute = [&](int buf) {
        const float* As_ = sm + buf * STAGE;
        const float* Bs_ = As_ + ASZ;
#pragma unroll
        for (int ks = 0; ks < 4; ks++) {
            unsigned a[MT][4];
            unsigned b[NT][2];
#pragma unroll
            for (int mt = 0; mt < MT; mt++) {
                int base = (wm * WM + mt * 16 + g) * LDA + ks * 8 + tig;
                a[mt][0] = rawtf(As_[base]);
                a[mt][1] = rawtf(As_[base + 8 * LDA]);
                a[mt][2] = rawtf(As_[base + 4]);
                a[mt][3] = rawtf(As_[base + 8 * LDA + 4]);
            }
#pragma unroll
            for (int nt = 0; nt < NT; nt++) {
                if (!TB) {
                    int base = (ks * 8 + tig) * LDBN + wn * WN + nt * 8 + g;
                    b[nt][0] = rawtf(Bs_[base]);
                    b[nt][1] = rawtf(Bs_[base + 4 * LDBN]);
                } else {
                    int base = (wn * WN + nt * 8 + g) * 36 + ks * 8 + tig;
                    b[nt][0] = rawtf(Bs_[base]);
                    b[nt][1] = rawtf(Bs_[base + 4]);
                }
            }
#pragma unroll
            for (int mt = 0; mt < MT; mt++)
#pragma unroll
                for (int nt = 0; nt < NT; nt++)
                    mma8(acc[mt][nt], a[mt], b[nt][0], b[nt][1]);
        }
    };

    int ntiles = p.K >> 5;
    load_tile(0, 0);
    load_tile(1, 1);
    for (int i = 0; i < ntiles; i++) {
        CP_WAIT1();
        __syncthreads();
        compute(i & 1);
        __syncthreads();
        if (i + 2 < ntiles) load_tile(i + 2, i & 1);
        else CP_COMMIT();
    }

    const float* bias = p.bias ? (p.bias + zo * p.sBias) : nullptr;
#pragma unroll
    for (int mt = 0; mt < MT; mt++) {
#pragma unroll
        for (int half = 0; half < 2; half++) {
            int m = m0 + wm * WM + mt * 16 + g + half * 8;
#pragma unroll
            for (int nt = 0; nt < NT; nt++) {
                int n = n0 + wn * WN + nt * 8 + tig * 2;
                float v0 = acc[mt][nt][half * 2 + 0] * p.alpha;
                float v1 = acc[mt][nt][half * 2 + 1] * p.alpha;
                if (p.epi & 1) { v0 += bias[n]; v1 += bias[n + 1]; }
                if (p.epi & 2) { v0 = gelu_f(v0); v1 = gelu_f(v1); }
                if (p.epi & 4) {
                    v0 += p.res[(long long)m * p.ldres + n];
                    v1 += p.res[(long long)m * p.ldres + n + 1];
                }
                *(float2*)&C[(long long)m * p.ldc + n] = make_float2(v0, v1);
            }
        }
    }
}

template <bool TB, bool GATHER>
static void launch2(const GemmP& p, int M, int N, int batch) {
    constexpr int ASZ = 128 * 36;
    constexpr int BSZ = TB ? 128 * 36 : 32 * 136;
    int smem = 2 * (ASZ + BSZ) * 4;
    cudaFuncSetAttribute(tgemm2<TB, GATHER>,
                         cudaFuncAttributeMaxDynamicSharedMemorySize, smem);
    dim3 grid(M / 128, N / 128, batch);
    tgemm2<TB, GATHER><<<grid, 256, smem>>>(p);
}

// ---------------- layernorm (one block per row, D = 1024) ----------------
__global__ __launch_bounds__(256) void ln_kernel(const float* __restrict__ x,
                                                 const float* __restrict__ g,
                                                 const float* __restrict__ b,
                                                 float* __restrict__ out) {
    int row = blockIdx.x;
    int tid = threadIdx.x;
    const float4* xr = (const float4*)(x + (long long)row * Dd);
    float4 v = xr[tid];
    __shared__ float s[256];

    s[tid] = v.x + v.y + v.z + v.w;
    __syncthreads();
    for (int o = 128; o > 0; o >>= 1) { if (tid < o) s[tid] += s[tid + o]; __syncthreads(); }
    float mu = s[0] * (1.0f / Dd);
    __syncthreads();

    float dx = v.x - mu, dy = v.y - mu, dz = v.z - mu, dw = v.w - mu;
    s[tid] = dx * dx + dy * dy + dz * dz + dw * dw;
    __syncthreads();
    for (int o = 128; o > 0; o >>= 1) { if (tid < o) s[tid] += s[tid + o]; __syncthreads(); }
    float rstd = rsqrtf(s[0] * (1.0f / Dd) + 1e-5f);

    float4 gg = ((const float4*)g)[tid];
    float4 bb = ((const float4*)b)[tid];
    float4 o4;
    o4.x = dx * rstd * gg.x + bb.x;
    o4.y = dy * rstd * gg.y + bb.y;
    o4.z = dz * rstd * gg.z + bb.z;
    o4.w = dw * rstd * gg.w + bb.w;
    ((float4*)(out + (long long)row * Dd))[tid] = o4;
}

// ---------------- router: logits + noisy softplus + top-2 ----------------
__global__ __launch_bounds__(256) void route_kernel(const float* __restrict__ x2,
                                                    const float* __restrict__ wr,
                                                    const float* __restrict__ br,
                                                    const float* __restrict__ wn,
                                                    const float* __restrict__ bn,
                                                    const float* __restrict__ noise,
                                                    int2* __restrict__ topi,
                                                    float2* __restrict__ tw) {
    int t    = blockIdx.x * 8 + (threadIdx.x >> 5);
    int lane = threadIdx.x & 31;
    if (t >= Tn) return;
    const float* xr = x2 + (long long)t * Dd;

    float aR[4] = {0, 0, 0, 0}, aN[4] = {0, 0, 0, 0};
    for (int d = lane; d < Dd; d += 32) {
        float xv = xr[d];
        float4 r = ((const float4*)wr)[d];
        float4 nq = ((const float4*)wn)[d];
        aR[0] += xv * r.x;  aR[1] += xv * r.y;  aR[2] += xv * r.z;  aR[3] += xv * r.w;
        aN[0] += xv * nq.x; aN[1] += xv * nq.y; aN[2] += xv * nq.z; aN[3] += xv * nq.w;
    }
#pragma unroll
    for (int o = 16; o > 0; o >>= 1) {
#pragma unroll
        for (int e = 0; e < 4; e++) {
            aR[e] += __shfl_down_sync(0xffffffffu, aR[e], o);
            aN[e] += __shfl_down_sync(0xffffffffu, aN[e], o);
        }
    }
    if (lane == 0) {
        float nv[4];
#pragma unroll
        for (int e = 0; e < 4; e++) {
            float lg  = aR[e] + br[e];
            float pre = aN[e] + bn[e];
            float sp  = (pre > 20.0f) ? pre : log1pf(expf(pre));
            nv[e] = lg + noise[t * 4 + e] * sp;
        }
        int e0 = 0;
#pragma unroll
        for (int e = 1; e < 4; e++) if (nv[e] > nv[e0]) e0 = e;
        int e1 = -1;
#pragma unroll
        for (int e = 0; e < 4; e++) if (e != e0 && (e1 < 0 || nv[e] > nv[e1])) e1 = e;
        float d  = expf(nv[e1] - nv[e0]);
        float p0 = 1.0f / (1.0f + d);
        topi[t] = make_int2(e0, e1);
        tw[t]   = make_float2(p0, d * p0);
    }
}

// ---------------- capacity scan: stable order per expert ----------------
__global__ __launch_bounds__(1024) void scan_kernel(const int2* __restrict__ topi,
                                                    int* __restrict__ sel,
                                                    int* __restrict__ tslot) {
    int e = blockIdx.x;
    int tid = threadIdx.x;
    __shared__ int s[1024];

    int m[4]; int cnt = 0;
#pragma unroll
    for (int i = 0; i < 4; i++) {
        int t = tid * 4 + i;
        int2 ti = topi[t];
        m[i] = (ti.x == e) ? 1 : ((ti.y == e) ? 2 : 0);
        cnt += (m[i] != 0);
    }
    s[tid] = cnt;
    __syncthreads();
    for (int off = 1; off < 1024; off <<= 1) {
        int v = 0;
        if (tid >= off) v = s[tid - off];
        __syncthreads();
        s[tid] += v;
        __syncthreads();
    }
    int total = s[1023];
    int rank  = s[tid] - cnt;  // exclusive prefix
#pragma unroll
    for (int i = 0; i < 4; i++) {
        if (m[i]) {
            int t = tid * 4 + i;
            int j = m[i] - 1;
            if (rank < CAP) { sel[e * CAP + rank] = t; tslot[t * 2 + j] = rank; }
            else            { tslot[t * 2 + j] = -1; }
            rank++;
        }
    }
    for (int r = total + tid; r < CAP; r += 1024) sel[e * CAP + r] = 0;
}

// ---------------- final combine: out = xres + mlp + gated expert outs ----
__global__ __launch_bounds__(256) void final_kernel(const float* __restrict__ xres,
                                                    const float* __restrict__ mlp,
                                                    const float* __restrict__ moeout,
                                                    const int2* __restrict__ topi,
                                                    const int* __restrict__ tslot,
                                                    const float2* __restrict__ tw,
                                                    float* __restrict__ out) {
    long long idx = (long long)blockIdx.x * blockDim.x + threadIdx.x;
    int t = (int)(idx >> 10);
    int dcol = (int)(idx & 1023);
    float v = xres[idx] + mlp[idx];
    int2 ti = topi[t];
    float2 w = tw[t];
    int s0 = tslot[t * 2], s1 = tslot[t * 2 + 1];
    if (s0 >= 0) v += w.x * moeout[((long long)ti.x * CAP + s0) * Dd + dcol];
    if (s1 >= 0) v += w.y * moeout[((long long)ti.y * CAP + s1) * Dd + dcol];
    out[idx] = v;
}

extern "C" void kernel_launch(void* const* d_in, const int* in_sizes, int n_in,
                              void* d_out, int out_size) {
    const float* x       = (const float*)d_in[0];
    const float* noise   = (const float*)d_in[1];
    const float* ln1_g   = (const float*)d_in[2];
    const float* ln1_b   = (const float*)d_in[3];
    const float* ln2_g   = (const float*)d_in[4];
    const float* ln2_b   = (const float*)d_in[5];
    const float* w_qkv   = (const float*)d_in[6];
    const float* w_proj  = (const float*)d_in[7];
    const float* b_proj  = (const float*)d_in[8];
    const float* w_route = (const float*)d_in[9];
    const float* b_route = (const float*)d_in[10];
    const float* w_noise = (const float*)d_in[11];
    const float* b_noise = (const float*)d_in[12];
    const float* we1     = (const float*)d_in[13];
    const float* be1     = (const float*)d_in[14];
    const float* we2     = (const float*)d_in[15];
    const float* be2     = (const float*)d_in[16];
    const float* w_mlp1  = (const float*)d_in[17];
    const float* b_mlp1  = (const float*)d_in[18];
    const float* w_mlp2  = (const float*)d_in[19];
    const float* b_mlp2  = (const float*)d_in[20];
    float* out = (float*)d_out;

    float*  buf;   cudaGetSymbolAddress((void**)&buf,   g_buf);
    int2*   topi;  cudaGetSymbolAddress((void**)&topi,  g_topi);
    float2* tw;    cudaGetSymbolAddress((void**)&tw,    g_tw);
    int*    tslot; cudaGetSymbolAddress((void**)&tslot, g_tslot);
    int*    sel;   cudaGetSymbolAddress((void**)&sel,   g_sel);

    float* qkv    = buf + OFF_QKV;
    float* hmlp   = buf + OFF_HMLP;
    float* x1     = buf + OFF_X1;
    float* ao     = buf + OFF_AO;
    float* xres   = buf + OFF_XRES;
    float* x2     = buf + OFF_X2;
    float* mlpout = buf + OFF_MLPOUT;
    float* moeout = buf + OFF_MOEOUT;
    float* hmoe   = buf + OFF_HMOE;

    // 1) LN1
    ln_kernel<<<Tn, 256>>>(x, ln1_g, ln1_b, x1);

    // 2) QKV = x1 @ w_qkv^T   (4096 x 3072 x 1024)
    {
        GemmP p{}; p.zdiv = 1; p.alpha = 1.0f; p.K = Dd;
        p.A = x1; p.lda = Dd;
        p.B = w_qkv; p.ldb = Dd;
        p.C = qkv; p.ldc = 3 * Dd;
        launch2<true, false>(p, Tn, 3 * Dd, 1);
    }

    // 3) fused flash attention -> ao
    {
        cudaFuncSetAttribute(flash_k, cudaFuncAttributeMaxDynamicSharedMemorySize,
                             FLASH_SMEM);
        dim3 grid(Nn / 128, Bb * Hh);
        flash_k<<<grid, 256, FLASH_SMEM>>>(qkv, ao);
    }

    // 4) xres = x + ao @ w_proj^T + b_proj
    {
        GemmP p{}; p.zdiv = 1; p.alpha = 1.0f; p.K = Dd;
        p.A = ao; p.lda = Dd;
        p.B = w_proj; p.ldb = Dd;
        p.C = xres; p.ldc = Dd;
        p.bias = b_proj; p.res = x; p.ldres = Dd;
        p.epi = 1 | 4;
        launch2<true, false>(p, Tn, Dd, 1);
    }

    // 5) LN2
    ln_kernel<<<Tn, 256>>>(xres, ln2_g, ln2_b, x2);

    // 6) routing (noisy top-2)
    route_kernel<<<Tn / 8, 256>>>(x2, w_route, b_route, w_noise, b_noise, noise, topi, tw);

    // 7) per-expert stable capacity scan
    scan_kernel<<<Ee, 1024>>>(topi, sel, tslot);

    // 8) MoE expert GEMM 1 (gathered rows): gelu(Xsel @ we1[e] + be1[e])
    {
        GemmP p{}; p.zdiv = 1; p.alpha = 1.0f; p.K = Dd;
        p.A = x2; p.lda = Dd;
        p.gidx = sel; p.sG = CAP;
        p.B = we1; p.ldb = MOEH; p.sB0 = (long long)Dd * MOEH;
        p.C = hmoe; p.ldc = MOEH; p.sC0 = (long long)CAP * MOEH;
        p.bias = be1; p.sBias = MOEH;
        p.epi = 1 | 2;
        launch2<false, true>(p, CAP, MOEH, Ee);
    }

    // 9) MoE expert GEMM 2: h_e @ we2[e] + be2[e]
    {
        GemmP p{}; p.zdiv = 1; p.alpha = 1.0f; p.K = MOEH;
        p.A = hmoe; p.lda = MOEH; p.sA0 = (long long)CAP * MOEH;
        p.B = we2; p.ldb = Dd; p.sB0 = (long long)MOEH * Dd;
        p.C = moeout; p.ldc = Dd; p.sC0 = (long long)CAP * Dd;
        p.bias = be2; p.sBias = Dd;
        p.epi = 1;
        launch2<false, false>(p, CAP, Dd, Ee);
    }

    // 10) MLP1: gelu(x2 @ w_mlp1 + b_mlp1)
    {
        GemmP p{}; p.zdiv = 1; p.alpha = 1.0f; p.K = Dd;
        p.A = x2; p.lda = Dd;
        p.B = w_mlp1; p.ldb = MLPH;
        p.C = hmlp; p.ldc = MLPH;
        p.bias = b_mlp1;
        p.epi = 1 | 2;
        launch2<false, false>(p, Tn, MLPH, 1);
    }

    // 11) MLP2: hmlp @ w_mlp2 + b_mlp2
    {
        GemmP p{}; p.zdiv = 1; p.alpha = 1.0f; p.K = MLPH;
        p.A = hmlp; p.lda = MLPH;
        p.B = w_mlp2; p.ldb = Dd;
        p.C = mlpout; p.ldc = Dd;
        p.bias = b_mlp2;
        p.epi = 1;
        launch2<false, false>(p, Tn, Dd, 1);
    }

    // 12) out = xres + mlp + gated MoE (gather; deterministic, no atomics)
    final_kernel<<<(Tn * Dd) / 256, 256>>>(xres, mlpout, moeout, topi, tslot, tw, out);
}

// round 12
// speedup vs baseline: 4.6040x; 1.4633x over previous
#include <cuda_runtime.h>
#include <cuda_fp16.h>
#include <math.h>
#include <stdint.h>

// ---------------- problem constants ----------------
#define Tn   4096
#define Dd   1024
#define Hh   16
#define HD   64
#define Nn   2048
#define Bb   2
#define Ee   4
#define CAP  2048
#define MLPH 4096
#define MOEH 256

// ---------------- fp32 scratch ----------------
#define OFF_QKV    0LL
#define OFF_XRES   12582912LL
#define OFF_X2     16777216LL
#define OFF_MLPOUT 20971520LL
#define OFF_MOEOUT 25165824LL
#define BUF_TOTAL  33554432LL
__device__ float g_buf[BUF_TOTAL];

// ---------------- fp16 scratch ----------------
#define HOFF_X1    0LL
#define HOFF_X2    4194304LL
#define HOFF_AO    8388608LL
#define HOFF_HMLP  12582912LL
#define HOFF_HMOE  29360128LL
#define HOFF_WQKV  31457280LL
#define HOFF_WPROJ 34603008LL
#define HOFF_WMLP1 35651584LL
#define HOFF_WMLP2 39845888LL
#define HOFF_WE1   44040192LL
#define HOFF_WE2   45088768LL
#define HBUF_TOTAL 46137344LL
__device__ __half g_hbuf[HBUF_TOTAL];

__device__ int2   g_topi[Tn];
__device__ float2 g_tw[Tn];
__device__ int    g_tslot[Tn * 2];
__device__ int    g_sel[Ee * CAP];

// ---------------- helpers ----------------
__device__ __forceinline__ float gelu_f(float x) {
    return 0.5f * x * (1.0f + erff(x * 0.7071067811865476f));
}
__device__ __forceinline__ unsigned f2tf(float x) {
    unsigned u;
    asm("cvt.rna.tf32.f32 %0, %1;" : "=r"(u) : "f"(x));
    return u;
}
__device__ __forceinline__ void cp16(void* dst, const void* src) {
    unsigned s = (unsigned)__cvta_generic_to_shared(dst);
    asm volatile("cp.async.cg.shared.global [%0], [%1], 16;" :: "r"(s), "l"(src));
}
#define CP_COMMIT() asm volatile("cp.async.commit_group;")
#define CP_WAIT1()  asm volatile("cp.async.wait_group 1;")
#define CP_WAIT2()  asm volatile("cp.async.wait_group 2;")

__device__ __forceinline__ void mma8(float* c, const unsigned* a, unsigned b0, unsigned b1) {
    asm volatile(
        "mma.sync.aligned.m16n8k8.row.col.f32.tf32.tf32.f32 "
        "{%0,%1,%2,%3}, {%4,%5,%6,%7}, {%8,%9}, {%0,%1,%2,%3};"
        : "+f"(c[0]), "+f"(c[1]), "+f"(c[2]), "+f"(c[3])
        : "r"(a[0]), "r"(a[1]), "r"(a[2]), "r"(a[3]), "r"(b0), "r"(b1));
}
__device__ __forceinline__ void mma16h(float* c, const unsigned* a, unsigned b0, unsigned b1) {
    asm volatile(
        "mma.sync.aligned.m16n8k16.row.col.f32.f16.f16.f32 "
        "{%0,%1,%2,%3}, {%4,%5,%6,%7}, {%8,%9}, {%0,%1,%2,%3};"
        : "+f"(c[0]), "+f"(c[1]), "+f"(c[2]), "+f"(c[3])
        : "r"(a[0]), "r"(a[1]), "r"(a[2]), "r"(a[3]), "r"(b0), "r"(b1));
}

// ================= weight conversion kernels (per launch) =================
__global__ __launch_bounds__(256) void convert_h(const float* __restrict__ in,
                                                 __half* __restrict__ out, long long n2) {
    long long i = (long long)blockIdx.x * 256 + threadIdx.x;
    if (i >= n2) return;
    float2 v = ((const float2*)in)[i];
    ((__half2*)out)[i] = __floats2half2_rn(v.x, v.y);
}
// in: [z][R][C] fp32 -> out: [z][C][R] half  (R,C multiples of 32)
__global__ __launch_bounds__(256) void transpose_h(const float* __restrict__ in,
                                                   __half* __restrict__ out, int R, int C) {
    __shared__ float tile[32][33];
    const float* inz = in + (long long)blockIdx.z * R * C;
    __half* outz = out + (long long)blockIdx.z * R * C;
    int r0 = blockIdx.y * 32, c0 = blockIdx.x * 32;
    int tx = threadIdx.x & 31, ty = threadIdx.x >> 5;   // 32 x 8
#pragma unroll
    for (int j = 0; j < 4; j++) {
        int r = r0 + ty + j * 8;
        tile[ty + j * 8][tx] = inz[(long long)r * C + c0 + tx];
    }
    __syncthreads();
#pragma unroll
    for (int j = 0; j < 4; j++) {
        int c = c0 + ty + j * 8;
        outz[(long long)c * R + r0 + tx] = __float2half_rn(tile[tx][ty + j * 8]);
    }
}

// ================= fused flash attention (tf32 mma, RNA cvt) ==============
#define LDQ 68
#define LDK 68
#define LDV 72
#define KS_OFF  8704
#define VS_OFF  17408
#define FLASH_SMEM ((8704 + 2*4352 + 2*4608) * 4)

__global__ __launch_bounds__(256, 1) void flash_k(const float* __restrict__ qkv,
                                                  __half* __restrict__ aoh) {
    extern __shared__ float sm[];
    float* Qs = sm;
    int qt = blockIdx.x, bh = blockIdx.y;
    int b = bh >> 4, h = bh & 15;
    const float* base = qkv + (long long)b * Nn * 3072 + h * 64;

    int t = threadIdx.x, w = t >> 5, lane = t & 31;
    int g = lane >> 2, tig = lane & 3;

    {
        int row = t >> 1, c0 = (t & 1) * 32;
        const float* gq = base + (long long)(qt * 128 + row) * 3072 + c0;
        float* sq = Qs + row * LDQ + c0;
#pragma unroll
        for (int j = 0; j < 8; j++) cp16(sq + j * 4, gq + j * 4);
    }
    CP_COMMIT();

    int kr = t >> 2, kc = (t & 3) * 16;
    auto loadKV = [&](int ti, int buf) {
        const float* gk = base + 1024 + (long long)(ti * 64 + kr) * 3072 + kc;
        const float* gv = base + 2048 + (long long)(ti * 64 + kr) * 3072 + kc;
        float* sk = sm + KS_OFF + buf * 4352 + kr * LDK + kc;
        float* sv = sm + VS_OFF + buf * 4608 + kr * LDV + kc;
#pragma unroll
        for (int j = 0; j < 4; j++) cp16(sk + j * 4, gk + j * 4);
#pragma unroll
        for (int j = 0; j < 4; j++) cp16(sv + j * 4, gv + j * 4);
        CP_COMMIT();
    };
    loadKV(0, 0);
    loadKV(1, 1);

    unsigned aq[8][4];
    CP_WAIT2();
    __syncthreads();
    {
        int r0 = (w * 16 + g) * LDQ;
#pragma unroll
        for (int ks = 0; ks < 8; ks++) {
            int r = r0 + ks * 8 + tig;
            aq[ks][0] = f2tf(0.125f * Qs[r]);
            aq[ks][1] = f2tf(0.125f * Qs[r + 8 * LDQ]);
            aq[ks][2] = f2tf(0.125f * Qs[r + 4]);
            aq[ks][3] = f2tf(0.125f * Qs[r + 8 * LDQ + 4]);
        }
    }
    __syncthreads();

    float accO[8][4];
#pragma unroll
    for (int nt = 0; nt < 8; nt++)
#pragma unroll
        for (int q = 0; q < 4; q++) accO[nt][q] = 0.0f;
    float m0 = -3.0e38f, m1 = -3.0e38f;
    float l0 = 0.0f, l1 = 0.0f;

    float* Ps = Qs;
    for (int i = 0; i < 32; i++) {
        int buf = i & 1;
        CP_WAIT1();
        __syncthreads();
        const float* K_ = sm + KS_OFF + buf * 4352;
        const float* V_ = sm + VS_OFF + buf * 4608;

        float S[8][4];
#pragma unroll
        for (int nt = 0; nt < 8; nt++)
#pragma unroll
            for (int q = 0; q < 4; q++) S[nt][q] = 0.0f;
#pragma unroll
        for (int ks = 0; ks < 8; ks++) {
#pragma unroll
            for (int nt = 0; nt < 8; nt++) {
                int a = (nt * 8 + g) * LDK + ks * 8 + tig;
                mma8(S[nt], aq[ks], f2tf(K_[a]), f2tf(K_[a + 4]));
            }
        }

        float mx0 = S[0][0], mx1 = S[0][2];
#pragma unroll
        for (int nt = 0; nt < 8; nt++) {
            mx0 = fmaxf(mx0, fmaxf(S[nt][0], S[nt][1]));
            mx1 = fmaxf(mx1, fmaxf(S[nt][2], S[nt][3]));
        }
        mx0 = fmaxf(mx0, __shfl_xor_sync(0xffffffffu, mx0, 1));
        mx0 = fmaxf(mx0, __shfl_xor_sync(0xffffffffu, mx0, 2));
        mx1 = fmaxf(mx1, __shfl_xor_sync(0xffffffffu, mx1, 1));
        mx1 = fmaxf(mx1, __shfl_xor_sync(0xffffffffu, mx1, 2));
        float mn0 = fmaxf(m0, mx0), mn1 = fmaxf(m1, mx1);
        float c0 = __expf(m0 - mn0), c1 = __expf(m1 - mn1);
        m0 = mn0; m1 = mn1;
        float s0 = 0.0f, s1 = 0.0f;
#pragma unroll
        for (int nt = 0; nt < 8; nt++) {
            S[nt][0] = __expf(S[nt][0] - mn0);
            S[nt][1] = __expf(S[nt][1] - mn0);
            S[nt][2] = __expf(S[nt][2] - mn1);
            S[nt][3] = __expf(S[nt][3] - mn1);
            s0 += S[nt][0] + S[nt][1];
            s1 += S[nt][2] + S[nt][3];
        }
        l0 = l0 * c0 + s0;
        l1 = l1 * c1 + s1;
#pragma unroll
        for (int nt = 0; nt < 8; nt++) {
            accO[nt][0] *= c0; accO[nt][1] *= c0;
            accO[nt][2] *= c1; accO[nt][3] *= c1;
        }

        {
            int r = (w * 16 + g) * LDQ + 2 * tig;
#pragma unroll
            for (int nt = 0; nt < 8; nt++) {
                *(float2*)&Ps[r + nt * 8] = make_float2(S[nt][0], S[nt][1]);
                *(float2*)&Ps[r + 8 * LDQ + nt * 8] = make_float2(S[nt][2], S[nt][3]);
            }
        }
        __syncthreads();

#pragma unroll
        for (int ks = 0; ks < 8; ks++) {
            unsigned ap[4];
            int r = (w * 16 + g) * LDQ + ks * 8 + tig;
            ap[0] = f2tf(Ps[r]);
            ap[1] = f2tf(Ps[r + 8 * LDQ]);
            ap[2] = f2tf(Ps[r + 4]);
            ap[3] = f2tf(Ps[r + 8 * LDQ + 4]);
#pragma unroll
            for (int nt = 0; nt < 8; nt++) {
                unsigned bv0 = f2tf(V_[(ks * 8 + tig) * LDV + nt * 8 + g]);
                unsigned bv1 = f2tf(V_[(ks * 8 + tig + 4) * LDV + nt * 8 + g]);
                mma8(accO[nt], ap, bv0, bv1);
            }
        }
        __syncthreads();
        if (i + 2 < 32) loadKV(i + 2, buf);
        else CP_COMMIT();
    }

    l0 += __shfl_xor_sync(0xffffffffu, l0, 1);
    l0 += __shfl_xor_sync(0xffffffffu, l0, 2);
    l1 += __shfl_xor_sync(0xffffffffu, l1, 1);
    l1 += __shfl_xor_sync(0xffffffffu, l1, 2);
    float inv0 = 1.0f / l0, inv1 = 1.0f / l1;
    long long tok0 = (long long)b * Nn + qt * 128 + w * 16 + g;
#pragma unroll
    for (int nt = 0; nt < 8; nt++) {
        int n = h * 64 + nt * 8 + tig * 2;
        *(__half2*)&aoh[tok0 * Dd + n] = __floats2half2_rn(accO[nt][0] * inv0, accO[nt][1] * inv0);
        *(__half2*)&aoh[(tok0 + 8) * Dd + n] = __floats2half2_rn(accO[nt][2] * inv1, accO[nt][3] * inv1);
    }
}

// ================= fp16 tensor-core GEMM (cp.async 2-stage) ===============
// C[m,n] = alpha * sum_k A[m,k] * B[n,k]  (+bias)(gelu)(+res); A,B half; out f32/half.
// 128x128 CTA, 8 warps (WM=64, WN=32), K-tile 32, 2 CTAs/SM.
struct HGemmP {
    const __half* A; const __half* B; void* C;
    const float* bias; const float* res; const int* gidx;
    int lda, ldb, ldc, ldres;
    long long sA0, sB0, sC0, sBias, sG;
    int K;
    float alpha;
    int epi;  // bit0 bias, bit1 gelu, bit2 +res
};

template <bool GATHER, bool OUTH>
__global__ __launch_bounds__(256, 2) void hgemm(HGemmP p) {
    constexpr int LDA = 40;                 // halves: 32 + 8 pad
    constexpr int ASZ = 128 * LDA;          // 5120 halves
    constexpr int STAGE = 2 * ASZ;          // A + B
    extern __shared__ __half smh[];

    int z = blockIdx.z;
    const __half* A = p.A + z * p.sA0;
    const __half* B = p.B + z * p.sB0;

    int m0 = blockIdx.x * 128, n0 = blockIdx.y * 128;
    int t = threadIdx.x;
    int w = t >> 5, lane = t & 31;
    int wm = w & 1, wn = w >> 1;            // 2 x 4 warp grid
    int g = lane >> 2, tig = lane & 3;

    // loaders: 2 threads per row, 16 halves (2x cp16) each
    int rowi = t >> 1, koff = (t & 1) * 16;
    long long arow = m0 + rowi;
    if (GATHER) arow = p.gidx[z * p.sG + m0 + rowi];
    const __half* gA = A + arow * (long long)p.lda;
    const __half* gB = B + (long long)(n0 + rowi) * p.ldb;
    int sAoff = rowi * LDA + koff;
    int sBoff = ASZ + rowi * LDA + koff;

    float acc[4][4][4];
#pragma unroll
    for (int i = 0; i < 4; i++)
#pragma unroll
        for (int j = 0; j < 4; j++)
#pragma unroll
            for (int q = 0; q < 4; q++) acc[i][j][q] = 0.0f;

    auto load_tile = [&](int ti, int buf) {
        __half* s = smh + buf * STAGE;
        int kt = ti * 32;
        cp16(s + sAoff,     gA + kt + koff);
        cp16(s + sAoff + 8, gA + kt + koff + 8);
        cp16(s + sBoff,     gB + kt + koff);
        cp16(s + sBoff + 8, gB + kt + koff + 8);
        CP_COMMIT();
    };

    auto compute = [&](int buf) {
        const __half* As_ = smh + buf * STAGE;
        const __half* Bs_ = As_ + ASZ;
#pragma unroll
        for (int ks = 0; ks < 2; ks++) {      // two k16 blocks per 32-k tile
            unsigned a[4][4], b[4][2];
#pragma unroll
            for (int mt = 0; mt < 4; mt++) {
                int rb = (wm * 64 + mt * 16 + g) * LDA + ks * 16 + 2 * tig;
                a[mt][0] = *(const unsigned*)(As_ + rb);
                a[mt][1] = *(const unsigned*)(As_ + rb + 8 * LDA);
                a[mt][2] = *(const unsigned*)(As_ + rb + 8);
                a[mt][3] = *(const unsigned*)(As_ + rb + 8 * LDA + 8);
            }
#pragma unroll
            for (int nt = 0; nt < 4; nt++) {
                int nb = (wn * 32 + nt * 8 + g) * LDA + ks * 16 + 2 * tig;
                b[nt][0] = *(const unsigned*)(Bs_ + nb);
                b[nt][1] = *(const unsigned*)(Bs_ + nb + 8);
            }
#pragma unroll
            for (int mt = 0; mt < 4; mt++)
#pragma unroll
                for (int nt = 0; nt < 4; nt++)
                    mma16h(acc[mt][nt], a[mt], b[nt][0], b[nt][1]);
        }
    };

    int ntiles = p.K >> 5;
    load_tile(0, 0);
    load_tile(1, 1);
    for (int i = 0; i < ntiles; i++) {
        CP_WAIT1();
        __syncthreads();
        compute(i & 1);
        __syncthreads();
        if (i + 2 < ntiles) load_tile(i + 2, i & 1);
        else CP_COMMIT();
    }

    const float* bias = p.bias ? (p.bias + z * p.sBias) : nullptr;
#pragma unroll
    for (int mt = 0; mt < 4; mt++) {
#pragma unroll
        for (int half_ = 0; half_ < 2; half_++) {
            int m = m0 + wm * 64 + mt * 16 + g + half_ * 8;
#pragma unroll
            for (int nt = 0; nt < 4; nt++) {
                int n = n0 + wn * 32 + nt * 8 + tig * 2;
                float v0 = acc[mt][nt][half_ * 2 + 0] * p.alpha;
                float v1 = acc[mt][nt][half_ * 2 + 1] * p.alpha;
                if (p.epi & 1) { v0 += bias[n]; v1 += bias[n + 1]; }
                if (p.epi & 2) { v0 = gelu_f(v0); v1 = gelu_f(v1); }
                if (p.epi & 4) {
                    v0 += p.res[(long long)m * p.ldres + n];
                    v1 += p.res[(long long)m * p.ldres + n + 1];
                }
                long long cidx = (long long)m * p.ldc + n + z * p.sC0;
                if (OUTH) *(__half2*)&((__half*)p.C)[cidx] = __floats2half2_rn(v0, v1);
                else      *(float2*)&((float*)p.C)[cidx] = make_float2(v0, v1);
            }
        }
    }
}

template <bool GATHER, bool OUTH>
static void launch_h(const HGemmP& p, int M, int N, int batch) {
    int smem = 2 * 2 * 128 * 40 * 2;   // 2 stages * (A+B) * 128*40 halves * 2B
    cudaFuncSetAttribute(hgemm<GATHER, OUTH>,
                         cudaFuncAttributeMaxDynamicSharedMemorySize, smem);
    dim3 grid(M / 128, N / 128, batch);
    hgemm<GATHER, OUTH><<<grid, 256, smem>>>(p);
}

// ---------------- layernorm: fp32 in, optional fp32/fp16 out -------------
__global__ __launch_bounds__(256) void ln_kernel(const float* __restrict__ x,
                                                 const float* __restrict__ g,
                                                 const float* __restrict__ b,
                                                 float* __restrict__ outf,
                                                 __half* __restrict__ outh) {
    int row = blockIdx.x;
    int tid = threadIdx.x;
    const float4* xr = (const float4*)(x + (long long)row * Dd);
    float4 v = xr[tid];
    __shared__ float s[256];

    s[tid] = v.x + v.y + v.z + v.w;
    __syncthreads();
    for (int o = 128; o > 0; o >>= 1) { if (tid < o) s[tid] += s[tid + o]; __syncthreads(); }
    float mu = s[0] * (1.0f / Dd);
    __syncthreads();

    float dx = v.x - mu, dy = v.y - mu, dz = v.z - mu, dw = v.w - mu;
    s[tid] = dx * dx + dy * dy + dz * dz + dw * dw;
    __syncthreads();
    for (int o = 128; o > 0; o >>= 1) { if (tid < o) s[tid] += s[tid + o]; __syncthreads(); }
    float rstd = rsqrtf(s[0] * (1.0f / Dd) + 1e-5f);

    float4 gg = ((const float4*)g)[tid];
    float4 bb = ((const float4*)b)[tid];
    float4 o4;
    o4.x = dx * rstd * gg.x + bb.x;
    o4.y = dy * rstd * gg.y + bb.y;
    o4.z = dz * rstd * gg.z + bb.z;
    o4.w = dw * rstd * gg.w + bb.w;
    if (outf) ((float4*)(outf + (long long)row * Dd))[tid] = o4;
    if (outh) {
        __half2* oh = (__half2*)(outh + (long long)row * Dd);
        oh[tid * 2]     = __floats2half2_rn(o4.x, o4.y);
        oh[tid * 2 + 1] = __floats2half2_rn(o4.z, o4.w);
    }
}

// ---------------- router ----------------
__global__ __launch_bounds__(256) void route_kernel(const float* __restrict__ x2,
                                                    const float* __restrict__ wr,
                                                    const float* __restrict__ br,
                                                    const float* __restrict__ wn,
                                                    const float* __restrict__ bn,
                                                    const float* __restrict__ noise,
                                                    int2* __restrict__ topi,
                                                    float2* __restrict__ tw) {
    int t    = blockIdx.x * 8 + (threadIdx.x >> 5);
    int lane = threadIdx.x & 31;
    if (t >= Tn) return;
    const float* xr = x2 + (long long)t * Dd;

    float aR[4] = {0, 0, 0, 0}, aN[4] = {0, 0, 0, 0};
    for (int d = lane; d < Dd; d += 32) {
        float xv = xr[d];
        float4 r = ((const float4*)wr)[d];
        float4 nq = ((const float4*)wn)[d];
        aR[0] += xv * r.x;  aR[1] += xv * r.y;  aR[2] += xv * r.z;  aR[3] += xv * r.w;
        aN[0] += xv * nq.x; aN[1] += xv * nq.y; aN[2] += xv * nq.z; aN[3] += xv * nq.w;
    }
#pragma unroll
    for (int o = 16; o > 0; o >>= 1) {
#pragma unroll
        for (int e = 0; e < 4; e++) {
            aR[e] += __shfl_down_sync(0xffffffffu, aR[e], o);
            aN[e] += __shfl_down_sync(0xffffffffu, aN[e], o);
        }
    }
    if (lane == 0) {
        float nv[4];
#pragma unroll
        for (int e = 0; e < 4; e++) {
            float lg  = aR[e] + br[e];
            float pre = aN[e] + bn[e];
            float sp  = (pre > 20.0f) ? pre : log1pf(expf(pre));
            nv[e] = lg + noise[t * 4 + e] * sp;
        }
        int e0 = 0;
#pragma unroll
        for (int e = 1; e < 4; e++) if (nv[e] > nv[e0]) e0 = e;
        int e1 = -1;
#pragma unroll
        for (int e = 0; e < 4; e++) if (e != e0 && (e1 < 0 || nv[e] > nv[e1])) e1 = e;
        float d  = expf(nv[e1] - nv[e0]);
        float p0 = 1.0f / (1.0f + d);
        topi[t] = make_int2(e0, e1);
        tw[t]   = make_float2(p0, d * p0);
    }
}

// ---------------- capacity scan ----------------
__global__ __launch_bounds__(1024) void scan_kernel(const int2* __restrict__ topi,
                                                    int* __restrict__ sel,
                                                    int* __restrict__ tslot) {
    int e = blockIdx.x;
    int tid = threadIdx.x;
    __shared__ int s[1024];

    int m[4]; int cnt = 0;
#pragma unroll
    for (int i = 0; i < 4; i++) {
        int t = tid * 4 + i;
        int2 ti = topi[t];
        m[i] = (ti.x == e) ? 1 : ((ti.y == e) ? 2 : 0);
        cnt += (m[i] != 0);
    }
    s[tid] = cnt;
    __syncthreads();
    for (int off = 1; off < 1024; off <<= 1) {
        int v = 0;
        if (tid >= off) v = s[tid - off];
        __syncthreads();
        s[tid] += v;
        __syncthreads();
    }
    int total = s[1023];
    int rank  = s[tid] - cnt;
#pragma unroll
    for (int i = 0; i < 4; i++) {
        if (m[i]) {
            int t = tid * 4 + i;
            int j = m[i] - 1;
            if (rank < CAP) { sel[e * CAP + rank] = t; tslot[t * 2 + j] = rank; }
            else            { tslot[t * 2 + j] = -1; }
            rank++;
        }
    }
    for (int r = total + tid; r < CAP; r += 1024) sel[e * CAP + r] = 0;
}

// ---------------- final combine ----------------
__global__ __launch_bounds__(256) void final_kernel(const float* __restrict__ xres,
                                                    const float* __restrict__ mlp,
                                                    const float* __restrict__ moeout,
                                                    const int2* __restrict__ topi,
                                                    const int* __restrict__ tslot,
                                                    const float2* __restrict__ tw,
                                                    float* __restrict__ out) {
    long long idx = (long long)blockIdx.x * blockDim.x + threadIdx.x;
    int t = (int)(idx >> 10);
    int dcol = (int)(idx & 1023);
    float v = xres[idx] + mlp[idx];
    int2 ti = topi[t];
    float2 w = tw[t];
    int s0 = tslot[t * 2], s1 = tslot[t * 2 + 1];
    if (s0 >= 0) v += w.x * moeout[((long long)ti.x * CAP + s0) * Dd + dcol];
    if (s1 >= 0) v += w.y * moeout[((long long)ti.y * CAP + s1) * Dd + dcol];
    out[idx] = v;
}

extern "C" void kernel_launch(void* const* d_in, const int* in_sizes, int n_in,
                              void* d_out, int out_size) {
    const float* x       = (const float*)d_in[0];
    const float* noise   = (const float*)d_in[1];
    const float* ln1_g   = (const float*)d_in[2];
    const float* ln1_b   = (const float*)d_in[3];
    const float* ln2_g   = (const float*)d_in[4];
    const float* ln2_b   = (const float*)d_in[5];
    const float* w_qkv   = (const float*)d_in[6];
    const float* w_proj  = (const float*)d_in[7];
    const float* b_proj  = (const float*)d_in[8];
    const float* w_route = (const float*)d_in[9];
    const float* b_route = (const float*)d_in[10];
    const float* w_noise = (const float*)d_in[11];
    const float* b_noise = (const float*)d_in[12];
    const float* we1     = (const float*)d_in[13];
    const float* be1     = (const float*)d_in[14];
    const float* we2     = (const float*)d_in[15];
    const float* be2     = (const float*)d_in[16];
    const float* w_mlp1  = (const float*)d_in[17];
    const float* b_mlp1  = (const float*)d_in[18];
    const float* w_mlp2  = (const float*)d_in[19];
    const float* b_mlp2  = (const float*)d_in[20];
    float* out = (float*)d_out;

    float*  buf;   cudaGetSymbolAddress((void**)&buf,   g_buf);
    __half* hbuf;  cudaGetSymbolAddress((void**)&hbuf,  g_hbuf);
    int2*   topi;  cudaGetSymbolAddress((void**)&topi,  g_topi);
    float2* tw;    cudaGetSymbolAddress((void**)&tw,    g_tw);
    int*    tslot; cudaGetSymbolAddress((void**)&tslot, g_tslot);
    int*    sel;   cudaGetSymbolAddress((void**)&sel,   g_sel);

    float* qkv    = buf + OFF_QKV;
    float* xres   = buf + OFF_XRES;
    float* x2     = buf + OFF_X2;
    float* mlpout = buf + OFF_MLPOUT;
    float* moeout = buf + OFF_MOEOUT;

    __half* x1h    = hbuf + HOFF_X1;
    __half* x2h    = hbuf + HOFF_X2;
    __half* aoh    = hbuf + HOFF_AO;
    __half* hmlph  = hbuf + HOFF_HMLP;
    __half* hmoeh  = hbuf + HOFF_HMOE;
    __half* wqkvh  = hbuf + HOFF_WQKV;
    __half* wprojh = hbuf + HOFF_WPROJ;
    __half* wmlp1h = hbuf + HOFF_WMLP1;
    __half* wmlp2h = hbuf + HOFF_WMLP2;
    __half* we1h   = hbuf + HOFF_WE1;
    __half* we2h   = hbuf + HOFF_WE2;

    // 0) weight shadows: straight converts ([n][k] already) + transposes ([k][n] -> [n][k])
    convert_h<<<(3145728 / 2 + 255) / 256, 256>>>(w_qkv, wqkvh, 3145728 / 2);
    convert_h<<<(1048576 / 2 + 255) / 256, 256>>>(w_proj, wprojh, 1048576 / 2);
    { dim3 g2(MLPH / 32, Dd / 32, 1);  transpose_h<<<g2, 256>>>(w_mlp1, wmlp1h, Dd, MLPH); }
    { dim3 g2(Dd / 32, MLPH / 32, 1);  transpose_h<<<g2, 256>>>(w_mlp2, wmlp2h, MLPH, Dd); }
    { dim3 g2(MOEH / 32, Dd / 32, Ee); transpose_h<<<g2, 256>>>(we1, we1h, Dd, MOEH); }
    { dim3 g2(Dd / 32, MOEH / 32, Ee); transpose_h<<<g2, 256>>>(we2, we2h, MOEH, Dd); }

    // 1) LN1 -> x1h (half only)
    ln_kernel<<<Tn, 256>>>(x, ln1_g, ln1_b, nullptr, x1h);

    // 2) QKV = x1 @ w_qkv^T -> qkv fp32
    {
        HGemmP p{}; p.alpha = 1.0f; p.K = Dd;
        p.A = x1h; p.lda = Dd;
        p.B = wqkvh; p.ldb = Dd;
        p.C = qkv; p.ldc = 3 * Dd;
        p.epi = 0;
        launch_h<false, false>(p, Tn, 3 * Dd, 1);
    }

    // 3) flash attention -> aoh (half)
    {
        cudaFuncSetAttribute(flash_k, cudaFuncAttributeMaxDynamicSharedMemorySize,
                             FLASH_SMEM);
        dim3 grid(Nn / 128, Bb * Hh);
        flash_k<<<grid, 256, FLASH_SMEM>>>(qkv, aoh);
    }

    // 4) xres = x + ao @ w_proj^T + b_proj
    {
        HGemmP p{}; p.alpha = 1.0f; p.K = Dd;
        p.A = aoh; p.lda = Dd;
        p.B = wprojh; p.ldb = Dd;
        p.C = xres; p.ldc = Dd;
        p.bias = b_proj; p.res = x; p.ldres = Dd;
        p.epi = 1 | 4;
        launch_h<false, false>(p, Tn, Dd, 1);
    }

    // 5) LN2 -> x2 (fp32, for router) + x2h
    ln_kernel<<<Tn, 256>>>(xres, ln2_g, ln2_b, x2, x2h);

    // 6) routing (fp32)
    route_kernel<<<Tn / 8, 256>>>(x2, w_route, b_route, w_noise, b_noise, noise, topi, tw);

    // 7) capacity scan
    scan_kernel<<<Ee, 1024>>>(topi, sel, tslot);

    // 8) MoE GEMM 1: gelu(gather(x2h) @ we1[e] + be1[e]) -> hmoeh (half)
    {
        HGemmP p{}; p.alpha = 1.0f; p.K = Dd;
        p.A = x2h; p.lda = Dd;
        p.gidx = sel; p.sG = CAP;
        p.B = we1h; p.ldb = Dd; p.sB0 = (long long)MOEH * Dd;
        p.C = hmoeh; p.ldc = MOEH; p.sC0 = (long long)CAP * MOEH;
        p.bias = be1; p.sBias = MOEH;
        p.epi = 1 | 2;
        launch_h<true, true>(p, CAP, MOEH, Ee);
    }

    // 9) MoE GEMM 2: hmoeh @ we2[e] + be2[e] -> moeout fp32
    {
        HGemmP p{}; p.alpha = 1.0f; p.K = MOEH;
        p.A = hmoeh; p.lda = MOEH; p.sA0 = (long long)CAP * MOEH;
        p.B = we2h; p.ldb = MOEH; p.sB0 = (long long)Dd * MOEH;
        p.C = moeout; p.ldc = Dd; p.sC0 = (long long)CAP * Dd;
        p.bias = be2; p.sBias = Dd;
        p.epi = 1;
        launch_h<false, false>(p, CAP, Dd, Ee);
    }

    // 10) MLP1 -> hmlph (half)
    {
        HGemmP p{}; p.alpha = 1.0f; p.K = Dd;
        p.A = x2h; p.lda = Dd;
        p.B = wmlp1h; p.ldb = Dd;
        p.C = hmlph; p.ldc = MLPH;
        p.bias = b_mlp1;
        p.epi = 1 | 2;
        launch_h<false, true>(p, Tn, MLPH, 1);
    }

    // 11) MLP2 -> mlpout fp32
    {
        HGemmP p{}; p.alpha = 1.0f; p.K = MLPH;
        p.A = hmlph; p.lda = MLPH;
        p.B = wmlp2h; p.ldb = MLPH;
        p.C = mlpout; p.ldc = Dd;
        p.bias = b_mlp2;
        p.epi = 1;
        launch_h<false, false>(p, Tn, Dd, 1);
    }

    // 12) final combine
    final_kernel<<<(Tn * Dd) / 256, 256>>>(xres, mlpout, moeout, topi, tslot, tw, out);
}

// round 14
// speedup vs baseline: 5.0877x; 1.1051x over previous
#include <cuda_runtime.h>
#include <cuda_fp16.h>
#include <math.h>
#include <stdint.h>

// ---------------- problem constants ----------------
#define Tn   4096
#define Dd   1024
#define Hh   16
#define HD   64
#define Nn   2048
#define Bb   2
#define Ee   4
#define CAP  2048
#define MLPH 4096
#define MOEH 256

// ---------------- fp32 scratch ----------------
#define OFF_QKV    0LL
#define OFF_XRES   12582912LL
#define OFF_X2     16777216LL
#define OFF_MLPOUT 20971520LL
#define OFF_MOEOUT 25165824LL
#define BUF_TOTAL  33554432LL
__device__ float g_buf[BUF_TOTAL];

// ---------------- fp16 scratch ----------------
#define HOFF_X1    0LL
#define HOFF_X2    4194304LL
#define HOFF_AO    8388608LL
#define HOFF_HMLP  12582912LL
#define HOFF_HMOE  29360128LL
#define HOFF_WQKV  31457280LL
#define HOFF_WPROJ 34603008LL
#define HOFF_WMLP1 35651584LL
#define HOFF_WMLP2 39845888LL
#define HOFF_WE1   44040192LL
#define HOFF_WE2   45088768LL
#define HOFF_QKVH  46137344LL
#define HBUF_TOTAL 58720256LL
__device__ __half g_hbuf[HBUF_TOTAL];

__device__ int2   g_topi[Tn];
__device__ float2 g_tw[Tn];
__device__ int    g_tslot[Tn * 2];
__device__ int    g_sel[Ee * CAP];

// ---------------- helpers ----------------
__device__ __forceinline__ float gelu_f(float x) {
    return 0.5f * x * (1.0f + erff(x * 0.7071067811865476f));
}
__device__ __forceinline__ unsigned f2tf(float x) {
    unsigned u;
    asm("cvt.rna.tf32.f32 %0, %1;" : "=r"(u) : "f"(x));
    return u;
}
__device__ __forceinline__ void cp16(void* dst, const void* src) {
    unsigned s = (unsigned)__cvta_generic_to_shared(dst);
    asm volatile("cp.async.cg.shared.global [%0], [%1], 16;" :: "r"(s), "l"(src));
}
#define CP_COMMIT() asm volatile("cp.async.commit_group;")
#define CP_WAIT1()  asm volatile("cp.async.wait_group 1;")
#define CP_WAIT2()  asm volatile("cp.async.wait_group 2;")

__device__ __forceinline__ void mma8(float* c, const unsigned* a, unsigned b0, unsigned b1) {
    asm volatile(
        "mma.sync.aligned.m16n8k8.row.col.f32.tf32.tf32.f32 "
        "{%0,%1,%2,%3}, {%4,%5,%6,%7}, {%8,%9}, {%0,%1,%2,%3};"
        : "+f"(c[0]), "+f"(c[1]), "+f"(c[2]), "+f"(c[3])
        : "r"(a[0]), "r"(a[1]), "r"(a[2]), "r"(a[3]), "r"(b0), "r"(b1));
}
__device__ __forceinline__ void mma16h(float* c, const unsigned* a, unsigned b0, unsigned b1) {
    asm volatile(
        "mma.sync.aligned.m16n8k16.row.col.f32.f16.f16.f32 "
        "{%0,%1,%2,%3}, {%4,%5,%6,%7}, {%8,%9}, {%0,%1,%2,%3};"
        : "+f"(c[0]), "+f"(c[1]), "+f"(c[2]), "+f"(c[3])
        : "r"(a[0]), "r"(a[1]), "r"(a[2]), "r"(a[3]), "r"(b0), "r"(b1));
}

// ================= weight conversion kernels (per launch) =================
__global__ __launch_bounds__(256) void convert_h(const float* __restrict__ in,
                                                 __half* __restrict__ out, long long n2) {
    long long i = (long long)blockIdx.x * 256 + threadIdx.x;
    if (i >= n2) return;
    float2 v = ((const float2*)in)[i];
    ((__half2*)out)[i] = __floats2half2_rn(v.x, v.y);
}
// in: [z][R][C] fp32 -> out: [z][C][R] half
__global__ __launch_bounds__(256) void transpose_h(const float* __restrict__ in,
                                                   __half* __restrict__ out, int R, int C) {
    __shared__ float tile[32][33];
    const float* inz = in + (long long)blockIdx.z * R * C;
    __half* outz = out + (long long)blockIdx.z * R * C;
    int r0 = blockIdx.y * 32, c0 = blockIdx.x * 32;
    int tx = threadIdx.x & 31, ty = threadIdx.x >> 5;
#pragma unroll
    for (int j = 0; j < 4; j++) {
        int r = r0 + ty + j * 8;
        tile[ty + j * 8][tx] = inz[(long long)r * C + c0 + tx];
    }
    __syncthreads();
#pragma unroll
    for (int j = 0; j < 4; j++) {
        int c = c0 + ty + j * 8;
        outz[(long long)c * R + r0 + tx] = __float2half_rn(tile[tx][ty + j * 8]);
    }
}

// ================= fused flash attention: fp16 QK^T, tf32 PV ==============
// smem bytes: Ps(float 128x68)=34816 | Ks(half 2x 64x72)=18432 | Vs(float 2x 64x72)=36864
#define LDQ  68      // floats, P staging
#define LDQH 72      // halves, Q tile
#define LDKH 72      // halves, K tiles
#define LDV  72      // floats, V tiles
#define KS_BYTE  34816
#define VS_BYTE  53248
#define FLASH_SMEM 90112

__global__ __launch_bounds__(256, 1) void flash_k(const float* __restrict__ qkv,
                                                  const __half* __restrict__ qkvh,
                                                  __half* __restrict__ aoh) {
    extern __shared__ char smraw[];
    float*  Ps = (float*)smraw;
    __half* Qh = (__half*)smraw;
    int qt = blockIdx.x, bh = blockIdx.y;
    int b = bh >> 4, h = bh & 15;
    const float*  basef = qkv  + (long long)b * Nn * 3072 + h * 64;
    const __half* baseh = qkvh + (long long)b * Nn * 3072 + h * 64;

    int t = threadIdx.x, w = t >> 5, lane = t & 31;
    int g = lane >> 2, tig = lane & 3;

    // ---- Q tile (half) load: group 0 ----
    {
        int row = t >> 1, c0 = (t & 1) * 32;
        const __half* gq = baseh + (long long)(qt * 128 + row) * 3072 + c0;
        __half* sq = Qh + row * LDQH + c0;
#pragma unroll
        for (int j = 0; j < 4; j++) cp16(sq + j * 8, gq + j * 8);
    }
    CP_COMMIT();

    // ---- K(half)/V(float) tile loader ----
    int kr = t >> 2;
    int kch = (t & 3) * 16;
    int kcf = (t & 3) * 16;
    auto loadKV = [&](int ti, int buf) {
        const __half* gk = baseh + 1024 + (long long)(ti * 64 + kr) * 3072 + kch;
        const float*  gv = basef + 2048 + (long long)(ti * 64 + kr) * 3072 + kcf;
        __half* sk = (__half*)(smraw + KS_BYTE + buf * 9216) + kr * LDKH + kch;
        float*  sv = (float*)(smraw + VS_BYTE + buf * 18432) + kr * LDV + kcf;
        cp16(sk, gk); cp16(sk + 8, gk + 8);
#pragma unroll
        for (int j = 0; j < 4; j++) cp16(sv + j * 4, gv + j * 4);
        CP_COMMIT();
    };
    loadKV(0, 0);
    loadKV(1, 1);

    // ---- Q fragments (half, scaled by 1/8 exactly) ----
    unsigned aq[4][4];
    CP_WAIT2();
    __syncthreads();
    {
        __half2 s8 = __floats2half2_rn(0.125f, 0.125f);
        int r0 = (w * 16 + g) * LDQH;
#pragma unroll
        for (int ks = 0; ks < 4; ks++) {
            int base = r0 + ks * 16 + 2 * tig;
            __half2 a0 = *(const __half2*)&Qh[base];
            __half2 a1 = *(const __half2*)&Qh[base + 8 * LDQH];
            __half2 a2 = *(const __half2*)&Qh[base + 8];
            __half2 a3 = *(const __half2*)&Qh[base + 8 * LDQH + 8];
            a0 = __hmul2(a0, s8); a1 = __hmul2(a1, s8);
            a2 = __hmul2(a2, s8); a3 = __hmul2(a3, s8);
            aq[ks][0] = *(unsigned*)&a0; aq[ks][1] = *(unsigned*)&a1;
            aq[ks][2] = *(unsigned*)&a2; aq[ks][3] = *(unsigned*)&a3;
        }
    }
    __syncthreads();   // Qh region now reusable as Ps (float)

    float accO[8][4];
#pragma unroll
    for (int nt = 0; nt < 8; nt++)
#pragma unroll
        for (int q = 0; q < 4; q++) accO[nt][q] = 0.0f;
    float m0 = -3.0e38f, m1 = -3.0e38f;
    float l0 = 0.0f, l1 = 0.0f;

    for (int i = 0; i < 32; i++) {
        int buf = i & 1;
        CP_WAIT1();
        __syncthreads();
        const __half* K_ = (const __half*)(smraw + KS_BYTE + buf * 9216);
        const float*  V_ = (const float*)(smraw + VS_BYTE + buf * 18432);

        // ---- S = Q @ K^T (fp16 mma) ----
        float S[8][4];
#pragma unroll
        for (int nt = 0; nt < 8; nt++)
#pragma unroll
            for (int q = 0; q < 4; q++) S[nt][q] = 0.0f;
#pragma unroll
        for (int ks = 0; ks < 4; ks++) {
#pragma unroll
            for (int nt = 0; nt < 8; nt++) {
                int kb = (nt * 8 + g) * LDKH + ks * 16 + 2 * tig;
                unsigned b0 = *(const unsigned*)&K_[kb];
                unsigned b1 = *(const unsigned*)&K_[kb + 8];
                mma16h(S[nt], aq[ks], b0, b1);
            }
        }

        // ---- online softmax ----
        float mx0 = S[0][0], mx1 = S[0][2];
#pragma unroll
        for (int nt = 0; nt < 8; nt++) {
            mx0 = fmaxf(mx0, fmaxf(S[nt][0], S[nt][1]));
            mx1 = fmaxf(mx1, fmaxf(S[nt][2], S[nt][3]));
        }
        mx0 = fmaxf(mx0, __shfl_xor_sync(0xffffffffu, mx0, 1));
        mx0 = fmaxf(mx0, __shfl_xor_sync(0xffffffffu, mx0, 2));
        mx1 = fmaxf(mx1, __shfl_xor_sync(0xffffffffu, mx1, 1));
        mx1 = fmaxf(mx1, __shfl_xor_sync(0xffffffffu, mx1, 2));
        float mn0 = fmaxf(m0, mx0), mn1 = fmaxf(m1, mx1);
        float c0 = __expf(m0 - mn0), c1 = __expf(m1 - mn1);
        m0 = mn0; m1 = mn1;
        float s0 = 0.0f, s1 = 0.0f;
#pragma unroll
        for (int nt = 0; nt < 8; nt++) {
            S[nt][0] = __expf(S[nt][0] - mn0);
            S[nt][1] = __expf(S[nt][1] - mn0);
            S[nt][2] = __expf(S[nt][2] - mn1);
            S[nt][3] = __expf(S[nt][3] - mn1);
            s0 += S[nt][0] + S[nt][1];
            s1 += S[nt][2] + S[nt][3];
        }
        l0 = l0 * c0 + s0;
        l1 = l1 * c1 + s1;
#pragma unroll
        for (int nt = 0; nt < 8; nt++) {
            accO[nt][0] *= c0; accO[nt][1] *= c0;
            accO[nt][2] *= c1; accO[nt][3] *= c1;
        }

        // ---- stage P (float) ----
        {
            int r = (w * 16 + g) * LDQ + 2 * tig;
#pragma unroll
            for (int nt = 0; nt < 8; nt++) {
                *(float2*)&Ps[r + nt * 8] = make_float2(S[nt][0], S[nt][1]);
                *(float2*)&Ps[r + 8 * LDQ + nt * 8] = make_float2(S[nt][2], S[nt][3]);
            }
        }
        __syncthreads();

        // ---- O += P @ V (tf32 mma) ----
#pragma unroll
        for (int ks = 0; ks < 8; ks++) {
            unsigned ap[4];
            int r = (w * 16 + g) * LDQ + ks * 8 + tig;
            ap[0] = f2tf(Ps[r]);
            ap[1] = f2tf(Ps[r + 8 * LDQ]);
            ap[2] = f2tf(Ps[r + 4]);
            ap[3] = f2tf(Ps[r + 8 * LDQ + 4]);
#pragma unroll
            for (int nt = 0; nt < 8; nt++) {
                unsigned bv0 = f2tf(V_[(ks * 8 + tig) * LDV + nt * 8 + g]);
                unsigned bv1 = f2tf(V_[(ks * 8 + tig + 4) * LDV + nt * 8 + g]);
                mma8(accO[nt], ap, bv0, bv1);
            }
        }
        __syncthreads();
        if (i + 2 < 32) loadKV(i + 2, buf);
        else CP_COMMIT();
    }

    l0 += __shfl_xor_sync(0xffffffffu, l0, 1);
    l0 += __shfl_xor_sync(0xffffffffu, l0, 2);
    l1 += __shfl_xor_sync(0xffffffffu, l1, 1);
    l1 += __shfl_xor_sync(0xffffffffu, l1, 2);
    float inv0 = 1.0f / l0, inv1 = 1.0f / l1;
    long long tok0 = (long long)b * Nn + qt * 128 + w * 16 + g;
#pragma unroll
    for (int nt = 0; nt < 8; nt++) {
        int n = h * 64 + nt * 8 + tig * 2;
        *(__half2*)&aoh[tok0 * Dd + n] = __floats2half2_rn(accO[nt][0] * inv0, accO[nt][1] * inv0);
        *(__half2*)&aoh[(tok0 + 8) * Dd + n] = __floats2half2_rn(accO[nt][2] * inv1, accO[nt][3] * inv1);
    }
}

// ================= fp16 tensor-core GEMM (cp.async 3-stage) ===============
struct HGemmP {
    const __half* A; const __half* B; void* C; __half* C2;
    const float* bias; const float* res; const int* gidx;
    int lda, ldb, ldc, ldres;
    long long sA0, sB0, sC0, sBias, sG;
    int K;
    float alpha;
    int epi;  // bit0 bias, bit1 gelu, bit2 +res
};

template <bool GATHER, bool OUTH>
__global__ __launch_bounds__(256, 2) void hgemm(HGemmP p) {
    constexpr int LDA = 40;
    constexpr int ASZ = 128 * LDA;          // 5120 halves
    constexpr int STAGE = 2 * ASZ;
    extern __shared__ __half smh[];

    int z = blockIdx.z;
    const __half* A = p.A + z * p.sA0;
    const __half* B = p.B + z * p.sB0;

    int m0 = blockIdx.x * 128, n0 = blockIdx.y * 128;
    int t = threadIdx.x;
    int w = t >> 5, lane = t & 31;
    int wm = w & 1, wn = w >> 1;
    int g = lane >> 2, tig = lane & 3;

    int rowi = t >> 1, koff = (t & 1) * 16;
    long long arow = m0 + rowi;
    if (GATHER) arow = p.gidx[z * p.sG + m0 + rowi];
    const __half* gA = A + arow * (long long)p.lda;
    const __half* gB = B + (long long)(n0 + rowi) * p.ldb;
    int sAoff = rowi * LDA + koff;
    int sBoff = ASZ + rowi * LDA + koff;

    float acc[4][4][4];
#pragma unroll
    for (int i = 0; i < 4; i++)
#pragma unroll
        for (int j = 0; j < 4; j++)
#pragma unroll
            for (int q = 0; q < 4; q++) acc[i][j][q] = 0.0f;

    auto load_tile = [&](int ti, int slot) {
        __half* s = smh + slot * STAGE;
        int kt = ti * 32;
        cp16(s + sAoff,     gA + kt + koff);
        cp16(s + sAoff + 8, gA + kt + koff + 8);
        cp16(s + sBoff,     gB + kt + koff);
        cp16(s + sBoff + 8, gB + kt + koff + 8);
        CP_COMMIT();
    };

    auto compute = [&](int slot) {
        const __half* As_ = smh + slot * STAGE;
        const __half* Bs_ = As_ + ASZ;
#pragma unroll
        for (int ks = 0; ks < 2; ks++) {
            unsigned a[4][4], b[4][2];
#pragma unroll
            for (int mt = 0; mt < 4; mt++) {
                int rb = (wm * 64 + mt * 16 + g) * LDA + ks * 16 + 2 * tig;
                a[mt][0] = *(const unsigned*)(As_ + rb);
                a[mt][1] = *(const unsigned*)(As_ + rb + 8 * LDA);
                a[mt][2] = *(const unsigned*)(As_ + rb + 8);
                a[mt][3] = *(const unsigned*)(As_ + rb + 8 * LDA + 8);
            }
#pragma unroll
            for (int nt = 0; nt < 4; nt++) {
                int nb = (wn * 32 + nt * 8 + g) * LDA + ks * 16 + 2 * tig;
                b[nt][0] = *(const unsigned*)(Bs_ + nb);
                b[nt][1] = *(const unsigned*)(Bs_ + nb + 8);
            }
#pragma unroll
            for (int mt = 0; mt < 4; mt++)
#pragma unroll
                for (int nt = 0; nt < 4; nt++)
                    mma16h(acc[mt][nt], a[mt], b[nt][0], b[nt][1]);
        }
    };

    // ---- 3-stage pipeline: one barrier per tile, 2 tiles in flight ----
    int ntiles = p.K >> 5;
    load_tile(0, 0);
    load_tile(1, 1);
    for (int i = 0; i < ntiles; i++) {
        CP_WAIT1();
        __syncthreads();
        if (i + 2 < ntiles) {
            int s2 = i + 2; s2 = s2 - (s2 / 3) * 3;
            load_tile(i + 2, s2);
        } else CP_COMMIT();
        compute(i - (i / 3) * 3);
    }

    const float* bias = p.bias ? (p.bias + z * p.sBias) : nullptr;
#pragma unroll
    for (int mt = 0; mt < 4; mt++) {
#pragma unroll
        for (int half_ = 0; half_ < 2; half_++) {
            int m = m0 + wm * 64 + mt * 16 + g + half_ * 8;
#pragma unroll
            for (int nt = 0; nt < 4; nt++) {
                int n = n0 + wn * 32 + nt * 8 + tig * 2;
                float v0 = acc[mt][nt][half_ * 2 + 0] * p.alpha;
                float v1 = acc[mt][nt][half_ * 2 + 1] * p.alpha;
                if (p.epi & 1) { v0 += bias[n]; v1 += bias[n + 1]; }
                if (p.epi & 2) { v0 = gelu_f(v0); v1 = gelu_f(v1); }
                if (p.epi & 4) {
                    v0 += p.res[(long long)m * p.ldres + n];
                    v1 += p.res[(long long)m * p.ldres + n + 1];
                }
                long long cidx = (long long)m * p.ldc + n + z * p.sC0;
                if (OUTH) *(__half2*)&((__half*)p.C)[cidx] = __floats2half2_rn(v0, v1);
                else      *(float2*)&((float*)p.C)[cidx] = make_float2(v0, v1);
                if (p.C2) *(__half2*)&p.C2[cidx] = __floats2half2_rn(v0, v1);
            }
        }
    }
}

template <bool GATHER, bool OUTH>
static void launch_h(const HGemmP& p, int M, int N, int batch) {
    int smem = 3 * 2 * 128 * 40 * 2;   // 3 stages * (A+B) * 128*40 halves * 2B
    cudaFuncSetAttribute(hgemm<GATHER, OUTH>,
                         cudaFuncAttributeMaxDynamicSharedMemorySize, smem);
    dim3 grid(M / 128, N / 128, batch);
    hgemm<GATHER, OUTH><<<grid, 256, smem>>>(p);
}

// ---------------- layernorm ----------------
__global__ __launch_bounds__(256) void ln_kernel(const float* __restrict__ x,
                                                 const float* __restrict__ g,
                                                 const float* __restrict__ b,
                                                 float* __restrict__ outf,
                                                 __half* __restrict__ outh) {
    int row = blockIdx.x;
    int tid = threadIdx.x;
    const float4* xr = (const float4*)(x + (long long)row * Dd);
    float4 v = xr[tid];
    __shared__ float s[256];

    s[tid] = v.x + v.y + v.z + v.w;
    __syncthreads();
    for (int o = 128; o > 0; o >>= 1) { if (tid < o) s[tid] += s[tid + o]; __syncthreads(); }
    float mu = s[0] * (1.0f / Dd);
    __syncthreads();

    float dx = v.x - mu, dy = v.y - mu, dz = v.z - mu, dw = v.w - mu;
    s[tid] = dx * dx + dy * dy + dz * dz + dw * dw;
    __syncthreads();
    for (int o = 128; o > 0; o >>= 1) { if (tid < o) s[tid] += s[tid + o]; __syncthreads(); }
    float rstd = rsqrtf(s[0] * (1.0f / Dd) + 1e-5f);

    float4 gg = ((const float4*)g)[tid];
    float4 bb = ((const float4*)b)[tid];
    float4 o4;
    o4.x = dx * rstd * gg.x + bb.x;
    o4.y = dy * rstd * gg.y + bb.y;
    o4.z = dz * rstd * gg.z + bb.z;
    o4.w = dw * rstd * gg.w + bb.w;
    if (outf) ((float4*)(outf + (long long)row * Dd))[tid] = o4;
    if (outh) {
        __half2* oh = (__half2*)(outh + (long long)row * Dd);
        oh[tid * 2]     = __floats2half2_rn(o4.x, o4.y);
        oh[tid * 2 + 1] = __floats2half2_rn(o4.z, o4.w);
    }
}

// ---------------- router ----------------
__global__ __launch_bounds__(256) void route_kernel(const float* __restrict__ x2,
                                                    const float* __restrict__ wr,
                                                    const float* __restrict__ br,
                                                    const float* __restrict__ wn,
                                                    const float* __restrict__ bn,
                                                    const float* __restrict__ noise,
                                                    int2* __restrict__ topi,
                                                    float2* __restrict__ tw) {
    int t    = blockIdx.x * 8 + (threadIdx.x >> 5);
    int lane = threadIdx.x & 31;
    if (t >= Tn) return;
    const float* xr = x2 + (long long)t * Dd;

    float aR[4] = {0, 0, 0, 0}, aN[4] = {0, 0, 0, 0};
    for (int d = lane; d < Dd; d += 32) {
        float xv = xr[d];
        float4 r = ((const float4*)wr)[d];
        float4 nq = ((const float4*)wn)[d];
        aR[0] += xv * r.x;  aR[1] += xv * r.y;  aR[2] += xv * r.z;  aR[3] += xv * r.w;
        aN[0] += xv * nq.x; aN[1] += xv * nq.y; aN[2] += xv * nq.z; aN[3] += xv * nq.w;
    }
#pragma unroll
    for (int o = 16; o > 0; o >>= 1) {
#pragma unroll
        for (int e = 0; e < 4; e++) {
            aR[e] += __shfl_down_sync(0xffffffffu, aR[e], o);
            aN[e] += __shfl_down_sync(0xffffffffu, aN[e], o);
        }
    }
    if (lane == 0) {
        float nv[4];
#pragma unroll
        for (int e = 0; e < 4; e++) {
            float lg  = aR[e] + br[e];
            float pre = aN[e] + bn[e];
            float sp  = (pre > 20.0f) ? pre : log1pf(expf(pre));
            nv[e] = lg + noise[t * 4 + e] * sp;
        }
        int e0 = 0;
#pragma unroll
        for (int e = 1; e < 4; e++) if (nv[e] > nv[e0]) e0 = e;
        int e1 = -1;
#pragma unroll
        for (int e = 0; e < 4; e++) if (e != e0 && (e1 < 0 || nv[e] > nv[e1])) e1 = e;
        float d  = expf(nv[e1] - nv[e0]);
        float p0 = 1.0f / (1.0f + d);
        topi[t] = make_int2(e0, e1);
        tw[t]   = make_float2(p0, d * p0);
    }
}

// ---------------- capacity scan ----------------
__global__ __launch_bounds__(1024) void scan_kernel(const int2* __restrict__ topi,
                                                    int* __restrict__ sel,
                                                    int* __restrict__ tslot) {
    int e = blockIdx.x;
    int tid = threadIdx.x;
    __shared__ int s[1024];

    int m[4]; int cnt = 0;
#pragma unroll
    for (int i = 0; i < 4; i++) {
        int t = tid * 4 + i;
        int2 ti = topi[t];
        m[i] = (ti.x == e) ? 1 : ((ti.y == e) ? 2 : 0);
        cnt += (m[i] != 0);
    }
    s[tid] = cnt;
    __syncthreads();
    for (int off = 1; off < 1024; off <<= 1) {
        int v = 0;
        if (tid >= off) v = s[tid - off];
        __syncthreads();
        s[tid] += v;
        __syncthreads();
    }
    int total = s[1023];
    int rank  = s[tid] - cnt;
#pragma unroll
    for (int i = 0; i < 4; i++) {
        if (m[i]) {
            int t = tid * 4 + i;
            int j = m[i] - 1;
            if (rank < CAP) { sel[e * CAP + rank] = t; tslot[t * 2 + j] = rank; }
            else            { tslot[t * 2 + j] = -1; }
            rank++;
        }
    }
    for (int r = total + tid; r < CAP; r += 1024) sel[e * CAP + r] = 0;
}

// ---------------- final combine ----------------
__global__ __launch_bounds__(256) void final_kernel(const float* __restrict__ xres,
                                                    const float* __restrict__ mlp,
                                                    const float* __restrict__ moeout,
                                                    const int2* __restrict__ topi,
                                                    const int* __restrict__ tslot,
                                                    const float2* __restrict__ tw,
                                                    float* __restrict__ out) {
    long long idx = (long long)blockIdx.x * blockDim.x + threadIdx.x;
    int t = (int)(idx >> 10);
    int dcol = (int)(idx & 1023);
    float v = xres[idx] + mlp[idx];
    int2 ti = topi[t];
    float2 w = tw[t];
    int s0 = tslot[t * 2], s1 = tslot[t * 2 + 1];
    if (s0 >= 0) v += w.x * moeout[((long long)ti.x * CAP + s0) * Dd + dcol];
    if (s1 >= 0) v += w.y * moeout[((long long)ti.y * CAP + s1) * Dd + dcol];
    out[idx] = v;
}

extern "C" void kernel_launch(void* const* d_in, const int* in_sizes, int n_in,
                              void* d_out, int out_size) {
    const float* x       = (const float*)d_in[0];
    const float* noise   = (const float*)d_in[1];
    const float* ln1_g   = (const float*)d_in[2];
    const float* ln1_b   = (const float*)d_in[3];
    const float* ln2_g   = (const float*)d_in[4];
    const float* ln2_b   = (const float*)d_in[5];
    const float* w_qkv   = (const float*)d_in[6];
    const float* w_proj  = (const float*)d_in[7];
    const float* b_proj  = (const float*)d_in[8];
    const float* w_route = (const float*)d_in[9];
    const float* b_route = (const float*)d_in[10];
    const float* w_noise = (const float*)d_in[11];
    const float* b_noise = (const float*)d_in[12];
    const float* we1     = (const float*)d_in[13];
    const float* be1     = (const float*)d_in[14];
    const float* we2     = (const float*)d_in[15];
    const float* be2     = (const float*)d_in[16];
    const float* w_mlp1  = (const float*)d_in[17];
    const float* b_mlp1  = (const float*)d_in[18];
    const float* w_mlp2  = (const float*)d_in[19];
    const float* b_mlp2  = (const float*)d_in[20];
    float* out = (float*)d_out;

    float*  buf;   cudaGetSymbolAddress((void**)&buf,   g_buf);
    __half* hbuf;  cudaGetSymbolAddress((void**)&hbuf,  g_hbuf);
    int2*   topi;  cudaGetSymbolAddress((void**)&topi,  g_topi);
    float2* tw;    cudaGetSymbolAddress((void**)&tw,    g_tw);
    int*    tslot; cudaGetSymbolAddress((void**)&tslot, g_tslot);
    int*    sel;   cudaGetSymbolAddress((void**)&sel,   g_sel);

    float* qkv    = buf + OFF_QKV;
    float* xres   = buf + OFF_XRES;
    float* x2     = buf + OFF_X2;
    float* mlpout = buf + OFF_MLPOUT;
    float* moeout = buf + OFF_MOEOUT;

    __half* x1h    = hbuf + HOFF_X1;
    __half* x2h    = hbuf + HOFF_X2;
    __half* aoh    = hbuf + HOFF_AO;
    __half* hmlph  = hbuf + HOFF_HMLP;
    __half* hmoeh  = hbuf + HOFF_HMOE;
    __half* wqkvh  = hbuf + HOFF_WQKV;
    __half* wprojh = hbuf + HOFF_WPROJ;
    __half* wmlp1h = hbuf + HOFF_WMLP1;
    __half* wmlp2h = hbuf + HOFF_WMLP2;
    __half* we1h   = hbuf + HOFF_WE1;
    __half* we2h   = hbuf + HOFF_WE2;
    __half* qkvh   = hbuf + HOFF_QKVH;

    // 0) weight shadows
    convert_h<<<(3145728 / 2 + 255) / 256, 256>>>(w_qkv, wqkvh, 3145728 / 2);
    convert_h<<<(1048576 / 2 + 255) / 256, 256>>>(w_proj, wprojh, 1048576 / 2);
    { dim3 g2(MLPH / 32, Dd / 32, 1);  transpose_h<<<g2, 256>>>(w_mlp1, wmlp1h, Dd, MLPH); }
    { dim3 g2(Dd / 32, MLPH / 32, 1);  transpose_h<<<g2, 256>>>(w_mlp2, wmlp2h, MLPH, Dd); }
    { dim3 g2(MOEH / 32, Dd / 32, Ee); transpose_h<<<g2, 256>>>(we1, we1h, Dd, MOEH); }
    { dim3 g2(Dd / 32, MOEH / 32, Ee); transpose_h<<<g2, 256>>>(we2, we2h, MOEH, Dd); }

    // 1) LN1 -> x1h
    ln_kernel<<<Tn, 256>>>(x, ln1_g, ln1_b, nullptr, x1h);

    // 2) QKV GEMM -> qkv (fp32) + qkvh (half)
    {
        HGemmP p{}; p.alpha = 1.0f; p.K = Dd;
        p.A = x1h; p.lda = Dd;
        p.B = wqkvh; p.ldb = Dd;
        p.C = qkv; p.ldc = 3 * Dd;
        p.C2 = qkvh;
        p.epi = 0;
        launch_h<false, false>(p, Tn, 3 * Dd, 1);
    }

    // 3) flash attention (fp16 QK, tf32 PV) -> aoh
    {
        cudaFuncSetAttribute(flash_k, cudaFuncAttributeMaxDynamicSharedMemorySize,
                             FLASH_SMEM);
        dim3 grid(Nn / 128, Bb * Hh);
        flash_k<<<grid, 256, FLASH_SMEM>>>(qkv, qkvh, aoh);
    }

    // 4) xres = x + ao @ w_proj^T + b_proj
    {
        HGemmP p{}; p.alpha = 1.0f; p.K = Dd;
        p.A = aoh; p.lda = Dd;
        p.B = wprojh; p.ldb = Dd;
        p.C = xres; p.ldc = Dd;
        p.bias = b_proj; p.res = x; p.ldres = Dd;
        p.epi = 1 | 4;
        launch_h<false, false>(p, Tn, Dd, 1);
    }

    // 5) LN2 -> x2 (fp32) + x2h
    ln_kernel<<<Tn, 256>>>(xres, ln2_g, ln2_b, x2, x2h);

    // 6) routing
    route_kernel<<<Tn / 8, 256>>>(x2, w_route, b_route, w_noise, b_noise, noise, topi, tw);

    // 7) capacity scan
    scan_kernel<<<Ee, 1024>>>(topi, sel, tslot);

    // 8) MoE GEMM 1 -> hmoeh (half)
    {
        HGemmP p{}; p.alpha = 1.0f; p.K = Dd;
        p.A = x2h; p.lda = Dd;
        p.gidx = sel; p.sG = CAP;
        p.B = we1h; p.ldb = Dd; p.sB0 = (long long)MOEH * Dd;
        p.C = hmoeh; p.ldc = MOEH; p.sC0 = (long long)CAP * MOEH;
        p.bias = be1; p.sBias = MOEH;
        p.epi = 1 | 2;
        launch_h<true, true>(p, CAP, MOEH, Ee);
    }

    // 9) MoE GEMM 2 -> moeout fp32
    {
        HGemmP p{}; p.alpha = 1.0f; p.K = MOEH;
        p.A = hmoeh; p.lda = MOEH; p.sA0 = (long long)CAP * MOEH;
        p.B = we2h; p.ldb = MOEH; p.sB0 = (long long)Dd * MOEH;
        p.C = moeout; p.ldc = Dd; p.sC0 = (long long)CAP * Dd;
        p.bias = be2; p.sBias = Dd;
        p.epi = 1;
        launch_h<false, false>(p, CAP, Dd, Ee);
    }

    // 10) MLP1 -> hmlph (half)
    {
        HGemmP p{}; p.alpha = 1.0f; p.K = Dd;
        p.A = x2h; p.lda = Dd;
        p.B = wmlp1h; p.ldb = Dd;
        p.C = hmlph; p.ldc = MLPH;
        p.bias = b_mlp1;
        p.epi = 1 | 2;
        launch_h<false, true>(p, Tn, MLPH, 1);
    }

    // 11) MLP2 -> mlpout fp32
    {
        HGemmP p{}; p.alpha = 1.0f; p.K = MLPH;
        p.A = hmlph; p.lda = MLPH;
        p.B = wmlp2h; p.ldb = MLPH;
        p.C = mlpout; p.ldc = Dd;
        p.bias = b_mlp2;
        p.epi = 1;
        launch_h<false, false>(p, Tn, Dd, 1);
    }

    // 12) final combine
    final_kernel<<<(Tn * Dd) / 256, 256>>>(xres, mlpout, moeout, topi, tslot, tw, out);
}

// round 17
// speedup vs baseline: 5.8862x; 1.1569x over previous
#include <cuda_runtime.h>
#include <cuda_fp16.h>
#include <math.h>
#include <stdint.h>

// ---------------- problem constants ----------------
#define Tn   4096
#define Dd   1024
#define Hh   16
#define HD   64
#define Nn   2048
#define Bb   2
#define Ee   4
#define CAP  2048
#define MLPH 4096
#define MOEH 256

// ---------------- fp32 scratch ----------------
#define OFF_XRES   0LL
#define OFF_X2     4194304LL
#define OFF_MLPOUT 8388608LL
#define OFF_MOEOUT 12582912LL
#define BUF_TOTAL  20971520LL
__device__ float g_buf[BUF_TOTAL];

// ---------------- fp16 scratch ----------------
#define HOFF_X1    0LL
#define HOFF_X2    4194304LL
#define HOFF_AO    8388608LL
#define HOFF_HMLP  12582912LL
#define HOFF_HMOE  29360128LL
#define HOFF_WQKV  31457280LL
#define HOFF_WPROJ 34603008LL
#define HOFF_WMLP1 35651584LL
#define HOFF_WMLP2 39845888LL
#define HOFF_WE1   44040192LL
#define HOFF_WE2   45088768LL
#define HOFF_QKVH  46137344LL
#define HOFF_VT    58720256LL
#define HBUF_TOTAL 62914560LL
__device__ __half g_hbuf[HBUF_TOTAL];

__device__ int2   g_topi[Tn];
__device__ float2 g_tw[Tn];
__device__ int    g_tslot[Tn * 2];
__device__ int    g_sel[Ee * CAP];

// ---------------- helpers ----------------
__device__ __forceinline__ float gelu_f(float x) {
    return 0.5f * x * (1.0f + erff(x * 0.7071067811865476f));
}
__device__ __forceinline__ void cp16(void* dst, const void* src) {
    unsigned s = (unsigned)__cvta_generic_to_shared(dst);
    asm volatile("cp.async.cg.shared.global [%0], [%1], 16;" :: "r"(s), "l"(src));
}
#define CP_COMMIT() asm volatile("cp.async.commit_group;")
#define CP_WAIT1()  asm volatile("cp.async.wait_group 1;")
#define CP_WAIT2()  asm volatile("cp.async.wait_group 2;")

__device__ __forceinline__ void mma16h(float* c, const unsigned* a, unsigned b0, unsigned b1) {
    asm volatile(
        "mma.sync.aligned.m16n8k16.row.col.f32.f16.f16.f32 "
        "{%0,%1,%2,%3}, {%4,%5,%6,%7}, {%8,%9}, {%0,%1,%2,%3};"
        : "+f"(c[0]), "+f"(c[1]), "+f"(c[2]), "+f"(c[3])
        : "r"(a[0]), "r"(a[1]), "r"(a[2]), "r"(a[3]), "r"(b0), "r"(b1));
}

// ================= weight conversion kernels (per launch) =================
__global__ __launch_bounds__(256) void convert_h(const float* __restrict__ in,
                                                 __half* __restrict__ out, long long n2) {
    long long i = (long long)blockIdx.x * 256 + threadIdx.x;
    if (i >= n2) return;
    float2 v = ((const float2*)in)[i];
    ((__half2*)out)[i] = __floats2half2_rn(v.x, v.y);
}
// in: [z][R][C] fp32 -> out: [z][C][R] half
__global__ __launch_bounds__(256) void transpose_h(const float* __restrict__ in,
                                                   __half* __restrict__ out, int R, int C) {
    __shared__ float tile[32][33];
    const float* inz = in + (long long)blockIdx.z * R * C;
    __half* outz = out + (long long)blockIdx.z * R * C;
    int r0 = blockIdx.y * 32, c0 = blockIdx.x * 32;
    int tx = threadIdx.x & 31, ty = threadIdx.x >> 5;
#pragma unroll
    for (int j = 0; j < 4; j++) {
        int r = r0 + ty + j * 8;
        tile[ty + j * 8][tx] = inz[(long long)r * C + c0 + tx];
    }
    __syncthreads();
#pragma unroll
    for (int j = 0; j < 4; j++) {
        int c = c0 + ty + j * 8;
        outz[(long long)c * R + r0 + tx] = __float2half_rn(tile[tx][ty + j * 8]);
    }
}

// V transpose: qkvh V slice [key][dim] -> vth[bh][dim][key]
__global__ __launch_bounds__(256) void vtrans_k(const __half* __restrict__ qkvh,
                                                __half* __restrict__ vth) {
    __shared__ __half tile[64][72];
    int bh = blockIdx.y, key0 = blockIdx.x * 64;
    int b = bh >> 4, h = bh & 15;
    const __half* src = qkvh + (long long)b * Nn * 3072 + 2048 + h * 64;
    int t = threadIdx.x;
    int r = t >> 2, c0 = (t & 3) * 16;
    const __half* s = src + (long long)(key0 + r) * 3072 + c0;
    *(uint4*)&tile[r][c0]     = *(const uint4*)(s);
    *(uint4*)&tile[r][c0 + 8] = *(const uint4*)(s + 8);
    __syncthreads();
    int d = t >> 2, k0 = (t & 3) * 16;
    __half* o = vth + ((long long)bh * 64 + d) * 2048 + key0 + k0;
#pragma unroll
    for (int j = 0; j < 16; j++) o[j] = tile[k0 + j][d];
}

// ================= fused flash attention: all fp16 mma ====================
// smem (halves, ld 72): QP 128x72 | Ks 2x 64x72 | Vt 2x 64x72  = 55296 B
#define LDH 72
#define KS_OFFH 9216
#define VS_OFFH 18432
#define FLASH_SMEM 55296

__global__ __launch_bounds__(256, 2) void flash_k(const __half* __restrict__ qkvh,
                                                  const __half* __restrict__ vth,
                                                  __half* __restrict__ aoh) {
    extern __shared__ __half smh[];
    __half* QP = smh;
    int qt = blockIdx.x, bh = blockIdx.y;
    int b = bh >> 4, h = bh & 15;
    const __half* baseh = qkvh + (long long)b * Nn * 3072 + h * 64;
    const __half* vbase = vth + (long long)bh * 64 * 2048;

    int t = threadIdx.x, w = t >> 5, lane = t & 31;
    int g = lane >> 2, tig = lane & 3;

    // ---- Q tile load (group 0) ----
    {
        int row = t >> 1, c0 = (t & 1) * 32;
        const __half* gq = baseh + (long long)(qt * 128 + row) * 3072 + c0;
        __half* sq = QP + row * LDH + c0;
#pragma unroll
        for (int j = 0; j < 4; j++) cp16(sq + j * 8, gq + j * 8);
    }
    CP_COMMIT();

    // ---- K / Vt tile loader (both half) ----
    int kr = t >> 2, kc = (t & 3) * 16;
    auto loadKV = [&](int ti, int buf) {
        const __half* gk = baseh + 1024 + (long long)(ti * 64 + kr) * 3072 + kc;
        const __half* gv = vbase + (long long)kr * 2048 + ti * 64 + kc;
        __half* sk = smh + KS_OFFH + buf * 4608 + kr * LDH + kc;
        __half* sv = smh + VS_OFFH + buf * 4608 + kr * LDH + kc;
        cp16(sk, gk); cp16(sk + 8, gk + 8);
        cp16(sv, gv); cp16(sv + 8, gv + 8);
        CP_COMMIT();
    };
    loadKV(0, 0);
    loadKV(1, 1);

    // ---- Q fragments (half, scaled by 1/8 exactly) ----
    unsigned aq[4][4];
    CP_WAIT2();
    __syncthreads();
    {
        __half2 s8 = __floats2half2_rn(0.125f, 0.125f);
        int r0 = (w * 16 + g) * LDH;
#pragma unroll
        for (int ks = 0; ks < 4; ks++) {
            int base = r0 + ks * 16 + 2 * tig;
            __half2 a0 = *(const __half2*)&QP[base];
            __half2 a1 = *(const __half2*)&QP[base + 8 * LDH];
            __half2 a2 = *(const __half2*)&QP[base + 8];
            __half2 a3 = *(const __half2*)&QP[base + 8 * LDH + 8];
            a0 = __hmul2(a0, s8); a1 = __hmul2(a1, s8);
            a2 = __hmul2(a2, s8); a3 = __hmul2(a3, s8);
            aq[ks][0] = *(unsigned*)&a0; aq[ks][1] = *(unsigned*)&a1;
            aq[ks][2] = *(unsigned*)&a2; aq[ks][3] = *(unsigned*)&a3;
        }
    }
    __syncthreads();   // QP now reusable as P staging

    float accO[8][4];
#pragma unroll
    for (int nt = 0; nt < 8; nt++)
#pragma unroll
        for (int q = 0; q < 4; q++) accO[nt][q] = 0.0f;
    float m0 = -3.0e38f, m1 = -3.0e38f;
    float l0 = 0.0f, l1 = 0.0f;

    for (int i = 0; i < 32; i++) {
        int buf = i & 1;
        CP_WAIT1();
        __syncthreads();
        const __half* K_ = smh + KS_OFFH + buf * 4608;
        const __half* V_ = smh + VS_OFFH + buf * 4608;

        // ---- S = Q @ K^T (fp16) ----
        float S[8][4];
#pragma unroll
        for (int nt = 0; nt < 8; nt++)
#pragma unroll
            for (int q = 0; q < 4; q++) S[nt][q] = 0.0f;
#pragma unroll
        for (int ks = 0; ks < 4; ks++) {
#pragma unroll
            for (int nt = 0; nt < 8; nt++) {
                int kb = (nt * 8 + g) * LDH + ks * 16 + 2 * tig;
                unsigned b0 = *(const unsigned*)&K_[kb];
                unsigned b1 = *(const unsigned*)&K_[kb + 8];
                mma16h(S[nt], aq[ks], b0, b1);
            }
        }

        // ---- online softmax ----
        float mx0 = S[0][0], mx1 = S[0][2];
#pragma unroll
        for (int nt = 0; nt < 8; nt++) {
            mx0 = fmaxf(mx0, fmaxf(S[nt][0], S[nt][1]));
            mx1 = fmaxf(mx1, fmaxf(S[nt][2], S[nt][3]));
        }
        mx0 = fmaxf(mx0, __shfl_xor_sync(0xffffffffu, mx0, 1));
        mx0 = fmaxf(mx0, __shfl_xor_sync(0xffffffffu, mx0, 2));
        mx1 = fmaxf(mx1, __shfl_xor_sync(0xffffffffu, mx1, 1));
        mx1 = fmaxf(mx1, __shfl_xor_sync(0xffffffffu, mx1, 2));
        float mn0 = fmaxf(m0, mx0), mn1 = fmaxf(m1, mx1);
        float c0 = __expf(m0 - mn0), c1 = __expf(m1 - mn1);
        m0 = mn0; m1 = mn1;
        float s0 = 0.0f, s1 = 0.0f;
#pragma unroll
        for (int nt = 0; nt < 8; nt++) {
            S[nt][0] = __expf(S[nt][0] - mn0);
            S[nt][1] = __expf(S[nt][1] - mn0);
            S[nt][2] = __expf(S[nt][2] - mn1);
            S[nt][3] = __expf(S[nt][3] - mn1);
            s0 += S[nt][0] + S[nt][1];
            s1 += S[nt][2] + S[nt][3];
        }
        l0 = l0 * c0 + s0;
        l1 = l1 * c1 + s1;
#pragma unroll
        for (int nt = 0; nt < 8; nt++) {
            accO[nt][0] *= c0; accO[nt][1] *= c0;
            accO[nt][2] *= c1; accO[nt][3] *= c1;
        }

        // ---- stage P as half ----
        {
            int r = (w * 16 + g) * LDH + 2 * tig;
#pragma unroll
            for (int nt = 0; nt < 8; nt++) {
                *(__half2*)&QP[r + nt * 8] = __floats2half2_rn(S[nt][0], S[nt][1]);
                *(__half2*)&QP[r + 8 * LDH + nt * 8] = __floats2half2_rn(S[nt][2], S[nt][3]);
            }
        }
        __syncthreads();

        // ---- O += P @ V (fp16; V^T tile is n-major k-contig) ----
#pragma unroll
        for (int ks = 0; ks < 4; ks++) {
            unsigned ap[4];
            int rr = (w * 16 + g) * LDH + ks * 16 + 2 * tig;
            ap[0] = *(const unsigned*)&QP[rr];
            ap[1] = *(const unsigned*)&QP[rr + 8 * LDH];
            ap[2] = *(const unsigned*)&QP[rr + 8];
            ap[3] = *(const unsigned*)&QP[rr + 8 * LDH + 8];
#pragma unroll
            for (int nt = 0; nt < 8; nt++) {
                int nb = (nt * 8 + g) * LDH + ks * 16 + 2 * tig;
                unsigned bv0 = *(const unsigned*)&V_[nb];
                unsigned bv1 = *(const unsigned*)&V_[nb + 8];
                mma16h(accO[nt], ap, bv0, bv1);
            }
        }
        __syncthreads();
        if (i + 2 < 32) loadKV(i + 2, buf);
        else CP_COMMIT();
    }

    l0 += __shfl_xor_sync(0xffffffffu, l0, 1);
    l0 += __shfl_xor_sync(0xffffffffu, l0, 2);
    l1 += __shfl_xor_sync(0xffffffffu, l1, 1);
    l1 += __shfl_xor_sync(0xffffffffu, l1, 2);
    float inv0 = 1.0f / l0, inv1 = 1.0f / l1;
    long long tok0 = (long long)b * Nn + qt * 128 + w * 16 + g;
#pragma unroll
    for (int nt = 0; nt < 8; nt++) {
        int n = h * 64 + nt * 8 + tig * 2;
        *(__half2*)&aoh[tok0 * Dd + n] = __floats2half2_rn(accO[nt][0] * inv0, accO[nt][1] * inv0);
        *(__half2*)&aoh[(tok0 + 8) * Dd + n] = __floats2half2_rn(accO[nt][2] * inv1, accO[nt][3] * inv1);
    }
}

// ================= fp16 tensor-core GEMM (cp.async 3-stage) ===============
struct HGemmP {
    const __half* A; const __half* B; void* C;
    const float* bias; const float* res; const int* gidx;
    int lda, ldb, ldc, ldres;
    long long sA0, sB0, sC0, sBias, sG;
    int K;
    float alpha;
    int epi;  // bit0 bias, bit1 gelu, bit2 +res
};

template <bool GATHER, bool OUTH>
__global__ __launch_bounds__(256, 2) void hgemm(HGemmP p) {
    constexpr int LDA = 40;
    constexpr int ASZ = 128 * LDA;
    constexpr int STAGE = 2 * ASZ;
    extern __shared__ __half smh[];

    int z = blockIdx.z;
    const __half* A = p.A + z * p.sA0;
    const __half* B = p.B + z * p.sB0;

    int m0 = blockIdx.x * 128, n0 = blockIdx.y * 128;
    int t = threadIdx.x;
    int w = t >> 5, lane = t & 31;
    int wm = w & 1, wn = w >> 1;
    int g = lane >> 2, tig = lane & 3;

    int rowi = t >> 1, koff = (t & 1) * 16;
    long long arow = m0 + rowi;
    if (GATHER) arow = p.gidx[z * p.sG + m0 + rowi];
    const __half* gA = A + arow * (long long)p.lda;
    const __half* gB = B + (long long)(n0 + rowi) * p.ldb;
    int sAoff = rowi * LDA + koff;
    int sBoff = ASZ + rowi * LDA + koff;

    float acc[4][4][4];
#pragma unroll
    for (int i = 0; i < 4; i++)
#pragma unroll
        for (int j = 0; j < 4; j++)
#pragma unroll
            for (int q = 0; q < 4; q++) acc[i][j][q] = 0.0f;

    auto load_tile = [&](int ti, int slot) {
        __half* s = smh + slot * STAGE;
        int kt = ti * 32;
        cp16(s + sAoff,     gA + kt + koff);
        cp16(s + sAoff + 8, gA + kt + koff + 8);
        cp16(s + sBoff,     gB + kt + koff);
        cp16(s + sBoff + 8, gB + kt + koff + 8);
        CP_COMMIT();
    };

    auto compute = [&](int slot) {
        const __half* As_ = smh + slot * STAGE;
        const __half* Bs_ = As_ + ASZ;
#pragma unroll
        for (int ks = 0; ks < 2; ks++) {
            unsigned a[4][4], b[4][2];
#pragma unroll
            for (int mt = 0; mt < 4; mt++) {
                int rb = (wm * 64 + mt * 16 + g) * LDA + ks * 16 + 2 * tig;
                a[mt][0] = *(const unsigned*)(As_ + rb);
                a[mt][1] = *(const unsigned*)(As_ + rb + 8 * LDA);
                a[mt][2] = *(const unsigned*)(As_ + rb + 8);
                a[mt][3] = *(const unsigned*)(As_ + rb + 8 * LDA + 8);
            }
#pragma unroll
            for (int nt = 0; nt < 4; nt++) {
                int nb = (wn * 32 + nt * 8 + g) * LDA + ks * 16 + 2 * tig;
                b[nt][0] = *(const unsigned*)(Bs_ + nb);
                b[nt][1] = *(const unsigned*)(Bs_ + nb + 8);
            }
#pragma unroll
            for (int mt = 0; mt < 4; mt++)
#pragma unroll
                for (int nt = 0; nt < 4; nt++)
                    mma16h(acc[mt][nt], a[mt], b[nt][0], b[nt][1]);
        }
    };

    int ntiles = p.K >> 5;
    load_tile(0, 0);
    load_tile(1, 1);
    for (int i = 0; i < ntiles; i++) {
        CP_WAIT1();
        __syncthreads();
        if (i + 2 < ntiles) {
            int s2 = i + 2; s2 = s2 - (s2 / 3) * 3;
            load_tile(i + 2, s2);
        } else CP_COMMIT();
        compute(i - (i / 3) * 3);
    }

    const float* bias = p.bias ? (p.bias + z * p.sBias) : nullptr;
#pragma unroll
    for (int mt = 0; mt < 4; mt++) {
#pragma unroll
        for (int half_ = 0; half_ < 2; half_++) {
            int m = m0 + wm * 64 + mt * 16 + g + half_ * 8;
#pragma unroll
            for (int nt = 0; nt < 4; nt++) {
                int n = n0 + wn * 32 + nt * 8 + tig * 2;
                float v0 = acc[mt][nt][half_ * 2 + 0] * p.alpha;
                float v1 = acc[mt][nt][half_ * 2 + 1] * p.alpha;
                if (p.epi & 1) { v0 += bias[n]; v1 += bias[n + 1]; }
                if (p.epi & 2) { v0 = gelu_f(v0); v1 = gelu_f(v1); }
                if (p.epi & 4) {
                    v0 += p.res[(long long)m * p.ldres + n];
                    v1 += p.res[(long long)m * p.ldres + n + 1];
                }
                long long cidx = (long long)m * p.ldc + n + z * p.sC0;
                if (OUTH) *(__half2*)&((__half*)p.C)[cidx] = __floats2half2_rn(v0, v1);
                else      *(float2*)&((float*)p.C)[cidx] = make_float2(v0, v1);
            }
        }
    }
}

template <bool GATHER, bool OUTH>
static void launch_h(const HGemmP& p, int M, int N, int batch) {
    int smem = 3 * 2 * 128 * 40 * 2;
    cudaFuncSetAttribute(hgemm<GATHER, OUTH>,
                         cudaFuncAttributeMaxDynamicSharedMemorySize, smem);
    dim3 grid(M / 128, N / 128, batch);
    hgemm<GATHER, OUTH><<<grid, 256, smem>>>(p);
}

// ---------------- layernorm ----------------
__global__ __launch_bounds__(256) void ln_kernel(const float* __restrict__ x,
                                                 const float* __restrict__ g,
                                                 const float* __restrict__ b,
                                                 float* __restrict__ outf,
                                                 __half* __restrict__ outh) {
    int row = blockIdx.x;
    int tid = threadIdx.x;
    const float4* xr = (const float4*)(x + (long long)row * Dd);
    float4 v = xr[tid];
    __shared__ float s[256];

    s[tid] = v.x + v.y + v.z + v.w;
    __syncthreads();
    for (int o = 128; o > 0; o >>= 1) { if (tid < o) s[tid] += s[tid + o]; __syncthreads(); }
    float mu = s[0] * (1.0f / Dd);
    __syncthreads();

    float dx = v.x - mu, dy = v.y - mu, dz = v.z - mu, dw = v.w - mu;
    s[tid] = dx * dx + dy * dy + dz * dz + dw * dw;
    __syncthreads();
    for (int o = 128; o > 0; o >>= 1) { if (tid < o) s[tid] += s[tid + o]; __syncthreads(); }
    float rstd = rsqrtf(s[0] * (1.0f / Dd) + 1e-5f);

    float4 gg = ((const float4*)g)[tid];
    float4 bb = ((const float4*)b)[tid];
    float4 o4;
    o4.x = dx * rstd * gg.x + bb.x;
    o4.y = dy * rstd * gg.y + bb.y;
    o4.z = dz * rstd * gg.z + bb.z;
    o4.w = dw * rstd * gg.w + bb.w;
    if (outf) ((float4*)(outf + (long long)row * Dd))[tid] = o4;
    if (outh) {
        __half2* oh = (__half2*)(outh + (long long)row * Dd);
        oh[tid * 2]     = __floats2half2_rn(o4.x, o4.y);
        oh[tid * 2 + 1] = __floats2half2_rn(o4.z, o4.w);
    }
}

// ---------------- router ----------------
__global__ __launch_bounds__(256) void route_kernel(const float* __restrict__ x2,
                                                    const float* __restrict__ wr,
                                                    const float* __restrict__ br,
                                                    const float* __restrict__ wn,
                                                    const float* __restrict__ bn,
                                                    const float* __restrict__ noise,
                                                    int2* __restrict__ topi,
                                                    float2* __restrict__ tw) {
    int t    = blockIdx.x * 8 + (threadIdx.x >> 5);
    int lane = threadIdx.x & 31;
    if (t >= Tn) return;
    const float* xr = x2 + (long long)t * Dd;

    float aR[4] = {0, 0, 0, 0}, aN[4] = {0, 0, 0, 0};
    for (int d = lane; d < Dd; d += 32) {
        float xv = xr[d];
        float4 r = ((const float4*)wr)[d];
        float4 nq = ((const float4*)wn)[d];
        aR[0] += xv * r.x;  aR[1] += xv * r.y;  aR[2] += xv * r.z;  aR[3] += xv * r.w;
        aN[0] += xv * nq.x; aN[1] += xv * nq.y; aN[2] += xv * nq.z; aN[3] += xv * nq.w;
    }
#pragma unroll
    for (int o = 16; o > 0; o >>= 1) {
#pragma unroll
        for (int e = 0; e < 4; e++) {
            aR[e] += __shfl_down_sync(0xffffffffu, aR[e], o);
            aN[e] += __shfl_down_sync(0xffffffffu, aN[e], o);
        }
    }
    if (lane == 0) {
        float nv[4];
#pragma unroll
        for (int e = 0; e < 4; e++) {
            float lg  = aR[e] + br[e];
            float pre = aN[e] + bn[e];
            float sp  = (pre > 20.0f) ? pre : log1pf(expf(pre));
            nv[e] = lg + noise[t * 4 + e] * sp;
        }
        int e0 = 0;
#pragma unroll
        for (int e = 1; e < 4; e++) if (nv[e] > nv[e0]) e0 = e;
        int e1 = -1;
#pragma unroll
        for (int e = 0; e < 4; e++) if (e != e0 && (e1 < 0 || nv[e] > nv[e1])) e1 = e;
        float d  = expf(nv[e1] - nv[e0]);
        float p0 = 1.0f / (1.0f + d);
        topi[t] = make_int2(e0, e1);
        tw[t]   = make_float2(p0, d * p0);
    }
}

// ---------------- capacity scan ----------------
__global__ __launch_bounds__(1024) void scan_kernel(const int2* __restrict__ topi,
                                                    int* __restrict__ sel,
                                                    int* __restrict__ tslot) {
    int e = blockIdx.x;
    int tid = threadIdx.x;
    __shared__ int s[1024];

    int m[4]; int cnt = 0;
#pragma unroll
    for (int i = 0; i < 4; i++) {
        int t = tid * 4 + i;
        int2 ti = topi[t];
        m[i] = (ti.x == e) ? 1 : ((ti.y == e) ? 2 : 0);
        cnt += (m[i] != 0);
    }
    s[tid] = cnt;
    __syncthreads();
    for (int off = 1; off < 1024; off <<= 1) {
        int v = 0;
        if (tid >= off) v = s[tid - off];
        __syncthreads();
        s[tid] += v;
        __syncthreads();
    }
    int total = s[1023];
    int rank  = s[tid] - cnt;
#pragma unroll
    for (int i = 0; i < 4; i++) {
        if (m[i]) {
            int t = tid * 4 + i;
            int j = m[i] - 1;
            if (rank < CAP) { sel[e * CAP + rank] = t; tslot[t * 2 + j] = rank; }
            else            { tslot[t * 2 + j] = -1; }
            rank++;
        }
    }
    for (int r = total + tid; r < CAP; r += 1024) sel[e * CAP + r] = 0;
}

// ---------------- final combine ----------------
__global__ __launch_bounds__(256) void final_kernel(const float* __restrict__ xres,
                                                    const float* __restrict__ mlp,
                                                    const float* __restrict__ moeout,
                                                    const int2* __restrict__ topi,
                                                    const int* __restrict__ tslot,
                                                    const float2* __restrict__ tw,
                                                    float* __restrict__ out) {
    long long idx = (long long)blockIdx.x * blockDim.x + threadIdx.x;
    int t = (int)(idx >> 10);
    int dcol = (int)(idx & 1023);
    float v = xres[idx] + mlp[idx];
    int2 ti = topi[t];
    float2 w = tw[t];
    int s0 = tslot[t * 2], s1 = tslot[t * 2 + 1];
    if (s0 >= 0) v += w.x * moeout[((long long)ti.x * CAP + s0) * Dd + dcol];
    if (s1 >= 0) v += w.y * moeout[((long long)ti.y * CAP + s1) * Dd + dcol];
    out[idx] = v;
}

extern "C" void kernel_launch(void* const* d_in, const int* in_sizes, int n_in,
                              void* d_out, int out_size) {
    const float* x       = (const float*)d_in[0];
    const float* noise   = (const float*)d_in[1];
    const float* ln1_g   = (const float*)d_in[2];
    const float* ln1_b   = (const float*)d_in[3];
    const float* ln2_g   = (const float*)d_in[4];
    const float* ln2_b   = (const float*)d_in[5];
    const float* w_qkv   = (const float*)d_in[6];
    const float* w_proj  = (const float*)d_in[7];
    const float* b_proj  = (const float*)d_in[8];
    const float* w_route = (const float*)d_in[9];
    const float* b_route = (const float*)d_in[10];
    const float* w_noise = (const float*)d_in[11];
    const float* b_noise = (const float*)d_in[12];
    const float* we1     = (const float*)d_in[13];
    const float* be1     = (const float*)d_in[14];
    const float* we2     = (const float*)d_in[15];
    const float* be2     = (const float*)d_in[16];
    const float* w_mlp1  = (const float*)d_in[17];
    const float* b_mlp1  = (const float*)d_in[18];
    const float* w_mlp2  = (const float*)d_in[19];
    const float* b_mlp2  = (const float*)d_in[20];
    float* out = (float*)d_out;

    float*  buf;   cudaGetSymbolAddress((void**)&buf,   g_buf);
    __half* hbuf;  cudaGetSymbolAddress((void**)&hbuf,  g_hbuf);
    int2*   topi;  cudaGetSymbolAddress((void**)&topi,  g_topi);
    float2* tw;    cudaGetSymbolAddress((void**)&tw,    g_tw);
    int*    tslot; cudaGetSymbolAddress((void**)&tslot, g_tslot);
    int*    sel;   cudaGetSymbolAddress((void**)&sel,   g_sel);

    float* xres   = buf + OFF_XRES;
    float* x2     = buf + OFF_X2;
    float* mlpout = buf + OFF_MLPOUT;
    float* moeout = buf + OFF_MOEOUT;

    __half* x1h    = hbuf + HOFF_X1;
    __half* x2h    = hbuf + HOFF_X2;
    __half* aoh    = hbuf + HOFF_AO;
    __half* hmlph  = hbuf + HOFF_HMLP;
    __half* hmoeh  = hbuf + HOFF_HMOE;
    __half* wqkvh  = hbuf + HOFF_WQKV;
    __half* wprojh = hbuf + HOFF_WPROJ;
    __half* wmlp1h = hbuf + HOFF_WMLP1;
    __half* wmlp2h = hbuf + HOFF_WMLP2;
    __half* we1h   = hbuf + HOFF_WE1;
    __half* we2h   = hbuf + HOFF_WE2;
    __half* qkvh   = hbuf + HOFF_QKVH;
    __half* vth    = hbuf + HOFF_VT;

    // 0) weight shadows
    convert_h<<<(3145728 / 2 + 255) / 256, 256>>>(w_qkv, wqkvh, 3145728 / 2);
    convert_h<<<(1048576 / 2 + 255) / 256, 256>>>(w_proj, wprojh, 1048576 / 2);
    { dim3 g2(MLPH / 32, Dd / 32, 1);  transpose_h<<<g2, 256>>>(w_mlp1, wmlp1h, Dd, MLPH); }
    { dim3 g2(Dd / 32, MLPH / 32, 1);  transpose_h<<<g2, 256>>>(w_mlp2, wmlp2h, MLPH, Dd); }
    { dim3 g2(MOEH / 32, Dd / 32, Ee); transpose_h<<<g2, 256>>>(we1, we1h, Dd, MOEH); }
    { dim3 g2(Dd / 32, MOEH / 32, Ee); transpose_h<<<g2, 256>>>(we2, we2h, MOEH, Dd); }

    // 1) LN1 -> x1h
    ln_kernel<<<Tn, 256>>>(x, ln1_g, ln1_b, nullptr, x1h);

    // 2) QKV GEMM -> qkvh (half only)
    {
        HGemmP p{}; p.alpha = 1.0f; p.K = Dd;
        p.A = x1h; p.lda = Dd;
        p.B = wqkvh; p.ldb = Dd;
        p.C = qkvh; p.ldc = 3 * Dd;
        p.epi = 0;
        launch_h<false, true>(p, Tn, 3 * Dd, 1);
    }

    // 2b) V transpose -> vth[bh][dim][key]
    { dim3 gv(Nn / 64, Bb * Hh); vtrans_k<<<gv, 256>>>(qkvh, vth); }

    // 3) flash attention (all fp16 mma) -> aoh
    {
        cudaFuncSetAttribute(flash_k, cudaFuncAttributeMaxDynamicSharedMemorySize,
                             FLASH_SMEM);
        dim3 grid(Nn / 128, Bb * Hh);
        flash_k<<<grid, 256, FLASH_SMEM>>>(qkvh, vth, aoh);
    }

    // 4) xres = x + ao @ w_proj^T + b_proj
    {
        HGemmP p{}; p.alpha = 1.0f; p.K = Dd;
        p.A = aoh; p.lda = Dd;
        p.B = wprojh; p.ldb = Dd;
        p.C = xres; p.ldc = Dd;
        p.bias = b_proj; p.res = x; p.ldres = Dd;
        p.epi = 1 | 4;
        launch_h<false, false>(p, Tn, Dd, 1);
    }

    // 5) LN2 -> x2 (fp32) + x2h
    ln_kernel<<<Tn, 256>>>(xres, ln2_g, ln2_b, x2, x2h);

    // 6) routing
    route_kernel<<<Tn / 8, 256>>>(x2, w_route, b_route, w_noise, b_noise, noise, topi, tw);

    // 7) capacity scan
    scan_kernel<<<Ee, 1024>>>(topi, sel, tslot);

    // 8) MoE GEMM 1 -> hmoeh (half)
    {
        HGemmP p{}; p.alpha = 1.0f; p.K = Dd;
        p.A = x2h; p.lda = Dd;
        p.gidx = sel; p.sG = CAP;
        p.B = we1h; p.ldb = Dd; p.sB0 = (long long)MOEH * Dd;
        p.C = hmoeh; p.ldc = MOEH; p.sC0 = (long long)CAP * MOEH;
        p.bias = be1; p.sBias = MOEH;
        p.epi = 1 | 2;
        launch_h<true, true>(p, CAP, MOEH, Ee);
    }

    // 9) MoE GEMM 2 -> moeout fp32
    {
        HGemmP p{}; p.alpha = 1.0f; p.K = MOEH;
        p.A = hmoeh; p.lda = MOEH; p.sA0 = (long long)CAP * MOEH;
        p.B = we2h; p.ldb = MOEH; p.sB0 = (long long)Dd * MOEH;
        p.C = moeout; p.ldc = Dd; p.sC0 = (long long)CAP * Dd;
        p.bias = be2; p.sBias = Dd;
        p.epi = 1;
        launch_h<false, false>(p, CAP, Dd, Ee);
    }

    // 10) MLP1 -> hmlph (half)
    {
        HGemmP p{}; p.alpha = 1.0f; p.K = Dd;
        p.A = x2h; p.lda = Dd;
        p.B = wmlp1h; p.ldb = Dd;
        p.C = hmlph; p.ldc = MLPH;
        p.bias = b_mlp1;
        p.epi = 1 | 2;
        launch_h<false, true>(p, Tn, MLPH, 1);
    }

    // 11) MLP2 -> mlpout fp32
    {
        HGemmP p{}; p.alpha = 1.0f; p.K = MLPH;
        p.A = hmlph; p.lda = MLPH;
        p.B = wmlp2h; p.ldb = MLPH;
        p.C = mlpout; p.ldc = Dd;
        p.bias = b_mlp2;
        p.epi = 1;
        launch_h<false, false>(p, Tn, Dd, 1);
    }

    // 12) final combine
    final_kernel<<<(Tn * Dd) / 256, 256>>>(xres, mlpout, moeout, topi, tslot, tw, out);
}